// round 10
// baseline (speedup 1.0000x reference)
#include <cuda_runtime.h>
#include <cstdint>

#define BB 16
#define LATENT 128
#define NN 1024
#define EE 32768
#define HH 64
#define LL 4
#define TPB 256                    // tiles per batch: EE/128
#define NTILES (BB * TPB)          // 4096
#define EDGE_GRID 592              // 148 SMs * 4 CTAs

// ---- scratch (device globals; no allocations allowed) ----
__device__ float d_g[BB * HH];
__device__ float d_h[BB * NN * HH];
__device__ float d_p1[BB * NN * HH];
__device__ float d_p2[BB * NN * HH];
__device__ float d_agg[BB * NN * HH];
__device__ int   d_rowptr[NN + 1];
__device__ int   d_rs[EE];                // row, CSR-sorted
__device__ int   d_cs[EE];                // col, CSR-sorted

__device__ __forceinline__ float silu(float x) {
    return x / (1.0f + __expf(-x));
}

__device__ __forceinline__ uint32_t f2tf32(float x) {
    uint32_t r;
    asm("cvt.rna.tf32.f32 %0, %1;" : "=r"(r) : "f"(x));
    return r;
}

__device__ __forceinline__ void mma_tf32(float* c, const uint32_t* a, const uint32_t* b) {
    asm volatile(
        "mma.sync.aligned.m16n8k8.row.col.f32.tf32.tf32.f32 "
        "{%0,%1,%2,%3}, {%4,%5,%6,%7}, {%8,%9}, {%0,%1,%2,%3};"
        : "+f"(c[0]), "+f"(c[1]), "+f"(c[2]), "+f"(c[3])
        : "r"(a[0]), "r"(a[1]), "r"(a[2]), "r"(a[3]), "r"(b[0]), "r"(b[1]));
}

// SMEM layout (edge kernel)
#define PAD_A 68
#define PAD_B 72
#define SME_A    0
#define SME_W2   34816
#define SME_BIAS (SME_W2 + 18432)
#define SME_R    (SME_BIAS + 256)
#define SME_TOTAL (SME_R + 512)

// ---- g = z @ Wg + bg ----
__global__ void g_kernel(const float* __restrict__ z,
                         const float* __restrict__ Wg,
                         const float* __restrict__ bg) {
    int t = blockIdx.x * blockDim.x + threadIdx.x;
    int b = t >> 6, k = t & 63;
    float acc = bg[k];
    const float* zr = z + b * LATENT;
    #pragma unroll 8
    for (int i = 0; i < LATENT; i++) acc += zr[i] * Wg[i * HH + k];
    d_g[t] = acc;
}

// ---- h + proj for layer 0 ----
__global__ void h_kernel(const float* __restrict__ nf,
                         const float* __restrict__ Wn,
                         const float* __restrict__ bn,
                         const float* __restrict__ eW1,
                         const float* __restrict__ eb1) {
    int node = blockIdx.x;
    int k = threadIdx.x;
    int b = node >> 10, n = node & (NN - 1);
    __shared__ float x[HH];
    float v = bn[k] + d_g[b * HH + k];
    v += nf[n * 3 + 0] * Wn[0 * HH + k]
       + nf[n * 3 + 1] * Wn[1 * HH + k]
       + nf[n * 3 + 2] * Wn[2 * HH + k];
    d_h[node * HH + k] = v;
    x[k] = v;
    __syncthreads();
    float a1 = eb1[k], a2 = 0.0f;
    #pragma unroll 8
    for (int i = 0; i < HH; i++) {
        float xv = x[i];
        a1 += xv * eW1[i * HH + k];
        a2 += xv * eW1[(HH + i) * HH + k];
    }
    d_p1[node * HH + k] = a1;
    d_p2[node * HH + k] = a2;
}

// ---- CSR build ----
__global__ void csr_kernel(const int* __restrict__ row,
                           const int* __restrict__ col) {
    __shared__ int sc[NN];
    __shared__ int wo[NN];
    int t = threadIdx.x;
    sc[t] = 0;
    __syncthreads();
    for (int e = t; e < EE; e += 1024) atomicAdd(&sc[row[e]], 1);
    __syncthreads();
    int v = sc[t];
    #pragma unroll
    for (int o = 1; o < NN; o <<= 1) {
        int u = (t >= o) ? sc[t - o] : 0;
        __syncthreads();
        sc[t] += u;
        __syncthreads();
    }
    d_rowptr[t + 1] = sc[t];
    if (t == 0) d_rowptr[0] = 0;
    wo[t] = sc[t] - v;
    __syncthreads();
    for (int e = t; e < EE; e += 1024) {
        int r = row[e];
        int p = atomicAdd(&wo[r], 1);
        d_rs[p] = r;
        d_cs[p] = col[e];
    }
}

// ---- fused edge kernel: 256 thr, 4 CTAs/SM, split-N warps ----
__global__ void __launch_bounds__(256, 4) edge_kernel(
    const float* __restrict__ eW2, const float* __restrict__ eb2) {
    extern __shared__ __align__(16) char smem[];
    float*    sAf = (float*)(smem + SME_A);
    uint32_t* sAu = (uint32_t*)(smem + SME_A);
    uint32_t* sW2 = (uint32_t*)(smem + SME_W2);
    float*    sB2 = (float*)(smem + SME_BIAS);
    int*      sR  = (int*)(smem + SME_R);

    int tid = threadIdx.x;
    int wid = tid >> 5;
    int lane = tid & 31;
    int g = lane >> 2;
    int tg = lane & 3;
    int rb = wid & 3;          // row block (32 rows)
    int ch = wid >> 2;         // col half (32 cols)

    for (int idx = tid; idx < HH * HH; idx += 256) {
        int i = idx >> 6;
        int n = idx & 63;
        sW2[i * PAD_B + n] = f2tf32(eW2[idx]);
    }
    if (tid < HH) sB2[tid] = eb2[tid];
    __syncthreads();

    int rrow = tid & 127;      // item row this thread gathers
    int half = tid >> 7;       // which 32-col half of the row

    for (int tile = blockIdx.x; tile < NTILES; tile += EDGE_GRID) {
        int b = tile >> 8;
        int jbase = (tile & (TPB - 1)) * 128;

        // gather: each thread loads a half-row of p1 and p2
        {
            int j = jbase + rrow;
            int r = d_rs[j], c = d_cs[j];
            if (half == 0) sR[rrow] = r;
            const float4* q1 = reinterpret_cast<const float4*>(
                d_p1 + (size_t)(b * NN + r) * HH + half * 32);
            const float4* q2 = reinterpret_cast<const float4*>(
                d_p2 + (size_t)(b * NN + c) * HH + half * 32);
            uint4* dst = reinterpret_cast<uint4*>(sAu + rrow * PAD_A + half * 32);
            #pragma unroll
            for (int i4 = 0; i4 < 8; i4++) {
                float4 u = q1[i4];
                float4 v = q2[i4];
                uint4 t;
                t.x = f2tf32(silu(u.x + v.x));
                t.y = f2tf32(silu(u.y + v.y));
                t.z = f2tf32(silu(u.z + v.z));
                t.w = f2tf32(silu(u.w + v.w));
                dst[i4] = t;
            }
        }
        __syncthreads();

        // GEMM: warp computes rows rb*32..+31, cols ch*32..+31
        float acc[2][4][4];
        #pragma unroll
        for (int mt = 0; mt < 2; mt++)
            #pragma unroll
            for (int jj = 0; jj < 4; jj++)
                #pragma unroll
                for (int q = 0; q < 4; q++) acc[mt][jj][q] = 0.0f;

        #pragma unroll
        for (int ks = 0; ks < 8; ks++) {
            uint32_t af[2][4];
            #pragma unroll
            for (int mt = 0; mt < 2; mt++) {
                int rr = rb * 32 + mt * 16 + g;
                int cc = ks * 8 + tg;
                af[mt][0] = sAu[rr * PAD_A + cc];
                af[mt][1] = sAu[(rr + 8) * PAD_A + cc];
                af[mt][2] = sAu[rr * PAD_A + cc + 4];
                af[mt][3] = sAu[(rr + 8) * PAD_A + cc + 4];
            }
            uint32_t bf[4][2];
            #pragma unroll
            for (int jj = 0; jj < 4; jj++) {
                int n = ch * 32 + jj * 8 + g;
                bf[jj][0] = sW2[(ks * 8 + tg) * PAD_B + n];
                bf[jj][1] = sW2[(ks * 8 + tg + 4) * PAD_B + n];
            }
            #pragma unroll
            for (int mt = 0; mt < 2; mt++)
                #pragma unroll
                for (int jj = 0; jj < 4; jj++) mma_tf32(acc[mt][jj], af[mt], bf[jj]);
        }
        __syncthreads();   // A staging reads done before epilogue overwrites

        // epilogue: m = silu(raw + b2) -> smem rows (own col half)
        #pragma unroll
        for (int mt = 0; mt < 2; mt++) {
            int r0 = rb * 32 + mt * 16 + g;
            #pragma unroll
            for (int jj = 0; jj < 4; jj++) {
                int c0 = ch * 32 + jj * 8 + tg * 2;
                sAf[r0 * PAD_A + c0]           = silu(acc[mt][jj][0] + sB2[c0]);
                sAf[r0 * PAD_A + c0 + 1]       = silu(acc[mt][jj][1] + sB2[c0 + 1]);
                sAf[(r0 + 8) * PAD_A + c0]     = silu(acc[mt][jj][2] + sB2[c0]);
                sAf[(r0 + 8) * PAD_A + c0 + 1] = silu(acc[mt][jj][3] + sB2[c0 + 1]);
            }
        }
        __syncthreads();

        // segmented reduction: thread = (column k2, quarter seg); 32 rows each
        {
            int k2 = tid & 63;
            int seg = tid >> 6;
            int r0 = seg * 32;
            int rcur = sR[r0];
            float a = 0.0f;
            #pragma unroll 8
            for (int rr = r0; rr < r0 + 32; rr++) {
                int rn = sR[rr];
                if (rn != rcur) {
                    atomicAdd(&d_agg[((size_t)b * NN + rcur) * HH + k2], a);
                    a = 0.0f;
                    rcur = rn;
                }
                a += sAf[rr * PAD_A + k2];
            }
            atomicAdd(&d_agg[((size_t)b * NN + rcur) * HH + k2], a);
        }
        __syncthreads();
    }
}

// ---- node update + fused proj; 4 nodes per 256-thread block ----
__global__ void __launch_bounds__(256) node_kernel(
    const float* __restrict__ nW1, const float* __restrict__ nb1,
    const float* __restrict__ nW2, const float* __restrict__ nb2,
    const float* __restrict__ lng, const float* __restrict__ lnb,
    const float* __restrict__ eW1n, const float* __restrict__ eb1n) {
    int sub = threadIdx.x >> 6;        // node within block
    int k = threadIdx.x & 63;
    int node = blockIdx.x * 4 + sub;
    __shared__ float x[4][2 * HH];
    __shared__ float y[4][HH];
    __shared__ float red[4][4];

    float hk = d_h[node * HH + k];
    float ak = d_agg[node * HH + k];
    d_agg[node * HH + k] = 0.0f;
    x[sub][k] = hk;
    x[sub][HH + k] = ak;
    __syncthreads();

    float u1 = nb1[k];
    #pragma unroll 8
    for (int i = 0; i < 2 * HH; i++) u1 += x[sub][i] * nW1[i * HH + k];
    y[sub][k] = silu(u1);
    __syncthreads();

    float u = nb2[k];
    #pragma unroll 8
    for (int i = 0; i < HH; i++) u += y[sub][i] * nW2[i * HH + k];
    float hn = hk + u;

    float v = hn;
    #pragma unroll
    for (int o = 16; o; o >>= 1) v += __shfl_xor_sync(0xffffffffu, v, o);
    if ((k & 31) == 0) red[sub][k >> 5] = v;
    __syncthreads();
    float mu = (red[sub][0] + red[sub][1]) * (1.0f / HH);
    float dv = hn - mu;
    float v2 = dv * dv;
    #pragma unroll
    for (int o = 16; o; o >>= 1) v2 += __shfl_xor_sync(0xffffffffu, v2, o);
    if ((k & 31) == 0) red[sub][2 + (k >> 5)] = v2;
    __syncthreads();
    float var = (red[sub][2] + red[sub][3]) * (1.0f / HH);
    float hnew = dv * rsqrtf(var + 1e-5f) * lng[k] + lnb[k];
    d_h[node * HH + k] = hnew;

    if (eW1n != nullptr) {
        x[sub][k] = hnew;
        __syncthreads();
        float a1 = eb1n[k], a2 = 0.0f;
        #pragma unroll 8
        for (int i = 0; i < HH; i++) {
            float xv = x[sub][i];
            a1 += xv * eW1n[i * HH + k];
            a2 += xv * eW1n[(HH + i) * HH + k];
        }
        d_p1[node * HH + k] = a1;
        d_p2[node * HH + k] = a2;
    }
}

// ---- output head; 4 nodes per 256-thread block ----
__global__ void __launch_bounds__(256) out_kernel(
    const float* __restrict__ oW1, const float* __restrict__ ob1,
    const float* __restrict__ oW2, const float* __restrict__ ob2,
    float* __restrict__ out) {
    int sub = threadIdx.x >> 6;
    int k = threadIdx.x & 63;
    int node = blockIdx.x * 4 + sub;
    __shared__ float x[4][HH];
    __shared__ float r[4][HH];
    x[sub][k] = d_h[node * HH + k];
    __syncthreads();
    float acc = ob1[k];
    #pragma unroll 8
    for (int i = 0; i < HH; i++) acc += x[sub][i] * oW1[i * HH + k];
    r[sub][k] = fmaxf(acc, 0.0f);
    __syncthreads();
    if (k < 3) {
        float o = ob2[k];
        #pragma unroll 8
        for (int i = 0; i < HH; i++) o += r[sub][i] * oW2[i * 3 + k];
        out[node * 3 + k] = o;
    }
}

extern "C" void kernel_launch(void* const* d_in, const int* in_sizes, int n_in,
                              void* d_out, int out_size) {
    const float* z   = (const float*)d_in[0];
    const int*   ei  = (const int*)d_in[1];
    const float* nf  = (const float*)d_in[2];
    const float* Wg  = (const float*)d_in[3];
    const float* bg  = (const float*)d_in[4];
    const float* Wn  = (const float*)d_in[5];
    const float* bn  = (const float*)d_in[6];
    const float* eW1 = (const float*)d_in[7];
    const float* eb1 = (const float*)d_in[8];
    const float* eW2 = (const float*)d_in[9];
    const float* eb2 = (const float*)d_in[10];
    const float* nW1 = (const float*)d_in[14];
    const float* nb1 = (const float*)d_in[15];
    const float* nW2 = (const float*)d_in[16];
    const float* nb2 = (const float*)d_in[17];
    const float* lng = (const float*)d_in[18];
    const float* lnb = (const float*)d_in[19];
    const float* oW1 = (const float*)d_in[20];
    const float* ob1 = (const float*)d_in[21];
    const float* oW2 = (const float*)d_in[22];
    const float* ob2 = (const float*)d_in[23];

    void* pAgg;
    cudaGetSymbolAddress(&pAgg, d_agg);
    cudaMemsetAsync(pAgg, 0, sizeof(float) * BB * NN * HH);

    cudaFuncSetAttribute((const void*)edge_kernel,
                         cudaFuncAttributeMaxDynamicSharedMemorySize, SME_TOTAL);

    g_kernel<<<1, 1024>>>(z, Wg, bg);
    h_kernel<<<BB * NN, HH>>>(nf, Wn, bn, eW1, eb1);
    csr_kernel<<<1, 1024>>>(ei, ei + EE);

    for (int l = 0; l < LL; l++) {
        edge_kernel<<<EDGE_GRID, 256, SME_TOTAL>>>(
            eW2 + (size_t)l * HH * HH, eb2 + l * HH);
        const float* eW1n = (l + 1 < LL) ? eW1 + (size_t)(l + 1) * 129 * HH : nullptr;
        const float* eb1n = (l + 1 < LL) ? eb1 + (l + 1) * HH : nullptr;
        node_kernel<<<BB * NN / 4, 256>>>(
            nW1 + (size_t)l * 2 * HH * HH, nb1 + l * HH,
            nW2 + (size_t)l * HH * HH, nb2 + l * HH,
            lng + l * HH, lnb + l * HH,
            eW1n, eb1n);
    }

    out_kernel<<<BB * NN / 4, 256>>>(oW1, ob1, oW2, ob2, (float*)d_out);
}

// round 11
// speedup vs baseline: 1.2442x; 1.2442x over previous
#include <cuda_runtime.h>
#include <cstdint>

#define BB 16
#define LATENT 128
#define NN 1024
#define EE 32768
#define HH 64
#define LL 4
#define TPB 256                    // tiles per batch: EE/128
#define NTILES (BB * TPB)          // 4096
#define EDGE_GRID 444              // 148 SMs * 3 CTAs

// ---- scratch (device globals; no allocations allowed) ----
__device__ float d_g[BB * HH];
__device__ float d_h[BB * NN * HH];
__device__ float d_p1[BB * NN * HH];
__device__ float d_p2[BB * NN * HH];
__device__ float d_agg[BB * NN * HH];
__device__ int   d_rowptr[NN + 1];
__device__ int   d_rs[EE];
__device__ int   d_cs[EE];

__device__ __forceinline__ float silu(float x) {
    return x / (1.0f + __expf(-x));
}

__device__ __forceinline__ uint32_t f2tf32(float x) {
    uint32_t r;
    asm("cvt.rna.tf32.f32 %0, %1;" : "=r"(r) : "f"(x));
    return r;
}

__device__ __forceinline__ void mma_tf32(float* c, const uint32_t* a, const uint32_t* b) {
    asm volatile(
        "mma.sync.aligned.m16n8k8.row.col.f32.tf32.tf32.f32 "
        "{%0,%1,%2,%3}, {%4,%5,%6,%7}, {%8,%9}, {%0,%1,%2,%3};"
        : "+f"(c[0]), "+f"(c[1]), "+f"(c[2]), "+f"(c[3])
        : "r"(a[0]), "r"(a[1]), "r"(a[2]), "r"(a[3]), "r"(b[0]), "r"(b[1]));
}

// ---- edge kernel SMEM layout ----
#define PAD_A 68
#define PAD_B 72
#define SME_A    0
#define SME_W2   34816
#define SME_BIAS (SME_W2 + 18432)
#define SME_R    (SME_BIAS + 256)
#define SME_TOTAL (SME_R + 512)

// ---- node kernel SMEM layout ----
#define PAD_NA 132      // A staging stride (K up to 128)
#define PAD_NP 136      // proj B stride (N=128)
#define SMN_A    0                          // 64*132*4 = 33792
#define SMN_B    33792                      // 36864 (nW1 128x72; proj 64x136)
#define SMN_BIAS (SMN_B + 36864)            // nb1,nb2,lng,lnb,eb1n: 5*256
#define SMN_LN   (SMN_BIAS + 1280)          // 64 rows * 4 parts * 2 * 4B
#define SMN_TOTAL (SMN_LN + 2048)           // 73984

// ---- g = z @ Wg + bg ----
__global__ void g_kernel(const float* __restrict__ z,
                         const float* __restrict__ Wg,
                         const float* __restrict__ bg) {
    int t = blockIdx.x * blockDim.x + threadIdx.x;
    int b = t >> 6, k = t & 63;
    float acc = bg[k];
    const float* zr = z + b * LATENT;
    #pragma unroll 8
    for (int i = 0; i < LATENT; i++) acc += zr[i] * Wg[i * HH + k];
    d_g[t] = acc;
}

// ---- h + proj for layer 0 (scalar fp32; runs once) ----
__global__ void h_kernel(const float* __restrict__ nf,
                         const float* __restrict__ Wn,
                         const float* __restrict__ bn,
                         const float* __restrict__ eW1,
                         const float* __restrict__ eb1) {
    int node = blockIdx.x;
    int k = threadIdx.x;
    int b = node >> 10, n = node & (NN - 1);
    __shared__ float x[HH];
    float v = bn[k] + d_g[b * HH + k];
    v += nf[n * 3 + 0] * Wn[0 * HH + k]
       + nf[n * 3 + 1] * Wn[1 * HH + k]
       + nf[n * 3 + 2] * Wn[2 * HH + k];
    d_h[node * HH + k] = v;
    x[k] = v;
    __syncthreads();
    float a1 = eb1[k], a2 = 0.0f;
    #pragma unroll 8
    for (int i = 0; i < HH; i++) {
        float xv = x[i];
        a1 += xv * eW1[i * HH + k];
        a2 += xv * eW1[(HH + i) * HH + k];
    }
    d_p1[node * HH + k] = a1;
    d_p2[node * HH + k] = a2;
}

// ---- CSR build ----
__global__ void csr_kernel(const int* __restrict__ row,
                           const int* __restrict__ col) {
    __shared__ int sc[NN];
    __shared__ int wo[NN];
    int t = threadIdx.x;
    sc[t] = 0;
    __syncthreads();
    for (int e = t; e < EE; e += 1024) atomicAdd(&sc[row[e]], 1);
    __syncthreads();
    int v = sc[t];
    #pragma unroll
    for (int o = 1; o < NN; o <<= 1) {
        int u = (t >= o) ? sc[t - o] : 0;
        __syncthreads();
        sc[t] += u;
        __syncthreads();
    }
    d_rowptr[t + 1] = sc[t];
    if (t == 0) d_rowptr[0] = 0;
    wo[t] = sc[t] - v;
    __syncthreads();
    for (int e = t; e < EE; e += 1024) {
        int r = row[e];
        int p = atomicAdd(&wo[r], 1);
        d_rs[p] = r;
        d_cs[p] = col[e];
    }
}

// ---- fused edge kernel (R9 config): 256 thr, 3 CTAs/SM ----
__global__ void __launch_bounds__(256, 3) edge_kernel(
    const float* __restrict__ eW2, const float* __restrict__ eb2) {
    extern __shared__ __align__(16) char smem[];
    float*    sAf = (float*)(smem + SME_A);
    uint32_t* sAu = (uint32_t*)(smem + SME_A);
    uint32_t* sW2 = (uint32_t*)(smem + SME_W2);
    float*    sB2 = (float*)(smem + SME_BIAS);
    int*      sR  = (int*)(smem + SME_R);

    int tid = threadIdx.x;
    int wid = tid >> 5;
    int lane = tid & 31;
    int g = lane >> 2;
    int tg = lane & 3;
    int rb = wid & 3;
    int ch = wid >> 2;

    for (int idx = tid; idx < HH * HH; idx += 256) {
        int i = idx >> 6;
        int n = idx & 63;
        sW2[i * PAD_B + n] = f2tf32(eW2[idx]);
    }
    if (tid < HH) sB2[tid] = eb2[tid];
    __syncthreads();

    int rrow = tid & 127;
    int half = tid >> 7;

    for (int tile = blockIdx.x; tile < NTILES; tile += EDGE_GRID) {
        int b = tile >> 8;
        int jbase = (tile & (TPB - 1)) * 128;

        {
            int j = jbase + rrow;
            int r = d_rs[j], c = d_cs[j];
            if (half == 0) sR[rrow] = r;
            const float4* q1 = reinterpret_cast<const float4*>(
                d_p1 + (size_t)(b * NN + r) * HH + half * 32);
            const float4* q2 = reinterpret_cast<const float4*>(
                d_p2 + (size_t)(b * NN + c) * HH + half * 32);
            uint4* dst = reinterpret_cast<uint4*>(sAu + rrow * PAD_A + half * 32);
            #pragma unroll
            for (int i4 = 0; i4 < 8; i4++) {
                float4 u = q1[i4];
                float4 v = q2[i4];
                uint4 t;
                t.x = f2tf32(silu(u.x + v.x));
                t.y = f2tf32(silu(u.y + v.y));
                t.z = f2tf32(silu(u.z + v.z));
                t.w = f2tf32(silu(u.w + v.w));
                dst[i4] = t;
            }
        }
        __syncthreads();

        float acc[2][4][4];
        #pragma unroll
        for (int mt = 0; mt < 2; mt++)
            #pragma unroll
            for (int jj = 0; jj < 4; jj++)
                #pragma unroll
                for (int q = 0; q < 4; q++) acc[mt][jj][q] = 0.0f;

        #pragma unroll
        for (int ks = 0; ks < 8; ks++) {
            uint32_t af[2][4];
            #pragma unroll
            for (int mt = 0; mt < 2; mt++) {
                int rr = rb * 32 + mt * 16 + g;
                int cc = ks * 8 + tg;
                af[mt][0] = sAu[rr * PAD_A + cc];
                af[mt][1] = sAu[(rr + 8) * PAD_A + cc];
                af[mt][2] = sAu[rr * PAD_A + cc + 4];
                af[mt][3] = sAu[(rr + 8) * PAD_A + cc + 4];
            }
            uint32_t bf[4][2];
            #pragma unroll
            for (int jj = 0; jj < 4; jj++) {
                int n = ch * 32 + jj * 8 + g;
                bf[jj][0] = sW2[(ks * 8 + tg) * PAD_B + n];
                bf[jj][1] = sW2[(ks * 8 + tg + 4) * PAD_B + n];
            }
            #pragma unroll
            for (int mt = 0; mt < 2; mt++)
                #pragma unroll
                for (int jj = 0; jj < 4; jj++) mma_tf32(acc[mt][jj], af[mt], bf[jj]);
        }
        __syncthreads();

        #pragma unroll
        for (int mt = 0; mt < 2; mt++) {
            int r0 = rb * 32 + mt * 16 + g;
            #pragma unroll
            for (int jj = 0; jj < 4; jj++) {
                int c0 = ch * 32 + jj * 8 + tg * 2;
                sAf[r0 * PAD_A + c0]           = silu(acc[mt][jj][0] + sB2[c0]);
                sAf[r0 * PAD_A + c0 + 1]       = silu(acc[mt][jj][1] + sB2[c0 + 1]);
                sAf[(r0 + 8) * PAD_A + c0]     = silu(acc[mt][jj][2] + sB2[c0]);
                sAf[(r0 + 8) * PAD_A + c0 + 1] = silu(acc[mt][jj][3] + sB2[c0 + 1]);
            }
        }
        __syncthreads();

        {
            int k2 = tid & 63;
            int seg = tid >> 6;
            int r0 = seg * 32;
            int rcur = sR[r0];
            float a = 0.0f;
            #pragma unroll 8
            for (int rr = r0; rr < r0 + 32; rr++) {
                int rn = sR[rr];
                if (rn != rcur) {
                    atomicAdd(&d_agg[((size_t)b * NN + rcur) * HH + k2], a);
                    a = 0.0f;
                    rcur = rn;
                }
                a += sAf[rr * PAD_A + k2];
            }
            atomicAdd(&d_agg[((size_t)b * NN + rcur) * HH + k2], a);
        }
        __syncthreads();
    }
}

// ---- tensorized node kernel: 64 nodes/block, 3 tf32 GEMMs + LN ----
__global__ void __launch_bounds__(256, 3) node_kernel(
    const float* __restrict__ nW1, const float* __restrict__ nb1,
    const float* __restrict__ nW2, const float* __restrict__ nb2,
    const float* __restrict__ lng, const float* __restrict__ lnb,
    const float* __restrict__ eW1n, const float* __restrict__ eb1n) {
    extern __shared__ __align__(16) char smem[];
    float*    sAf = (float*)(smem + SMN_A);
    uint32_t* sAu = (uint32_t*)(smem + SMN_A);
    uint32_t* sB  = (uint32_t*)(smem + SMN_B);
    float*    sNB1 = (float*)(smem + SMN_BIAS);
    float*    sNB2 = sNB1 + 64;
    float*    sLG  = sNB1 + 128;
    float*    sLB  = sNB1 + 192;
    float*    sEB  = sNB1 + 256;
    float*    sLNs = (float*)(smem + SMN_LN);        // [64][4] sums
    float*    sLNq = sLNs + 256;                     // [64][4] sumsq

    int tid = threadIdx.x;
    int wid = tid >> 5;
    int lane = tid & 31;
    int g = lane >> 2;
    int tg = lane & 3;
    int rw = wid & 1;          // 32-row block
    int cw = wid >> 1;         // 16-col block (GEMM1/2) or 32-col (GEMM3)
    int node0 = blockIdx.x * 64;

    // ---- stage A = [h | agg] (tf32) and B = nW1 ----
    {
        int row = tid & 63;
        int qtr = tid >> 6;                // 0,1: h ; 2,3: agg
        const float* src = (qtr < 2)
            ? d_h  + (size_t)(node0 + row) * HH + qtr * 32
            : d_agg + (size_t)(node0 + row) * HH + (qtr - 2) * 32;
        uint32_t* dst = sAu + row * PAD_NA + qtr * 32;
        #pragma unroll
        for (int i4 = 0; i4 < 8; i4++) {
            float4 v = reinterpret_cast<const float4*>(src)[i4];
            uint4 t;
            t.x = f2tf32(v.x); t.y = f2tf32(v.y);
            t.z = f2tf32(v.z); t.w = f2tf32(v.w);
            reinterpret_cast<uint4*>(dst)[i4] = t;
        }
        if (qtr >= 2) {
            float4* az = reinterpret_cast<float4*>(
                d_agg + (size_t)(node0 + row) * HH + (qtr - 2) * 32);
            #pragma unroll
            for (int i4 = 0; i4 < 8; i4++) az[i4] = make_float4(0, 0, 0, 0);
        }
    }
    for (int idx = tid; idx < 128 * 64; idx += 256) {
        sB[(idx >> 6) * PAD_B + (idx & 63)] = f2tf32(nW1[idx]);
    }
    if (tid < 64) {
        sNB1[tid] = nb1[tid];
        sNB2[tid] = nb2[tid];
        sLG[tid] = lng[tid];
        sLB[tid] = lnb[tid];
        if (eW1n) sEB[tid] = eb1n[tid];
    }
    __syncthreads();

    // ---- GEMM1: [64 x 128] @ nW1 -> raw u1 [64 x 64] ----
    float acc[2][2][4];
    #pragma unroll
    for (int mt = 0; mt < 2; mt++)
        #pragma unroll
        for (int nt = 0; nt < 2; nt++)
            #pragma unroll
            for (int q = 0; q < 4; q++) acc[mt][nt][q] = 0.0f;
    #pragma unroll
    for (int ks = 0; ks < 16; ks++) {
        uint32_t af[2][4];
        #pragma unroll
        for (int mt = 0; mt < 2; mt++) {
            int rr = rw * 32 + mt * 16 + g;
            int cc = ks * 8 + tg;
            af[mt][0] = sAu[rr * PAD_NA + cc];
            af[mt][1] = sAu[(rr + 8) * PAD_NA + cc];
            af[mt][2] = sAu[rr * PAD_NA + cc + 4];
            af[mt][3] = sAu[(rr + 8) * PAD_NA + cc + 4];
        }
        uint32_t bf[2][2];
        #pragma unroll
        for (int nt = 0; nt < 2; nt++) {
            int n = cw * 16 + nt * 8 + g;
            bf[nt][0] = sB[(ks * 8 + tg) * PAD_B + n];
            bf[nt][1] = sB[(ks * 8 + tg + 4) * PAD_B + n];
        }
        #pragma unroll
        for (int mt = 0; mt < 2; mt++)
            #pragma unroll
            for (int nt = 0; nt < 2; nt++) mma_tf32(acc[mt][nt], af[mt], bf[nt]);
    }
    __syncthreads();

    // ---- epilogue1: u1 = silu(raw + nb1) -> sA tf32 cols 0..63; restage nW2 ----
    #pragma unroll
    for (int mt = 0; mt < 2; mt++) {
        int r0 = rw * 32 + mt * 16 + g;
        #pragma unroll
        for (int nt = 0; nt < 2; nt++) {
            int c0 = cw * 16 + nt * 8 + tg * 2;
            sAu[r0 * PAD_NA + c0]           = f2tf32(silu(acc[mt][nt][0] + sNB1[c0]));
            sAu[r0 * PAD_NA + c0 + 1]       = f2tf32(silu(acc[mt][nt][1] + sNB1[c0 + 1]));
            sAu[(r0 + 8) * PAD_NA + c0]     = f2tf32(silu(acc[mt][nt][2] + sNB1[c0]));
            sAu[(r0 + 8) * PAD_NA + c0 + 1] = f2tf32(silu(acc[mt][nt][3] + sNB1[c0 + 1]));
        }
    }
    for (int idx = tid; idx < 64 * 64; idx += 256) {
        sB[(idx >> 6) * PAD_B + (idx & 63)] = f2tf32(nW2[idx]);
    }
    __syncthreads();

    // ---- GEMM2: u1 @ nW2 -> raw u [64 x 64] ----
    #pragma unroll
    for (int mt = 0; mt < 2; mt++)
        #pragma unroll
        for (int nt = 0; nt < 2; nt++)
            #pragma unroll
            for (int q = 0; q < 4; q++) acc[mt][nt][q] = 0.0f;
    #pragma unroll
    for (int ks = 0; ks < 8; ks++) {
        uint32_t af[2][4];
        #pragma unroll
        for (int mt = 0; mt < 2; mt++) {
            int rr = rw * 32 + mt * 16 + g;
            int cc = ks * 8 + tg;
            af[mt][0] = sAu[rr * PAD_NA + cc];
            af[mt][1] = sAu[(rr + 8) * PAD_NA + cc];
            af[mt][2] = sAu[rr * PAD_NA + cc + 4];
            af[mt][3] = sAu[(rr + 8) * PAD_NA + cc + 4];
        }
        uint32_t bf[2][2];
        #pragma unroll
        for (int nt = 0; nt < 2; nt++) {
            int n = cw * 16 + nt * 8 + g;
            bf[nt][0] = sB[(ks * 8 + tg) * PAD_B + n];
            bf[nt][1] = sB[(ks * 8 + tg + 4) * PAD_B + n];
        }
        #pragma unroll
        for (int mt = 0; mt < 2; mt++)
            #pragma unroll
            for (int nt = 0; nt < 2; nt++) mma_tf32(acc[mt][nt], af[mt], bf[nt]);
    }
    __syncthreads();

    // ---- epilogue2: hn = h + raw + nb2 -> sA fp32; restage proj weights ----
    #pragma unroll
    for (int mt = 0; mt < 2; mt++) {
        int r0 = rw * 32 + mt * 16 + g;
        #pragma unroll
        for (int nt = 0; nt < 2; nt++) {
            int c0 = cw * 16 + nt * 8 + tg * 2;
            float2 h0 = *reinterpret_cast<const float2*>(d_h + (size_t)(node0 + r0) * HH + c0);
            float2 h1 = *reinterpret_cast<const float2*>(d_h + (size_t)(node0 + r0 + 8) * HH + c0);
            sAf[r0 * PAD_NA + c0]           = h0.x + acc[mt][nt][0] + sNB2[c0];
            sAf[r0 * PAD_NA + c0 + 1]       = h0.y + acc[mt][nt][1] + sNB2[c0 + 1];
            sAf[(r0 + 8) * PAD_NA + c0]     = h1.x + acc[mt][nt][2] + sNB2[c0];
            sAf[(r0 + 8) * PAD_NA + c0 + 1] = h1.y + acc[mt][nt][3] + sNB2[c0 + 1];
        }
    }
    if (eW1n) {
        for (int idx = tid; idx < 64 * 128; idx += 256) {
            int i = idx >> 7, n = idx & 127;
            float v = (n < 64) ? eW1n[i * HH + n] : eW1n[(64 + i) * HH + (n - 64)];
            sB[i * PAD_NP + n] = f2tf32(v);
        }
    }
    __syncthreads();

    // ---- layernorm: row = tid>>2, part = tid&3 (16 cols each) ----
    {
        int row = tid >> 2;
        int part = tid & 3;
        float s = 0.0f, q = 0.0f;
        #pragma unroll
        for (int i = 0; i < 16; i++) {
            float v = sAf[row * PAD_NA + part * 16 + i];
            s += v;
            q += v * v;
        }
        sLNs[row * 4 + part] = s;
        sLNq[row * 4 + part] = q;
    }
    __syncthreads();
    {
        int row = tid >> 2;
        int part = tid & 3;
        float s = sLNs[row * 4] + sLNs[row * 4 + 1] + sLNs[row * 4 + 2] + sLNs[row * 4 + 3];
        float q = sLNq[row * 4] + sLNq[row * 4 + 1] + sLNq[row * 4 + 2] + sLNq[row * 4 + 3];
        float mu = s * (1.0f / HH);
        float var = q * (1.0f / HH) - mu * mu;
        float rstd = rsqrtf(var + 1e-5f);
        float hv[16];
        #pragma unroll
        for (int i = 0; i < 16; i++) {
            int c = part * 16 + i;
            hv[i] = (sAf[row * PAD_NA + c] - mu) * rstd * sLG[c] + sLB[c];
        }
        float4* hout = reinterpret_cast<float4*>(d_h + (size_t)(node0 + row) * HH + part * 16);
        #pragma unroll
        for (int i4 = 0; i4 < 4; i4++)
            hout[i4] = make_float4(hv[i4 * 4], hv[i4 * 4 + 1], hv[i4 * 4 + 2], hv[i4 * 4 + 3]);
        __syncthreads();          // all sAf reads done before tf32 overwrite
        #pragma unroll
        for (int i = 0; i < 16; i++)
            sAu[row * PAD_NA + part * 16 + i] = f2tf32(hv[i]);
    }
    __syncthreads();

    if (!eW1n) return;

    // ---- GEMM3 (proj): hnew[64x64] @ eW1 -> [64 x 128] = [p1 | p2] ----
    float acc3[2][4][4];
    #pragma unroll
    for (int mt = 0; mt < 2; mt++)
        #pragma unroll
        for (int nt = 0; nt < 4; nt++)
            #pragma unroll
            for (int q = 0; q < 4; q++) acc3[mt][nt][q] = 0.0f;
    #pragma unroll
    for (int ks = 0; ks < 8; ks++) {
        uint32_t af[2][4];
        #pragma unroll
        for (int mt = 0; mt < 2; mt++) {
            int rr = rw * 32 + mt * 16 + g;
            int cc = ks * 8 + tg;
            af[mt][0] = sAu[rr * PAD_NA + cc];
            af[mt][1] = sAu[(rr + 8) * PAD_NA + cc];
            af[mt][2] = sAu[rr * PAD_NA + cc + 4];
            af[mt][3] = sAu[(rr + 8) * PAD_NA + cc + 4];
        }
        uint32_t bf[4][2];
        #pragma unroll
        for (int nt = 0; nt < 4; nt++) {
            int n = cw * 32 + nt * 8 + g;
            bf[nt][0] = sB[(ks * 8 + tg) * PAD_NP + n];
            bf[nt][1] = sB[(ks * 8 + tg + 4) * PAD_NP + n];
        }
        #pragma unroll
        for (int mt = 0; mt < 2; mt++)
            #pragma unroll
            for (int nt = 0; nt < 4; nt++) mma_tf32(acc3[mt][nt], af[mt], bf[nt]);
    }

    #pragma unroll
    for (int mt = 0; mt < 2; mt++) {
        int r0 = rw * 32 + mt * 16 + g;
        #pragma unroll
        for (int nt = 0; nt < 4; nt++) {
            int c0 = cw * 32 + nt * 8 + tg * 2;
            #pragma unroll
            for (int hh = 0; hh < 2; hh++) {
                int rr = r0 + hh * 8;
                float v0 = acc3[mt][nt][hh * 2];
                float v1 = acc3[mt][nt][hh * 2 + 1];
                if (c0 < 64) {
                    v0 += sEB[c0];
                    v1 += sEB[c0 + 1];
                    *reinterpret_cast<float2*>(d_p1 + (size_t)(node0 + rr) * HH + c0)
                        = make_float2(v0, v1);
                } else {
                    *reinterpret_cast<float2*>(d_p2 + (size_t)(node0 + rr) * HH + (c0 - 64))
                        = make_float2(v0, v1);
                }
            }
        }
    }
}

// ---- output head; 4 nodes per 256-thread block ----
__global__ void __launch_bounds__(256) out_kernel(
    const float* __restrict__ oW1, const float* __restrict__ ob1,
    const float* __restrict__ oW2, const float* __restrict__ ob2,
    float* __restrict__ out) {
    int sub = threadIdx.x >> 6;
    int k = threadIdx.x & 63;
    int node = blockIdx.x * 4 + sub;
    __shared__ float x[4][HH];
    __shared__ float r[4][HH];
    x[sub][k] = d_h[node * HH + k];
    __syncthreads();
    float acc = ob1[k];
    #pragma unroll 8
    for (int i = 0; i < HH; i++) acc += x[sub][i] * oW1[i * HH + k];
    r[sub][k] = fmaxf(acc, 0.0f);
    __syncthreads();
    if (k < 3) {
        float o = ob2[k];
        #pragma unroll 8
        for (int i = 0; i < HH; i++) o += r[sub][i] * oW2[i * 3 + k];
        out[node * 3 + k] = o;
    }
}

extern "C" void kernel_launch(void* const* d_in, const int* in_sizes, int n_in,
                              void* d_out, int out_size) {
    const float* z   = (const float*)d_in[0];
    const int*   ei  = (const int*)d_in[1];
    const float* nf  = (const float*)d_in[2];
    const float* Wg  = (const float*)d_in[3];
    const float* bg  = (const float*)d_in[4];
    const float* Wn  = (const float*)d_in[5];
    const float* bn  = (const float*)d_in[6];
    const float* eW1 = (const float*)d_in[7];
    const float* eb1 = (const float*)d_in[8];
    const float* eW2 = (const float*)d_in[9];
    const float* eb2 = (const float*)d_in[10];
    const float* nW1 = (const float*)d_in[14];
    const float* nb1 = (const float*)d_in[15];
    const float* nW2 = (const float*)d_in[16];
    const float* nb2 = (const float*)d_in[17];
    const float* lng = (const float*)d_in[18];
    const float* lnb = (const float*)d_in[19];
    const float* oW1 = (const float*)d_in[20];
    const float* ob1 = (const float*)d_in[21];
    const float* oW2 = (const float*)d_in[22];
    const float* ob2 = (const float*)d_in[23];

    void* pAgg;
    cudaGetSymbolAddress(&pAgg, d_agg);
    cudaMemsetAsync(pAgg, 0, sizeof(float) * BB * NN * HH);

    cudaFuncSetAttribute((const void*)edge_kernel,
                         cudaFuncAttributeMaxDynamicSharedMemorySize, SME_TOTAL);
    cudaFuncSetAttribute((const void*)node_kernel,
                         cudaFuncAttributeMaxDynamicSharedMemorySize, SMN_TOTAL);

    g_kernel<<<1, 1024>>>(z, Wg, bg);
    h_kernel<<<BB * NN, HH>>>(nf, Wn, bn, eW1, eb1);
    csr_kernel<<<1, 1024>>>(ei, ei + EE);

    for (int l = 0; l < LL; l++) {
        edge_kernel<<<EDGE_GRID, 256, SME_TOTAL>>>(
            eW2 + (size_t)l * HH * HH, eb2 + l * HH);
        const float* eW1n = (l + 1 < LL) ? eW1 + (size_t)(l + 1) * 129 * HH : nullptr;
        const float* eb1n = (l + 1 < LL) ? eb1 + (l + 1) * HH : nullptr;
        node_kernel<<<BB * NN / 64, 256, SMN_TOTAL>>>(
            nW1 + (size_t)l * 2 * HH * HH, nb1 + l * HH,
            nW2 + (size_t)l * HH * HH, nb2 + l * HH,
            lng + l * HH, lnb + l * HH,
            eW1n, eb1n);
    }

    out_kernel<<<BB * NN / 4, 256>>>(oW1, ob1, oW2, ob2, (float*)d_out);
}

// round 12
// speedup vs baseline: 1.2816x; 1.0300x over previous
#include <cuda_runtime.h>
#include <cstdint>

#define BB 16
#define LATENT 128
#define NN 1024
#define EE 32768
#define HH 64
#define LL 4
#define TPB 256                    // tiles per batch: EE/128
#define NTILES (BB * TPB)          // 4096
#define EDGE_GRID 444              // 148 SMs * 3 CTAs

// ---- scratch (device globals; no allocations allowed) ----
__device__ float d_g[BB * HH];
__device__ float d_h[BB * NN * HH];
__device__ float d_p1[BB * NN * HH];
__device__ float d_p2[BB * NN * HH];
__device__ float d_agg[BB * NN * HH];
__device__ int   d_rowptr[NN + 1];
__device__ int   d_rs[EE];
__device__ int   d_cs[EE];

// fast silu: MUFU-based divide; rel err ~2^-21 << tf32 noise
__device__ __forceinline__ float silu(float x) {
    return __fdividef(x, 1.0f + __expf(-x));
}

__device__ __forceinline__ uint32_t f2tf32(float x) {
    uint32_t r;
    asm("cvt.rna.tf32.f32 %0, %1;" : "=r"(r) : "f"(x));
    return r;
}

__device__ __forceinline__ void mma_tf32(float* c, const uint32_t* a, const uint32_t* b) {
    asm volatile(
        "mma.sync.aligned.m16n8k8.row.col.f32.tf32.tf32.f32 "
        "{%0,%1,%2,%3}, {%4,%5,%6,%7}, {%8,%9}, {%0,%1,%2,%3};"
        : "+f"(c[0]), "+f"(c[1]), "+f"(c[2]), "+f"(c[3])
        : "r"(a[0]), "r"(a[1]), "r"(a[2]), "r"(a[3]), "r"(b[0]), "r"(b[1]));
}

// ---- edge kernel SMEM layout ----
#define PAD_A 68
#define PAD_B 72
#define SME_A    0
#define SME_W2   34816
#define SME_BIAS (SME_W2 + 18432)
#define SME_R    (SME_BIAS + 256)
#define SME_TOTAL (SME_R + 512)

// ---- node kernel SMEM layout ----
#define PAD_NA 132
#define PAD_NP 136
#define SMN_A    0
#define SMN_B    33792
#define SMN_BIAS (SMN_B + 36864)
#define SMN_LN   (SMN_BIAS + 1280)
#define SMN_TOTAL (SMN_LN + 2048)

// ---- g = z @ Wg + bg ----
__global__ void g_kernel(const float* __restrict__ z,
                         const float* __restrict__ Wg,
                         const float* __restrict__ bg) {
    int t = blockIdx.x * blockDim.x + threadIdx.x;
    int b = t >> 6, k = t & 63;
    float acc = bg[k];
    const float* zr = z + b * LATENT;
    #pragma unroll 8
    for (int i = 0; i < LATENT; i++) acc += zr[i] * Wg[i * HH + k];
    d_g[t] = acc;
}

// ---- h + proj for layer 0 ----
__global__ void h_kernel(const float* __restrict__ nf,
                         const float* __restrict__ Wn,
                         const float* __restrict__ bn,
                         const float* __restrict__ eW1,
                         const float* __restrict__ eb1) {
    int node = blockIdx.x;
    int k = threadIdx.x;
    int b = node >> 10, n = node & (NN - 1);
    __shared__ float x[HH];
    float v = bn[k] + d_g[b * HH + k];
    v += nf[n * 3 + 0] * Wn[0 * HH + k]
       + nf[n * 3 + 1] * Wn[1 * HH + k]
       + nf[n * 3 + 2] * Wn[2 * HH + k];
    d_h[node * HH + k] = v;
    x[k] = v;
    __syncthreads();
    float a1 = eb1[k], a2 = 0.0f;
    #pragma unroll 8
    for (int i = 0; i < HH; i++) {
        float xv = x[i];
        a1 += xv * eW1[i * HH + k];
        a2 += xv * eW1[(HH + i) * HH + k];
    }
    d_p1[node * HH + k] = a1;
    d_p2[node * HH + k] = a2;
}

// ---- CSR build ----
__global__ void csr_kernel(const int* __restrict__ row,
                           const int* __restrict__ col) {
    __shared__ int sc[NN];
    __shared__ int wo[NN];
    int t = threadIdx.x;
    sc[t] = 0;
    __syncthreads();
    for (int e = t; e < EE; e += 1024) atomicAdd(&sc[row[e]], 1);
    __syncthreads();
    int v = sc[t];
    #pragma unroll
    for (int o = 1; o < NN; o <<= 1) {
        int u = (t >= o) ? sc[t - o] : 0;
        __syncthreads();
        sc[t] += u;
        __syncthreads();
    }
    d_rowptr[t + 1] = sc[t];
    if (t == 0) d_rowptr[0] = 0;
    wo[t] = sc[t] - v;
    __syncthreads();
    for (int e = t; e < EE; e += 1024) {
        int r = row[e];
        int p = atomicAdd(&wo[r], 1);
        d_rs[p] = r;
        d_cs[p] = col[e];
    }
}

// ---- fused edge kernel: 256 thr, 3 CTAs/SM ----
__global__ void __launch_bounds__(256, 3) edge_kernel(
    const float* __restrict__ eW2, const float* __restrict__ eb2) {
    extern __shared__ __align__(16) char smem[];
    float*    sAf = (float*)(smem + SME_A);
    uint32_t* sAu = (uint32_t*)(smem + SME_A);
    uint32_t* sW2 = (uint32_t*)(smem + SME_W2);
    float*    sB2 = (float*)(smem + SME_BIAS);
    int*      sR  = (int*)(smem + SME_R);

    int tid = threadIdx.x;
    int wid = tid >> 5;
    int lane = tid & 31;
    int g = lane >> 2;
    int tg = lane & 3;
    int rb = wid & 3;
    int ch = wid >> 1 & 0;     // placeholder; real ch below
    ch = wid >> 2;

    for (int idx = tid; idx < HH * HH; idx += 256) {
        int i = idx >> 6;
        int n = idx & 63;
        sW2[i * PAD_B + n] = f2tf32(eW2[idx]);
    }
    if (tid < HH) sB2[tid] = eb2[tid];
    __syncthreads();

    int rrow = tid & 127;
    int half = tid >> 7;

    for (int tile = blockIdx.x; tile < NTILES; tile += EDGE_GRID) {
        int b = tile >> 8;
        int jbase = (tile & (TPB - 1)) * 128;

        {
            int j = jbase + rrow;
            int r = d_rs[j], c = d_cs[j];
            if (half == 0) sR[rrow] = r;
            const float4* q1 = reinterpret_cast<const float4*>(
                d_p1 + (size_t)(b * NN + r) * HH + half * 32);
            const float4* q2 = reinterpret_cast<const float4*>(
                d_p2 + (size_t)(b * NN + c) * HH + half * 32);
            uint4* dst = reinterpret_cast<uint4*>(sAu + rrow * PAD_A + half * 32);
            #pragma unroll
            for (int i4 = 0; i4 < 8; i4++) {
                float4 u = q1[i4];
                float4 v = q2[i4];
                uint4 t;
                t.x = f2tf32(silu(u.x + v.x));
                t.y = f2tf32(silu(u.y + v.y));
                t.z = f2tf32(silu(u.z + v.z));
                t.w = f2tf32(silu(u.w + v.w));
                dst[i4] = t;
            }
        }
        __syncthreads();

        float acc[2][4][4];
        #pragma unroll
        for (int mt = 0; mt < 2; mt++)
            #pragma unroll
            for (int jj = 0; jj < 4; jj++)
                #pragma unroll
                for (int q = 0; q < 4; q++) acc[mt][jj][q] = 0.0f;

        #pragma unroll
        for (int ks = 0; ks < 8; ks++) {
            uint32_t af[2][4];
            #pragma unroll
            for (int mt = 0; mt < 2; mt++) {
                int rr = rb * 32 + mt * 16 + g;
                int cc = ks * 8 + tg;
                af[mt][0] = sAu[rr * PAD_A + cc];
                af[mt][1] = sAu[(rr + 8) * PAD_A + cc];
                af[mt][2] = sAu[rr * PAD_A + cc + 4];
                af[mt][3] = sAu[(rr + 8) * PAD_A + cc + 4];
            }
            uint32_t bf[4][2];
            #pragma unroll
            for (int jj = 0; jj < 4; jj++) {
                int n = ch * 32 + jj * 8 + g;
                bf[jj][0] = sW2[(ks * 8 + tg) * PAD_B + n];
                bf[jj][1] = sW2[(ks * 8 + tg + 4) * PAD_B + n];
            }
            #pragma unroll
            for (int mt = 0; mt < 2; mt++)
                #pragma unroll
                for (int jj = 0; jj < 4; jj++) mma_tf32(acc[mt][jj], af[mt], bf[jj]);
        }
        __syncthreads();

        #pragma unroll
        for (int mt = 0; mt < 2; mt++) {
            int r0 = rb * 32 + mt * 16 + g;
            #pragma unroll
            for (int jj = 0; jj < 4; jj++) {
                int c0 = ch * 32 + jj * 8 + tg * 2;
                sAf[r0 * PAD_A + c0]           = silu(acc[mt][jj][0] + sB2[c0]);
                sAf[r0 * PAD_A + c0 + 1]       = silu(acc[mt][jj][1] + sB2[c0 + 1]);
                sAf[(r0 + 8) * PAD_A + c0]     = silu(acc[mt][jj][2] + sB2[c0]);
                sAf[(r0 + 8) * PAD_A + c0 + 1] = silu(acc[mt][jj][3] + sB2[c0 + 1]);
            }
        }
        __syncthreads();

        {
            int k2 = tid & 63;
            int seg = tid >> 6;
            int r0 = seg * 32;
            int rcur = sR[r0];
            float a = 0.0f;
            #pragma unroll 8
            for (int rr = r0; rr < r0 + 32; rr++) {
                int rn = sR[rr];
                if (rn != rcur) {
                    atomicAdd(&d_agg[((size_t)b * NN + rcur) * HH + k2], a);
                    a = 0.0f;
                    rcur = rn;
                }
                a += sAf[rr * PAD_A + k2];
            }
            atomicAdd(&d_agg[((size_t)b * NN + rcur) * HH + k2], a);
        }
        __syncthreads();
    }
}

// ---- tensorized node kernel: 64 nodes/block, 3 tf32 GEMMs + LN ----
__global__ void __launch_bounds__(256, 3) node_kernel(
    const float* __restrict__ nW1, const float* __restrict__ nb1,
    const float* __restrict__ nW2, const float* __restrict__ nb2,
    const float* __restrict__ lng, const float* __restrict__ lnb,
    const float* __restrict__ eW1n, const float* __restrict__ eb1n) {
    extern __shared__ __align__(16) char smem[];
    float*    sAf = (float*)(smem + SMN_A);
    uint32_t* sAu = (uint32_t*)(smem + SMN_A);
    uint32_t* sB  = (uint32_t*)(smem + SMN_B);
    float*    sNB1 = (float*)(smem + SMN_BIAS);
    float*    sNB2 = sNB1 + 64;
    float*    sLG  = sNB1 + 128;
    float*    sLB  = sNB1 + 192;
    float*    sEB  = sNB1 + 256;
    float*    sLNs = (float*)(smem + SMN_LN);
    float*    sLNq = sLNs + 256;

    int tid = threadIdx.x;
    int wid = tid >> 5;
    int lane = tid & 31;
    int g = lane >> 2;
    int tg = lane & 3;
    int rw = wid & 1;
    int cw = wid >> 1;
    int node0 = blockIdx.x * 64;

    {
        int row = tid & 63;
        int qtr = tid >> 6;
        const float* src = (qtr < 2)
            ? d_h  + (size_t)(node0 + row) * HH + qtr * 32
            : d_agg + (size_t)(node0 + row) * HH + (qtr - 2) * 32;
        uint32_t* dst = sAu + row * PAD_NA + qtr * 32;
        #pragma unroll
        for (int i4 = 0; i4 < 8; i4++) {
            float4 v = reinterpret_cast<const float4*>(src)[i4];
            uint4 t;
            t.x = f2tf32(v.x); t.y = f2tf32(v.y);
            t.z = f2tf32(v.z); t.w = f2tf32(v.w);
            reinterpret_cast<uint4*>(dst)[i4] = t;
        }
        if (qtr >= 2) {
            float4* az = reinterpret_cast<float4*>(
                d_agg + (size_t)(node0 + row) * HH + (qtr - 2) * 32);
            #pragma unroll
            for (int i4 = 0; i4 < 8; i4++) az[i4] = make_float4(0, 0, 0, 0);
        }
    }
    for (int idx = tid; idx < 128 * 64; idx += 256) {
        sB[(idx >> 6) * PAD_B + (idx & 63)] = f2tf32(nW1[idx]);
    }
    if (tid < 64) {
        sNB1[tid] = nb1[tid];
        sNB2[tid] = nb2[tid];
        sLG[tid] = lng[tid];
        sLB[tid] = lnb[tid];
        if (eW1n) sEB[tid] = eb1n[tid];
    }
    __syncthreads();

    float acc[2][2][4];
    #pragma unroll
    for (int mt = 0; mt < 2; mt++)
        #pragma unroll
        for (int nt = 0; nt < 2; nt++)
            #pragma unroll
            for (int q = 0; q < 4; q++) acc[mt][nt][q] = 0.0f;
    #pragma unroll
    for (int ks = 0; ks < 16; ks++) {
        uint32_t af[2][4];
        #pragma unroll
        for (int mt = 0; mt < 2; mt++) {
            int rr = rw * 32 + mt * 16 + g;
            int cc = ks * 8 + tg;
            af[mt][0] = sAu[rr * PAD_NA + cc];
            af[mt][1] = sAu[(rr + 8) * PAD_NA + cc];
            af[mt][2] = sAu[rr * PAD_NA + cc + 4];
            af[mt][3] = sAu[(rr + 8) * PAD_NA + cc + 4];
        }
        uint32_t bf[2][2];
        #pragma unroll
        for (int nt = 0; nt < 2; nt++) {
            int n = cw * 16 + nt * 8 + g;
            bf[nt][0] = sB[(ks * 8 + tg) * PAD_B + n];
            bf[nt][1] = sB[(ks * 8 + tg + 4) * PAD_B + n];
        }
        #pragma unroll
        for (int mt = 0; mt < 2; mt++)
            #pragma unroll
            for (int nt = 0; nt < 2; nt++) mma_tf32(acc[mt][nt], af[mt], bf[nt]);
    }
    __syncthreads();

    #pragma unroll
    for (int mt = 0; mt < 2; mt++) {
        int r0 = rw * 32 + mt * 16 + g;
        #pragma unroll
        for (int nt = 0; nt < 2; nt++) {
            int c0 = cw * 16 + nt * 8 + tg * 2;
            sAu[r0 * PAD_NA + c0]           = f2tf32(silu(acc[mt][nt][0] + sNB1[c0]));
            sAu[r0 * PAD_NA + c0 + 1]       = f2tf32(silu(acc[mt][nt][1] + sNB1[c0 + 1]));
            sAu[(r0 + 8) * PAD_NA + c0]     = f2tf32(silu(acc[mt][nt][2] + sNB1[c0]));
            sAu[(r0 + 8) * PAD_NA + c0 + 1] = f2tf32(silu(acc[mt][nt][3] + sNB1[c0 + 1]));
        }
    }
    for (int idx = tid; idx < 64 * 64; idx += 256) {
        sB[(idx >> 6) * PAD_B + (idx & 63)] = f2tf32(nW2[idx]);
    }
    __syncthreads();

    #pragma unroll
    for (int mt = 0; mt < 2; mt++)
        #pragma unroll
        for (int nt = 0; nt < 2; nt++)
            #pragma unroll
            for (int q = 0; q < 4; q++) acc[mt][nt][q] = 0.0f;
    #pragma unroll
    for (int ks = 0; ks < 8; ks++) {
        uint32_t af[2][4];
        #pragma unroll
        for (int mt = 0; mt < 2; mt++) {
            int rr = rw * 32 + mt * 16 + g;
            int cc = ks * 8 + tg;
            af[mt][0] = sAu[rr * PAD_NA + cc];
            af[mt][1] = sAu[(rr + 8) * PAD_NA + cc];
            af[mt][2] = sAu[rr * PAD_NA + cc + 4];
            af[mt][3] = sAu[(rr + 8) * PAD_NA + cc + 4];
        }
        uint32_t bf[2][2];
        #pragma unroll
        for (int nt = 0; nt < 2; nt++) {
            int n = cw * 16 + nt * 8 + g;
            bf[nt][0] = sB[(ks * 8 + tg) * PAD_B + n];
            bf[nt][1] = sB[(ks * 8 + tg + 4) * PAD_B + n];
        }
        #pragma unroll
        for (int mt = 0; mt < 2; mt++)
            #pragma unroll
            for (int nt = 0; nt < 2; nt++) mma_tf32(acc[mt][nt], af[mt], bf[nt]);
    }
    __syncthreads();

    #pragma unroll
    for (int mt = 0; mt < 2; mt++) {
        int r0 = rw * 32 + mt * 16 + g;
        #pragma unroll
        for (int nt = 0; nt < 2; nt++) {
            int c0 = cw * 16 + nt * 8 + tg * 2;
            float2 h0 = *reinterpret_cast<const float2*>(d_h + (size_t)(node0 + r0) * HH + c0);
            float2 h1 = *reinterpret_cast<const float2*>(d_h + (size_t)(node0 + r0 + 8) * HH + c0);
            sAf[r0 * PAD_NA + c0]           = h0.x + acc[mt][nt][0] + sNB2[c0];
            sAf[r0 * PAD_NA + c0 + 1]       = h0.y + acc[mt][nt][1] + sNB2[c0 + 1];
            sAf[(r0 + 8) * PAD_NA + c0]     = h1.x + acc[mt][nt][2] + sNB2[c0];
            sAf[(r0 + 8) * PAD_NA + c0 + 1] = h1.y + acc[mt][nt][3] + sNB2[c0 + 1];
        }
    }
    if (eW1n) {
        for (int idx = tid; idx < 64 * 128; idx += 256) {
            int i = idx >> 7, n = idx & 127;
            float v = (n < 64) ? eW1n[i * HH + n] : eW1n[(64 + i) * HH + (n - 64)];
            sB[i * PAD_NP + n] = f2tf32(v);
        }
    }
    __syncthreads();

    {
        int row = tid >> 2;
        int part = tid & 3;
        float s = 0.0f, q = 0.0f;
        #pragma unroll
        for (int i = 0; i < 16; i++) {
            float v = sAf[row * PAD_NA + part * 16 + i];
            s += v;
            q += v * v;
        }
        sLNs[row * 4 + part] = s;
        sLNq[row * 4 + part] = q;
    }
    __syncthreads();
    {
        int row = tid >> 2;
        int part = tid & 3;
        float s = sLNs[row * 4] + sLNs[row * 4 + 1] + sLNs[row * 4 + 2] + sLNs[row * 4 + 3];
        float q = sLNq[row * 4] + sLNq[row * 4 + 1] + sLNq[row * 4 + 2] + sLNq[row * 4 + 3];
        float mu = s * (1.0f / HH);
        float var = q * (1.0f / HH) - mu * mu;
        float rstd = rsqrtf(var + 1e-5f);
        float hv[16];
        #pragma unroll
        for (int i = 0; i < 16; i++) {
            int c = part * 16 + i;
            hv[i] = (sAf[row * PAD_NA + c] - mu) * rstd * sLG[c] + sLB[c];
        }
        float4* hout = reinterpret_cast<float4*>(d_h + (size_t)(node0 + row) * HH + part * 16);
        #pragma unroll
        for (int i4 = 0; i4 < 4; i4++)
            hout[i4] = make_float4(hv[i4 * 4], hv[i4 * 4 + 1], hv[i4 * 4 + 2], hv[i4 * 4 + 3]);
        __syncthreads();
        #pragma unroll
        for (int i = 0; i < 16; i++)
            sAu[row * PAD_NA + part * 16 + i] = f2tf32(hv[i]);
    }
    __syncthreads();

    if (!eW1n) return;

    float acc3[2][4][4];
    #pragma unroll
    for (int mt = 0; mt < 2; mt++)
        #pragma unroll
        for (int nt = 0; nt < 4; nt++)
            #pragma unroll
            for (int q = 0; q < 4; q++) acc3[mt][nt][q] = 0.0f;
    #pragma unroll
    for (int ks = 0; ks < 8; ks++) {
        uint32_t af[2][4];
        #pragma unroll
        for (int mt = 0; mt < 2; mt++) {
            int rr = rw * 32 + mt * 16 + g;
            int cc = ks * 8 + tg;
            af[mt][0] = sAu[rr * PAD_NA + cc];
            af[mt][1] = sAu[(rr + 8) * PAD_NA + cc];
            af[mt][2] = sAu[rr * PAD_NA + cc + 4];
            af[mt][3] = sAu[(rr + 8) * PAD_NA + cc + 4];
        }
        uint32_t bf[4][2];
        #pragma unroll
        for (int nt = 0; nt < 4; nt++) {
            int n = cw * 32 + nt * 8 + g;
            bf[nt][0] = sB[(ks * 8 + tg) * PAD_NP + n];
            bf[nt][1] = sB[(ks * 8 + tg + 4) * PAD_NP + n];
        }
        #pragma unroll
        for (int mt = 0; mt < 2; mt++)
            #pragma unroll
            for (int nt = 0; nt < 4; nt++) mma_tf32(acc3[mt][nt], af[mt], bf[nt]);
    }

    #pragma unroll
    for (int mt = 0; mt < 2; mt++) {
        int r0 = rw * 32 + mt * 16 + g;
        #pragma unroll
        for (int nt = 0; nt < 4; nt++) {
            int c0 = cw * 32 + nt * 8 + tg * 2;
            #pragma unroll
            for (int hh = 0; hh < 2; hh++) {
                int rr = r0 + hh * 8;
                float v0 = acc3[mt][nt][hh * 2];
                float v1 = acc3[mt][nt][hh * 2 + 1];
                if (c0 < 64) {
                    v0 += sEB[c0];
                    v1 += sEB[c0 + 1];
                    *reinterpret_cast<float2*>(d_p1 + (size_t)(node0 + rr) * HH + c0)
                        = make_float2(v0, v1);
                } else {
                    *reinterpret_cast<float2*>(d_p2 + (size_t)(node0 + rr) * HH + (c0 - 64))
                        = make_float2(v0, v1);
                }
            }
        }
    }
}

// ---- output head; 4 nodes per 256-thread block ----
__global__ void __launch_bounds__(256) out_kernel(
    const float* __restrict__ oW1, const float* __restrict__ ob1,
    const float* __restrict__ oW2, const float* __restrict__ ob2,
    float* __restrict__ out) {
    int sub = threadIdx.x >> 6;
    int k = threadIdx.x & 63;
    int node = blockIdx.x * 4 + sub;
    __shared__ float x[4][HH];
    __shared__ float r[4][HH];
    x[sub][k] = d_h[node * HH + k];
    __syncthreads();
    float acc = ob1[k];
    #pragma unroll 8
    for (int i = 0; i < HH; i++) acc += x[sub][i] * oW1[i * HH + k];
    r[sub][k] = fmaxf(acc, 0.0f);
    __syncthreads();
    if (k < 3) {
        float o = ob2[k];
        #pragma unroll 8
        for (int i = 0; i < HH; i++) o += r[sub][i] * oW2[i * 3 + k];
        out[node * 3 + k] = o;
    }
}

extern "C" void kernel_launch(void* const* d_in, const int* in_sizes, int n_in,
                              void* d_out, int out_size) {
    const float* z   = (const float*)d_in[0];
    const int*   ei  = (const int*)d_in[1];
    const float* nf  = (const float*)d_in[2];
    const float* Wg  = (const float*)d_in[3];
    const float* bg  = (const float*)d_in[4];
    const float* Wn  = (const float*)d_in[5];
    const float* bn  = (const float*)d_in[6];
    const float* eW1 = (const float*)d_in[7];
    const float* eb1 = (const float*)d_in[8];
    const float* eW2 = (const float*)d_in[9];
    const float* eb2 = (const float*)d_in[10];
    const float* nW1 = (const float*)d_in[14];
    const float* nb1 = (const float*)d_in[15];
    const float* nW2 = (const float*)d_in[16];
    const float* nb2 = (const float*)d_in[17];
    const float* lng = (const float*)d_in[18];
    const float* lnb = (const float*)d_in[19];
    const float* oW1 = (const float*)d_in[20];
    const float* ob1 = (const float*)d_in[21];
    const float* oW2 = (const float*)d_in[22];
    const float* ob2 = (const float*)d_in[23];

    void* pAgg;
    cudaGetSymbolAddress(&pAgg, d_agg);
    cudaMemsetAsync(pAgg, 0, sizeof(float) * BB * NN * HH);

    cudaFuncSetAttribute((const void*)edge_kernel,
                         cudaFuncAttributeMaxDynamicSharedMemorySize, SME_TOTAL);
    cudaFuncSetAttribute((const void*)node_kernel,
                         cudaFuncAttributeMaxDynamicSharedMemorySize, SMN_TOTAL);

    g_kernel<<<1, 1024>>>(z, Wg, bg);
    h_kernel<<<BB * NN, HH>>>(nf, Wn, bn, eW1, eb1);
    csr_kernel<<<1, 1024>>>(ei, ei + EE);

    for (int l = 0; l < LL; l++) {
        edge_kernel<<<EDGE_GRID, 256, SME_TOTAL>>>(
            eW2 + (size_t)l * HH * HH, eb2 + l * HH);
        const float* eW1n = (l + 1 < LL) ? eW1 + (size_t)(l + 1) * 129 * HH : nullptr;
        const float* eb1n = (l + 1 < LL) ? eb1 + (l + 1) * HH : nullptr;
        node_kernel<<<BB * NN / 64, 256, SMN_TOTAL>>>(
            nW1 + (size_t)l * 2 * HH * HH, nb1 + l * HH,
            nW2 + (size_t)l * HH * HH, nb2 + l * HH,
            lng + l * HH, lnb + l * HH,
            eW1n, eb1n);
    }

    out_kernel<<<BB * NN / 4, 256>>>(oW1, ob1, oW2, ob2, (float*)d_out);
}

// round 13
// speedup vs baseline: 1.3444x; 1.0490x over previous
#include <cuda_runtime.h>
#include <cstdint>

#define BB 16
#define LATENT 128
#define NN 1024
#define EE 32768
#define HH 64
#define LL 4
#define TPB 256                    // tiles per batch: EE/128
#define NTILES (BB * TPB)          // 4096
#define EDGE_GRID 444              // 148 SMs * 3 CTAs

// ---- scratch (device globals; no allocations allowed) ----
__device__ float d_g[BB * HH];
__device__ float d_h[BB * NN * HH];
__device__ float d_p1[BB * NN * HH];
__device__ float d_p2[BB * NN * HH];
__device__ float d_agg[BB * NN * HH];
__device__ int   d_rowptr[NN + 1];
__device__ int   d_rs[EE];
__device__ int   d_cs[EE];

__device__ __forceinline__ float silu(float x) {
    return __fdividef(x, 1.0f + __expf(-x));
}

__device__ __forceinline__ uint32_t f2tf32(float x) {
    uint32_t r;
    asm("cvt.rna.tf32.f32 %0, %1;" : "=r"(r) : "f"(x));
    return r;
}

__device__ __forceinline__ void mma_tf32(float* c, const uint32_t* a, const uint32_t* b) {
    asm volatile(
        "mma.sync.aligned.m16n8k8.row.col.f32.tf32.tf32.f32 "
        "{%0,%1,%2,%3}, {%4,%5,%6,%7}, {%8,%9}, {%0,%1,%2,%3};"
        : "+f"(c[0]), "+f"(c[1]), "+f"(c[2]), "+f"(c[3])
        : "r"(a[0]), "r"(a[1]), "r"(a[2]), "r"(a[3]), "r"(b[0]), "r"(b[1]));
}

// ---- edge kernel SMEM layout ----
#define PAD_A 68
#define SME_A     0                 // 128*68*4 = 34816
#define SME_W2P   34816             // packed B pairs: 32*68*8 = 17408
#define SME_B2    52224             // 256
#define SME_R     52480             // 512
#define SME_P1    52992             // p1 cache: 16*64*4 = 4096
#define SME_TOTAL 57088

// ---- node kernel SMEM layout ----
#define PAD_B  72
#define PAD_NA 132
#define PAD_NP 136
#define SMN_A    0
#define SMN_B    33792
#define SMN_BIAS (SMN_B + 36864)
#define SMN_LN   (SMN_BIAS + 1280)
#define SMN_TOTAL (SMN_LN + 2048)

// ---- g = z @ Wg + bg ----
__global__ void g_kernel(const float* __restrict__ z,
                         const float* __restrict__ Wg,
                         const float* __restrict__ bg) {
    int t = blockIdx.x * blockDim.x + threadIdx.x;
    int b = t >> 6, k = t & 63;
    float acc = bg[k];
    const float* zr = z + b * LATENT;
    #pragma unroll 8
    for (int i = 0; i < LATENT; i++) acc += zr[i] * Wg[i * HH + k];
    d_g[t] = acc;
}

// ---- h + proj for layer 0; 4 nodes per block ----
__global__ void __launch_bounds__(256) h_kernel(
    const float* __restrict__ nf, const float* __restrict__ Wn,
    const float* __restrict__ bn, const float* __restrict__ eW1,
    const float* __restrict__ eb1) {
    int sub = threadIdx.x >> 6;
    int k = threadIdx.x & 63;
    int node = blockIdx.x * 4 + sub;
    int b = node >> 10, n = node & (NN - 1);
    __shared__ float x[4][HH];
    float v = bn[k] + d_g[b * HH + k];
    v += nf[n * 3 + 0] * Wn[0 * HH + k]
       + nf[n * 3 + 1] * Wn[1 * HH + k]
       + nf[n * 3 + 2] * Wn[2 * HH + k];
    d_h[node * HH + k] = v;
    x[sub][k] = v;
    __syncthreads();
    float a1 = eb1[k], a2 = 0.0f;
    #pragma unroll 8
    for (int i = 0; i < HH; i++) {
        float xv = x[sub][i];
        a1 += xv * eW1[i * HH + k];
        a2 += xv * eW1[(HH + i) * HH + k];
    }
    d_p1[node * HH + k] = a1;
    d_p2[node * HH + k] = a2;
}

// ---- CSR build ----
__global__ void csr_kernel(const int* __restrict__ row,
                           const int* __restrict__ col) {
    __shared__ int sc[NN];
    __shared__ int wo[NN];
    int t = threadIdx.x;
    sc[t] = 0;
    __syncthreads();
    for (int e = t; e < EE; e += 1024) atomicAdd(&sc[row[e]], 1);
    __syncthreads();
    int v = sc[t];
    #pragma unroll
    for (int o = 1; o < NN; o <<= 1) {
        int u = (t >= o) ? sc[t - o] : 0;
        __syncthreads();
        sc[t] += u;
        __syncthreads();
    }
    d_rowptr[t + 1] = sc[t];
    if (t == 0) d_rowptr[0] = 0;
    wo[t] = sc[t] - v;
    __syncthreads();
    for (int e = t; e < EE; e += 1024) {
        int r = row[e];
        int p = atomicAdd(&wo[r], 1);
        d_rs[p] = r;
        d_cs[p] = col[e];
    }
}

// ---- fused edge kernel: p1 smem cache + packed-B LDS.64 GEMM ----
__global__ void __launch_bounds__(256, 3) edge_kernel(
    const float* __restrict__ eW2, const float* __restrict__ eb2) {
    extern __shared__ __align__(16) char smem[];
    float*    sAf  = (float*)(smem + SME_A);
    uint32_t* sAu  = (uint32_t*)(smem + SME_A);
    uint32_t* sW2p = (uint32_t*)(smem + SME_W2P);
    const uint2* sW2p2 = (const uint2*)(smem + SME_W2P);
    float*    sB2  = (float*)(smem + SME_B2);
    int*      sR   = (int*)(smem + SME_R);
    float*    sP1  = (float*)(smem + SME_P1);

    int tid = threadIdx.x;
    int wid = tid >> 5;
    int lane = tid & 31;
    int g = lane >> 2;
    int tg = lane & 3;
    int rb = wid & 3;
    int ch = wid >> 2;

    // stage weights as packed pairs: (W[ks*8+tg][n], W[ks*8+tg+4][n]) contiguous
    for (int idx = tid; idx < HH * HH; idx += 256) {
        int i = idx >> 6;      // k index
        int n = idx & 63;
        int ks = i >> 3;
        int r8 = i & 7;
        int tgw = (r8 < 4) ? r8 : r8 - 4;
        int slot = (r8 < 4) ? 0 : 1;
        sW2p[(((ks * 4 + tgw) * 68) + n) * 2 + slot] = f2tf32(eW2[idx]);
    }
    if (tid < HH) sB2[tid] = eb2[tid];
    __syncthreads();

    int rrow = tid & 127;
    int half = tid >> 7;

    for (int tile = blockIdx.x; tile < NTILES; tile += EDGE_GRID) {
        int b = tile >> 8;
        int jbase = (tile & (TPB - 1)) * 128;

        int j = jbase + rrow;
        int r = d_rs[j], c = d_cs[j];
        if (half == 0) sR[rrow] = r;
        __syncthreads();                       // sR visible

        int r0v = sR[0];
        int nseg = sR[127] - r0v + 1;          // rows are sorted -> range
        if (nseg <= 16) {
            // cooperative load of p1 rows r0v..r0v+nseg-1 (coalesced)
            for (int u = tid; u < nseg * 16; u += 256) {
                int s = u >> 4, q = (u & 15) * 4;
                float4 val = *reinterpret_cast<const float4*>(
                    d_p1 + (size_t)(b * NN + r0v + s) * HH + q);
                *reinterpret_cast<float4*>(sP1 + s * 64 + q) = val;
            }
        }
        __syncthreads();                       // sP1 ready

        // a-stage
        {
            const float4* q2 = reinterpret_cast<const float4*>(
                d_p2 + (size_t)(b * NN + c) * HH + half * 32);
            const float4* P1 = (nseg <= 16)
                ? reinterpret_cast<const float4*>(sP1 + (r - r0v) * 64 + half * 32)
                : reinterpret_cast<const float4*>(
                      d_p1 + (size_t)(b * NN + r) * HH + half * 32);
            uint4* dst = reinterpret_cast<uint4*>(sAu + rrow * PAD_A + half * 32);
            #pragma unroll
            for (int i4 = 0; i4 < 8; i4++) {
                float4 u = P1[i4];
                float4 v = q2[i4];
                uint4 t;
                t.x = f2tf32(silu(u.x + v.x));
                t.y = f2tf32(silu(u.y + v.y));
                t.z = f2tf32(silu(u.z + v.z));
                t.w = f2tf32(silu(u.w + v.w));
                dst[i4] = t;
            }
        }
        __syncthreads();

        // GEMM: warp computes rows rb*32..+31, cols ch*32..+31
        float acc[2][4][4];
        #pragma unroll
        for (int mt = 0; mt < 2; mt++)
            #pragma unroll
            for (int jj = 0; jj < 4; jj++)
                #pragma unroll
                for (int q = 0; q < 4; q++) acc[mt][jj][q] = 0.0f;

        #pragma unroll
        for (int ks = 0; ks < 8; ks++) {
            uint32_t af[2][4];
            #pragma unroll
            for (int mt = 0; mt < 2; mt++) {
                int rr = rb * 32 + mt * 16 + g;
                int cc = ks * 8 + tg;
                af[mt][0] = sAu[rr * PAD_A + cc];
                af[mt][1] = sAu[(rr + 8) * PAD_A + cc];
                af[mt][2] = sAu[rr * PAD_A + cc + 4];
                af[mt][3] = sAu[(rr + 8) * PAD_A + cc + 4];
            }
            uint32_t bf[4][2];
            #pragma unroll
            for (int jj = 0; jj < 4; jj++) {
                int n = ch * 32 + jj * 8 + g;
                uint2 bv = sW2p2[(ks * 4 + tg) * 68 + n];
                bf[jj][0] = bv.x;
                bf[jj][1] = bv.y;
            }
            #pragma unroll
            for (int mt = 0; mt < 2; mt++)
                #pragma unroll
                for (int jj = 0; jj < 4; jj++) mma_tf32(acc[mt][jj], af[mt], bf[jj]);
        }
        __syncthreads();

        // epilogue: m = silu(raw + b2) -> smem rows
        #pragma unroll
        for (int mt = 0; mt < 2; mt++) {
            int r0 = rb * 32 + mt * 16 + g;
            #pragma unroll
            for (int jj = 0; jj < 4; jj++) {
                int c0 = ch * 32 + jj * 8 + tg * 2;
                sAf[r0 * PAD_A + c0]           = silu(acc[mt][jj][0] + sB2[c0]);
                sAf[r0 * PAD_A + c0 + 1]       = silu(acc[mt][jj][1] + sB2[c0 + 1]);
                sAf[(r0 + 8) * PAD_A + c0]     = silu(acc[mt][jj][2] + sB2[c0]);
                sAf[(r0 + 8) * PAD_A + c0 + 1] = silu(acc[mt][jj][3] + sB2[c0 + 1]);
            }
        }
        __syncthreads();

        // segmented reduction: thread = (column k2, quarter seg)
        {
            int k2 = tid & 63;
            int seg = tid >> 6;
            int r0 = seg * 32;
            int rcur = sR[r0];
            float a = 0.0f;
            #pragma unroll 8
            for (int rr = r0; rr < r0 + 32; rr++) {
                int rn = sR[rr];
                if (rn != rcur) {
                    atomicAdd(&d_agg[((size_t)b * NN + rcur) * HH + k2], a);
                    a = 0.0f;
                    rcur = rn;
                }
                a += sAf[rr * PAD_A + k2];
            }
            atomicAdd(&d_agg[((size_t)b * NN + rcur) * HH + k2], a);
        }
        __syncthreads();
    }
}

// ---- tensorized node kernel: 64 nodes/block, 3 tf32 GEMMs + LN ----
__global__ void __launch_bounds__(256, 3) node_kernel(
    const float* __restrict__ nW1, const float* __restrict__ nb1,
    const float* __restrict__ nW2, const float* __restrict__ nb2,
    const float* __restrict__ lng, const float* __restrict__ lnb,
    const float* __restrict__ eW1n, const float* __restrict__ eb1n) {
    extern __shared__ __align__(16) char smem[];
    float*    sAf = (float*)(smem + SMN_A);
    uint32_t* sAu = (uint32_t*)(smem + SMN_A);
    uint32_t* sB  = (uint32_t*)(smem + SMN_B);
    float*    sNB1 = (float*)(smem + SMN_BIAS);
    float*    sNB2 = sNB1 + 64;
    float*    sLG  = sNB1 + 128;
    float*    sLB  = sNB1 + 192;
    float*    sEB  = sNB1 + 256;
    float*    sLNs = (float*)(smem + SMN_LN);
    float*    sLNq = sLNs + 256;

    int tid = threadIdx.x;
    int wid = tid >> 5;
    int lane = tid & 31;
    int g = lane >> 2;
    int tg = lane & 3;
    int rw = wid & 1;
    int cw = wid >> 1;
    int node0 = blockIdx.x * 64;

    {
        int row = tid & 63;
        int qtr = tid >> 6;
        const float* src = (qtr < 2)
            ? d_h  + (size_t)(node0 + row) * HH + qtr * 32
            : d_agg + (size_t)(node0 + row) * HH + (qtr - 2) * 32;
        uint32_t* dst = sAu + row * PAD_NA + qtr * 32;
        #pragma unroll
        for (int i4 = 0; i4 < 8; i4++) {
            float4 v = reinterpret_cast<const float4*>(src)[i4];
            uint4 t;
            t.x = f2tf32(v.x); t.y = f2tf32(v.y);
            t.z = f2tf32(v.z); t.w = f2tf32(v.w);
            reinterpret_cast<uint4*>(dst)[i4] = t;
        }
        if (qtr >= 2) {
            float4* az = reinterpret_cast<float4*>(
                d_agg + (size_t)(node0 + row) * HH + (qtr - 2) * 32);
            #pragma unroll
            for (int i4 = 0; i4 < 8; i4++) az[i4] = make_float4(0, 0, 0, 0);
        }
    }
    for (int idx = tid; idx < 128 * 64; idx += 256) {
        sB[(idx >> 6) * PAD_B + (idx & 63)] = f2tf32(nW1[idx]);
    }
    if (tid < 64) {
        sNB1[tid] = nb1[tid];
        sNB2[tid] = nb2[tid];
        sLG[tid] = lng[tid];
        sLB[tid] = lnb[tid];
        if (eW1n) sEB[tid] = eb1n[tid];
    }
    __syncthreads();

    float acc[2][2][4];
    #pragma unroll
    for (int mt = 0; mt < 2; mt++)
        #pragma unroll
        for (int nt = 0; nt < 2; nt++)
            #pragma unroll
            for (int q = 0; q < 4; q++) acc[mt][nt][q] = 0.0f;
    #pragma unroll
    for (int ks = 0; ks < 16; ks++) {
        uint32_t af[2][4];
        #pragma unroll
        for (int mt = 0; mt < 2; mt++) {
            int rr = rw * 32 + mt * 16 + g;
            int cc = ks * 8 + tg;
            af[mt][0] = sAu[rr * PAD_NA + cc];
            af[mt][1] = sAu[(rr + 8) * PAD_NA + cc];
            af[mt][2] = sAu[rr * PAD_NA + cc + 4];
            af[mt][3] = sAu[(rr + 8) * PAD_NA + cc + 4];
        }
        uint32_t bf[2][2];
        #pragma unroll
        for (int nt = 0; nt < 2; nt++) {
            int n = cw * 16 + nt * 8 + g;
            bf[nt][0] = sB[(ks * 8 + tg) * PAD_B + n];
            bf[nt][1] = sB[(ks * 8 + tg + 4) * PAD_B + n];
        }
        #pragma unroll
        for (int mt = 0; mt < 2; mt++)
            #pragma unroll
            for (int nt = 0; nt < 2; nt++) mma_tf32(acc[mt][nt], af[mt], bf[nt]);
    }
    __syncthreads();

    #pragma unroll
    for (int mt = 0; mt < 2; mt++) {
        int r0 = rw * 32 + mt * 16 + g;
        #pragma unroll
        for (int nt = 0; nt < 2; nt++) {
            int c0 = cw * 16 + nt * 8 + tg * 2;
            sAu[r0 * PAD_NA + c0]           = f2tf32(silu(acc[mt][nt][0] + sNB1[c0]));
            sAu[r0 * PAD_NA + c0 + 1]       = f2tf32(silu(acc[mt][nt][1] + sNB1[c0 + 1]));
            sAu[(r0 + 8) * PAD_NA + c0]     = f2tf32(silu(acc[mt][nt][2] + sNB1[c0]));
            sAu[(r0 + 8) * PAD_NA + c0 + 1] = f2tf32(silu(acc[mt][nt][3] + sNB1[c0 + 1]));
        }
    }
    for (int idx = tid; idx < 64 * 64; idx += 256) {
        sB[(idx >> 6) * PAD_B + (idx & 63)] = f2tf32(nW2[idx]);
    }
    __syncthreads();

    #pragma unroll
    for (int mt = 0; mt < 2; mt++)
        #pragma unroll
        for (int nt = 0; nt < 2; nt++)
            #pragma unroll
            for (int q = 0; q < 4; q++) acc[mt][nt][q] = 0.0f;
    #pragma unroll
    for (int ks = 0; ks < 8; ks++) {
        uint32_t af[2][4];
        #pragma unroll
        for (int mt = 0; mt < 2; mt++) {
            int rr = rw * 32 + mt * 16 + g;
            int cc = ks * 8 + tg;
            af[mt][0] = sAu[rr * PAD_NA + cc];
            af[mt][1] = sAu[(rr + 8) * PAD_NA + cc];
            af[mt][2] = sAu[rr * PAD_NA + cc + 4];
            af[mt][3] = sAu[(rr + 8) * PAD_NA + cc + 4];
        }
        uint32_t bf[2][2];
        #pragma unroll
        for (int nt = 0; nt < 2; nt++) {
            int n = cw * 16 + nt * 8 + g;
            bf[nt][0] = sB[(ks * 8 + tg) * PAD_B + n];
            bf[nt][1] = sB[(ks * 8 + tg + 4) * PAD_B + n];
        }
        #pragma unroll
        for (int mt = 0; mt < 2; mt++)
            #pragma unroll
            for (int nt = 0; nt < 2; nt++) mma_tf32(acc[mt][nt], af[mt], bf[nt]);
    }
    __syncthreads();

    #pragma unroll
    for (int mt = 0; mt < 2; mt++) {
        int r0 = rw * 32 + mt * 16 + g;
        #pragma unroll
        for (int nt = 0; nt < 2; nt++) {
            int c0 = cw * 16 + nt * 8 + tg * 2;
            float2 h0 = *reinterpret_cast<const float2*>(d_h + (size_t)(node0 + r0) * HH + c0);
            float2 h1 = *reinterpret_cast<const float2*>(d_h + (size_t)(node0 + r0 + 8) * HH + c0);
            sAf[r0 * PAD_NA + c0]           = h0.x + acc[mt][nt][0] + sNB2[c0];
            sAf[r0 * PAD_NA + c0 + 1]       = h0.y + acc[mt][nt][1] + sNB2[c0 + 1];
            sAf[(r0 + 8) * PAD_NA + c0]     = h1.x + acc[mt][nt][2] + sNB2[c0];
            sAf[(r0 + 8) * PAD_NA + c0 + 1] = h1.y + acc[mt][nt][3] + sNB2[c0 + 1];
        }
    }
    if (eW1n) {
        for (int idx = tid; idx < 64 * 128; idx += 256) {
            int i = idx >> 7, n = idx & 127;
            float v = (n < 64) ? eW1n[i * HH + n] : eW1n[(64 + i) * HH + (n - 64)];
            sB[i * PAD_NP + n] = f2tf32(v);
        }
    }
    __syncthreads();

    {
        int row = tid >> 2;
        int part = tid & 3;
        float s = 0.0f, q = 0.0f;
        #pragma unroll
        for (int i = 0; i < 16; i++) {
            float v = sAf[row * PAD_NA + part * 16 + i];
            s += v;
            q += v * v;
        }
        sLNs[row * 4 + part] = s;
        sLNq[row * 4 + part] = q;
    }
    __syncthreads();
    {
        int row = tid >> 2;
        int part = tid & 3;
        float s = sLNs[row * 4] + sLNs[row * 4 + 1] + sLNs[row * 4 + 2] + sLNs[row * 4 + 3];
        float q = sLNq[row * 4] + sLNq[row * 4 + 1] + sLNq[row * 4 + 2] + sLNq[row * 4 + 3];
        float mu = s * (1.0f / HH);
        float var = q * (1.0f / HH) - mu * mu;
        float rstd = rsqrtf(var + 1e-5f);
        float hv[16];
        #pragma unroll
        for (int i = 0; i < 16; i++) {
            int c = part * 16 + i;
            hv[i] = (sAf[row * PAD_NA + c] - mu) * rstd * sLG[c] + sLB[c];
        }
        float4* hout = reinterpret_cast<float4*>(d_h + (size_t)(node0 + row) * HH + part * 16);
        #pragma unroll
        for (int i4 = 0; i4 < 4; i4++)
            hout[i4] = make_float4(hv[i4 * 4], hv[i4 * 4 + 1], hv[i4 * 4 + 2], hv[i4 * 4 + 3]);
        __syncthreads();
        #pragma unroll
        for (int i = 0; i < 16; i++)
            sAu[row * PAD_NA + part * 16 + i] = f2tf32(hv[i]);
    }
    __syncthreads();

    if (!eW1n) return;

    float acc3[2][4][4];
    #pragma unroll
    for (int mt = 0; mt < 2; mt++)
        #pragma unroll
        for (int nt = 0; nt < 4; nt++)
            #pragma unroll
            for (int q = 0; q < 4; q++) acc3[mt][nt][q] = 0.0f;
    #pragma unroll
    for (int ks = 0; ks < 8; ks++) {
        uint32_t af[2][4];
        #pragma unroll
        for (int mt = 0; mt < 2; mt++) {
            int rr = rw * 32 + mt * 16 + g;
            int cc = ks * 8 + tg;
            af[mt][0] = sAu[rr * PAD_NA + cc];
            af[mt][1] = sAu[(rr + 8) * PAD_NA + cc];
            af[mt][2] = sAu[rr * PAD_NA + cc + 4];
            af[mt][3] = sAu[(rr + 8) * PAD_NA + cc + 4];
        }
        uint32_t bf[4][2];
        #pragma unroll
        for (int nt = 0; nt < 4; nt++) {
            int n = cw * 32 + nt * 8 + g;
            bf[nt][0] = sB[(ks * 8 + tg) * PAD_NP + n];
            bf[nt][1] = sB[(ks * 8 + tg + 4) * PAD_NP + n];
        }
        #pragma unroll
        for (int mt = 0; mt < 2; mt++)
            #pragma unroll
            for (int nt = 0; nt < 4; nt++) mma_tf32(acc3[mt][nt], af[mt], bf[nt]);
    }

    #pragma unroll
    for (int mt = 0; mt < 2; mt++) {
        int r0 = rw * 32 + mt * 16 + g;
        #pragma unroll
        for (int nt = 0; nt < 4; nt++) {
            int c0 = cw * 32 + nt * 8 + tg * 2;
            #pragma unroll
            for (int hh = 0; hh < 2; hh++) {
                int rr = r0 + hh * 8;
                float v0 = acc3[mt][nt][hh * 2];
                float v1 = acc3[mt][nt][hh * 2 + 1];
                if (c0 < 64) {
                    v0 += sEB[c0];
                    v1 += sEB[c0 + 1];
                    *reinterpret_cast<float2*>(d_p1 + (size_t)(node0 + rr) * HH + c0)
                        = make_float2(v0, v1);
                } else {
                    *reinterpret_cast<float2*>(d_p2 + (size_t)(node0 + rr) * HH + (c0 - 64))
                        = make_float2(v0, v1);
                }
            }
        }
    }
}

// ---- output head; 4 nodes per 256-thread block ----
__global__ void __launch_bounds__(256) out_kernel(
    const float* __restrict__ oW1, const float* __restrict__ ob1,
    const float* __restrict__ oW2, const float* __restrict__ ob2,
    float* __restrict__ out) {
    int sub = threadIdx.x >> 6;
    int k = threadIdx.x & 63;
    int node = blockIdx.x * 4 + sub;
    __shared__ float x[4][HH];
    __shared__ float r[4][HH];
    x[sub][k] = d_h[node * HH + k];
    __syncthreads();
    float acc = ob1[k];
    #pragma unroll 8
    for (int i = 0; i < HH; i++) acc += x[sub][i] * oW1[i * HH + k];
    r[sub][k] = fmaxf(acc, 0.0f);
    __syncthreads();
    if (k < 3) {
        float o = ob2[k];
        #pragma unroll 8
        for (int i = 0; i < HH; i++) o += r[sub][i] * oW2[i * 3 + k];
        out[node * 3 + k] = o;
    }
}

extern "C" void kernel_launch(void* const* d_in, const int* in_sizes, int n_in,
                              void* d_out, int out_size) {
    const float* z   = (const float*)d_in[0];
    const int*   ei  = (const int*)d_in[1];
    const float* nf  = (const float*)d_in[2];
    const float* Wg  = (const float*)d_in[3];
    const float* bg  = (const float*)d_in[4];
    const float* Wn  = (const float*)d_in[5];
    const float* bn  = (const float*)d_in[6];
    const float* eW1 = (const float*)d_in[7];
    const float* eb1 = (const float*)d_in[8];
    const float* eW2 = (const float*)d_in[9];
    const float* eb2 = (const float*)d_in[10];
    const float* nW1 = (const float*)d_in[14];
    const float* nb1 = (const float*)d_in[15];
    const float* nW2 = (const float*)d_in[16];
    const float* nb2 = (const float*)d_in[17];
    const float* lng = (const float*)d_in[18];
    const float* lnb = (const float*)d_in[19];
    const float* oW1 = (const float*)d_in[20];
    const float* ob1 = (const float*)d_in[21];
    const float* oW2 = (const float*)d_in[22];
    const float* ob2 = (const float*)d_in[23];

    void* pAgg;
    cudaGetSymbolAddress(&pAgg, d_agg);
    cudaMemsetAsync(pAgg, 0, sizeof(float) * BB * NN * HH);

    cudaFuncSetAttribute((const void*)edge_kernel,
                         cudaFuncAttributeMaxDynamicSharedMemorySize, SME_TOTAL);
    cudaFuncSetAttribute((const void*)node_kernel,
                         cudaFuncAttributeMaxDynamicSharedMemorySize, SMN_TOTAL);

    g_kernel<<<1, 1024>>>(z, Wg, bg);
    h_kernel<<<BB * NN / 4, 256>>>(nf, Wn, bn, eW1, eb1);
    csr_kernel<<<1, 1024>>>(ei, ei + EE);

    for (int l = 0; l < LL; l++) {
        edge_kernel<<<EDGE_GRID, 256, SME_TOTAL>>>(
            eW2 + (size_t)l * HH * HH, eb2 + l * HH);
        const float* eW1n = (l + 1 < LL) ? eW1 + (size_t)(l + 1) * 129 * HH : nullptr;
        const float* eb1n = (l + 1 < LL) ? eb1 + (l + 1) * HH : nullptr;
        node_kernel<<<BB * NN / 64, 256, SMN_TOTAL>>>(
            nW1 + (size_t)l * 2 * HH * HH, nb1 + l * HH,
            nW2 + (size_t)l * HH * HH, nb2 + l * HH,
            lng + l * HH, lnb + l * HH,
            eW1n, eb1n);
    }

    out_kernel<<<BB * NN / 4, 256>>>(oW1, ob1, oW2, ob2, (float*)d_out);
}

// round 14
// speedup vs baseline: 1.3859x; 1.0309x over previous
#include <cuda_runtime.h>
#include <cstdint>

#define BB 16
#define LATENT 128
#define NN 1024
#define EE 32768
#define HH 64
#define LL 4
#define TPB 256                    // tiles per batch: EE/128
#define NTILES (BB * TPB)          // 4096
#define EDGE_GRID 444              // 148 SMs * 3 CTAs

// ---- scratch (device globals; no allocations allowed) ----
__device__ float d_g[BB * HH];
__device__ float d_h[BB * NN * HH];
__device__ float d_p1[BB * NN * HH];
__device__ float d_p2[BB * NN * HH];
__device__ float d_agg[BB * NN * HH];
__device__ int   d_rowptr[NN + 1];
__device__ int   d_rs[EE];
__device__ int   d_cs[EE];

__device__ __forceinline__ float silu(float x) {
    return __fdividef(x, 1.0f + __expf(-x));
}

// rounding cvt: used for WEIGHTS only (once per CTA)
__device__ __forceinline__ uint32_t f2tf32(float x) {
    uint32_t r;
    asm("cvt.rna.tf32.f32 %0, %1;" : "=r"(r) : "f"(x));
    return r;
}

__device__ __forceinline__ void mma_tf32(float* c, const uint32_t* a, const uint32_t* b) {
    asm volatile(
        "mma.sync.aligned.m16n8k8.row.col.f32.tf32.tf32.f32 "
        "{%0,%1,%2,%3}, {%4,%5,%6,%7}, {%8,%9}, {%0,%1,%2,%3};"
        : "+f"(c[0]), "+f"(c[1]), "+f"(c[2]), "+f"(c[3])
        : "r"(a[0]), "r"(a[1]), "r"(a[2]), "r"(a[3]), "r"(b[0]), "r"(b[1]));
}

// ---- edge kernel SMEM layout ----
#define PAD_A 68
#define SME_A     0                 // 128*68*4 = 34816
#define SME_W2P   34816             // packed B pairs: 17408
#define SME_B2    52224             // 256
#define SME_R     52480             // 512
#define SME_P1    52992             // p1 cache: 16*64*4 = 4096
#define SME_TOTAL 57088

// ---- node kernel SMEM layout ----
#define PAD_B  72
#define PAD_NA 132
#define PAD_NP 136
#define SMN_A    0
#define SMN_B    33792
#define SMN_BIAS (SMN_B + 36864)
#define SMN_LN   (SMN_BIAS + 1280)
#define SMN_TOTAL (SMN_LN + 2048)

// ---- g = z @ Wg + bg ----
__global__ void g_kernel(const float* __restrict__ z,
                         const float* __restrict__ Wg,
                         const float* __restrict__ bg) {
    int t = blockIdx.x * blockDim.x + threadIdx.x;
    int b = t >> 6, k = t & 63;
    float acc = bg[k];
    const float* zr = z + b * LATENT;
    #pragma unroll 8
    for (int i = 0; i < LATENT; i++) acc += zr[i] * Wg[i * HH + k];
    d_g[t] = acc;
}

// ---- h + proj for layer 0; 4 nodes per block ----
__global__ void __launch_bounds__(256) h_kernel(
    const float* __restrict__ nf, const float* __restrict__ Wn,
    const float* __restrict__ bn, const float* __restrict__ eW1,
    const float* __restrict__ eb1) {
    int sub = threadIdx.x >> 6;
    int k = threadIdx.x & 63;
    int node = blockIdx.x * 4 + sub;
    int b = node >> 10, n = node & (NN - 1);
    __shared__ float x[4][HH];
    float v = bn[k] + d_g[b * HH + k];
    v += nf[n * 3 + 0] * Wn[0 * HH + k]
       + nf[n * 3 + 1] * Wn[1 * HH + k]
       + nf[n * 3 + 2] * Wn[2 * HH + k];
    d_h[node * HH + k] = v;
    x[sub][k] = v;
    __syncthreads();
    float a1 = eb1[k], a2 = 0.0f;
    #pragma unroll 8
    for (int i = 0; i < HH; i++) {
        float xv = x[sub][i];
        a1 += xv * eW1[i * HH + k];
        a2 += xv * eW1[(HH + i) * HH + k];
    }
    d_p1[node * HH + k] = a1;
    d_p2[node * HH + k] = a2;
}

// ---- CSR build ----
__global__ void csr_kernel(const int* __restrict__ row,
                           const int* __restrict__ col) {
    __shared__ int sc[NN];
    __shared__ int wo[NN];
    int t = threadIdx.x;
    sc[t] = 0;
    __syncthreads();
    for (int e = t; e < EE; e += 1024) atomicAdd(&sc[row[e]], 1);
    __syncthreads();
    int v = sc[t];
    #pragma unroll
    for (int o = 1; o < NN; o <<= 1) {
        int u = (t >= o) ? sc[t - o] : 0;
        __syncthreads();
        sc[t] += u;
        __syncthreads();
    }
    d_rowptr[t + 1] = sc[t];
    if (t == 0) d_rowptr[0] = 0;
    wo[t] = sc[t] - v;
    __syncthreads();
    for (int e = t; e < EE; e += 1024) {
        int r = row[e];
        int p = atomicAdd(&wo[r], 1);
        d_rs[p] = r;
        d_cs[p] = col[e];
    }
}

// ---- fused edge kernel: raw-f32-as-tf32, p1 cache, packed-B ----
__global__ void __launch_bounds__(256, 3) edge_kernel(
    const float* __restrict__ eW2, const float* __restrict__ eb2) {
    extern __shared__ __align__(16) char smem[];
    float*    sAf  = (float*)(smem + SME_A);
    uint32_t* sAu  = (uint32_t*)(smem + SME_A);
    uint32_t* sW2p = (uint32_t*)(smem + SME_W2P);
    const uint2* sW2p2 = (const uint2*)(smem + SME_W2P);
    float*    sB2  = (float*)(smem + SME_B2);
    int*      sR   = (int*)(smem + SME_R);
    float*    sP1  = (float*)(smem + SME_P1);

    int tid = threadIdx.x;
    int wid = tid >> 5;
    int lane = tid & 31;
    int g = lane >> 2;
    int tg = lane & 3;
    int rb = wid & 3;
    int ch = wid >> 2;

    for (int idx = tid; idx < HH * HH; idx += 256) {
        int i = idx >> 6;
        int n = idx & 63;
        int ks = i >> 3;
        int r8 = i & 7;
        int tgw = (r8 < 4) ? r8 : r8 - 4;
        int slot = (r8 < 4) ? 0 : 1;
        sW2p[(((ks * 4 + tgw) * 68) + n) * 2 + slot] = f2tf32(eW2[idx]);
    }
    if (tid < HH) sB2[tid] = eb2[tid];
    __syncthreads();

    int rrow = tid & 127;
    int half = tid >> 7;

    for (int tile = blockIdx.x; tile < NTILES; tile += EDGE_GRID) {
        int b = tile >> 8;
        int jbase = (tile & (TPB - 1)) * 128;

        int j = jbase + rrow;
        int r = d_rs[j], c = d_cs[j];
        if (half == 0) sR[rrow] = r;

        int r0v = d_rs[jbase];                     // broadcast loads
        int nseg = d_rs[jbase + 127] - r0v + 1;    // rows sorted -> range
        if (nseg <= 16) {
            for (int u = tid; u < nseg * 16; u += 256) {
                int s = u >> 4, q = (u & 15) * 4;
                float4 val = *reinterpret_cast<const float4*>(
                    d_p1 + (size_t)(b * NN + r0v + s) * HH + q);
                *reinterpret_cast<float4*>(sP1 + s * 64 + q) = val;
            }
        }
        __syncthreads();                           // sP1 + sR ready

        // a-stage: raw f32 bits (tf32 HW ignores low mantissa)
        {
            const float4* q2 = reinterpret_cast<const float4*>(
                d_p2 + (size_t)(b * NN + c) * HH + half * 32);
            const float4* P1 = (nseg <= 16)
                ? reinterpret_cast<const float4*>(sP1 + (r - r0v) * 64 + half * 32)
                : reinterpret_cast<const float4*>(
                      d_p1 + (size_t)(b * NN + r) * HH + half * 32);
            float4* dst = reinterpret_cast<float4*>(sAf + rrow * PAD_A + half * 32);
            #pragma unroll
            for (int i4 = 0; i4 < 8; i4++) {
                float4 u = P1[i4];
                float4 v = q2[i4];
                float4 w;
                w.x = silu(u.x + v.x);
                w.y = silu(u.y + v.y);
                w.z = silu(u.z + v.z);
                w.w = silu(u.w + v.w);
                dst[i4] = w;
            }
        }
        __syncthreads();

        float acc[2][4][4];
        #pragma unroll
        for (int mt = 0; mt < 2; mt++)
            #pragma unroll
            for (int jj = 0; jj < 4; jj++)
                #pragma unroll
                for (int q = 0; q < 4; q++) acc[mt][jj][q] = 0.0f;

        #pragma unroll
        for (int ks = 0; ks < 8; ks++) {
            uint32_t af[2][4];
            #pragma unroll
            for (int mt = 0; mt < 2; mt++) {
                int rr = rb * 32 + mt * 16 + g;
                int cc = ks * 8 + tg;
                af[mt][0] = sAu[rr * PAD_A + cc];
                af[mt][1] = sAu[(rr + 8) * PAD_A + cc];
                af[mt][2] = sAu[rr * PAD_A + cc + 4];
                af[mt][3] = sAu[(rr + 8) * PAD_A + cc + 4];
            }
            uint32_t bf[4][2];
            #pragma unroll
            for (int jj = 0; jj < 4; jj++) {
                int n = ch * 32 + jj * 8 + g;
                uint2 bv = sW2p2[(ks * 4 + tg) * 68 + n];
                bf[jj][0] = bv.x;
                bf[jj][1] = bv.y;
            }
            #pragma unroll
            for (int mt = 0; mt < 2; mt++)
                #pragma unroll
                for (int jj = 0; jj < 4; jj++) mma_tf32(acc[mt][jj], af[mt], bf[jj]);
        }
        __syncthreads();

        #pragma unroll
        for (int mt = 0; mt < 2; mt++) {
            int r0 = rb * 32 + mt * 16 + g;
            #pragma unroll
            for (int jj = 0; jj < 4; jj++) {
                int c0 = ch * 32 + jj * 8 + tg * 2;
                sAf[r0 * PAD_A + c0]           = silu(acc[mt][jj][0] + sB2[c0]);
                sAf[r0 * PAD_A + c0 + 1]       = silu(acc[mt][jj][1] + sB2[c0 + 1]);
                sAf[(r0 + 8) * PAD_A + c0]     = silu(acc[mt][jj][2] + sB2[c0]);
                sAf[(r0 + 8) * PAD_A + c0 + 1] = silu(acc[mt][jj][3] + sB2[c0 + 1]);
            }
        }
        __syncthreads();

        {
            int k2 = tid & 63;
            int seg = tid >> 6;
            int r0 = seg * 32;
            int rcur = sR[r0];
            float a = 0.0f;
            #pragma unroll 8
            for (int rr = r0; rr < r0 + 32; rr++) {
                int rn = sR[rr];
                if (rn != rcur) {
                    atomicAdd(&d_agg[((size_t)b * NN + rcur) * HH + k2], a);
                    a = 0.0f;
                    rcur = rn;
                }
                a += sAf[rr * PAD_A + k2];
            }
            atomicAdd(&d_agg[((size_t)b * NN + rcur) * HH + k2], a);
        }
        __syncthreads();
    }
}

// ---- tensorized node kernel + fused output head on last layer ----
__global__ void __launch_bounds__(256, 3) node_kernel(
    const float* __restrict__ nW1, const float* __restrict__ nb1,
    const float* __restrict__ nW2, const float* __restrict__ nb2,
    const float* __restrict__ lng, const float* __restrict__ lnb,
    const float* __restrict__ eW1n, const float* __restrict__ eb1n,
    const float* __restrict__ oW1, const float* __restrict__ ob1,
    const float* __restrict__ oW2, const float* __restrict__ ob2,
    float* __restrict__ outp) {
    extern __shared__ __align__(16) char smem[];
    float*    sAf = (float*)(smem + SMN_A);
    uint32_t* sAu = (uint32_t*)(smem + SMN_A);
    uint32_t* sB  = (uint32_t*)(smem + SMN_B);
    float*    sNB1 = (float*)(smem + SMN_BIAS);
    float*    sNB2 = sNB1 + 64;
    float*    sLG  = sNB1 + 128;
    float*    sLB  = sNB1 + 192;
    float*    sEB  = sNB1 + 256;
    float*    sLNs = (float*)(smem + SMN_LN);
    float*    sLNq = sLNs + 256;

    int tid = threadIdx.x;
    int wid = tid >> 5;
    int lane = tid & 31;
    int g = lane >> 2;
    int tg = lane & 3;
    int rw = wid & 1;
    int cw = wid >> 1;
    int node0 = blockIdx.x * 64;

    // stage A = [h | agg] (raw f32 bits) and B = nW1 (rounded tf32)
    {
        int row = tid & 63;
        int qtr = tid >> 6;
        const float* src = (qtr < 2)
            ? d_h  + (size_t)(node0 + row) * HH + qtr * 32
            : d_agg + (size_t)(node0 + row) * HH + (qtr - 2) * 32;
        float* dst = sAf + row * PAD_NA + qtr * 32;
        #pragma unroll
        for (int i4 = 0; i4 < 8; i4++)
            reinterpret_cast<float4*>(dst)[i4] = reinterpret_cast<const float4*>(src)[i4];
        if (qtr >= 2) {
            float4* az = reinterpret_cast<float4*>(
                d_agg + (size_t)(node0 + row) * HH + (qtr - 2) * 32);
            #pragma unroll
            for (int i4 = 0; i4 < 8; i4++) az[i4] = make_float4(0, 0, 0, 0);
        }
    }
    for (int idx = tid; idx < 128 * 64; idx += 256) {
        sB[(idx >> 6) * PAD_B + (idx & 63)] = f2tf32(nW1[idx]);
    }
    if (tid < 64) {
        sNB1[tid] = nb1[tid];
        sNB2[tid] = nb2[tid];
        sLG[tid] = lng[tid];
        sLB[tid] = lnb[tid];
        sEB[tid] = eW1n ? eb1n[tid] : ob1[tid];
    }
    __syncthreads();

    // GEMM1: [64 x 128] @ nW1
    float acc[2][2][4];
    #pragma unroll
    for (int mt = 0; mt < 2; mt++)
        #pragma unroll
        for (int nt = 0; nt < 2; nt++)
            #pragma unroll
            for (int q = 0; q < 4; q++) acc[mt][nt][q] = 0.0f;
    #pragma unroll
    for (int ks = 0; ks < 16; ks++) {
        uint32_t af[2][4];
        #pragma unroll
        for (int mt = 0; mt < 2; mt++) {
            int rr = rw * 32 + mt * 16 + g;
            int cc = ks * 8 + tg;
            af[mt][0] = sAu[rr * PAD_NA + cc];
            af[mt][1] = sAu[(rr + 8) * PAD_NA + cc];
            af[mt][2] = sAu[rr * PAD_NA + cc + 4];
            af[mt][3] = sAu[(rr + 8) * PAD_NA + cc + 4];
        }
        uint32_t bf[2][2];
        #pragma unroll
        for (int nt = 0; nt < 2; nt++) {
            int n = cw * 16 + nt * 8 + g;
            bf[nt][0] = sB[(ks * 8 + tg) * PAD_B + n];
            bf[nt][1] = sB[(ks * 8 + tg + 4) * PAD_B + n];
        }
        #pragma unroll
        for (int mt = 0; mt < 2; mt++)
            #pragma unroll
            for (int nt = 0; nt < 2; nt++) mma_tf32(acc[mt][nt], af[mt], bf[nt]);
    }
    __syncthreads();

    // epilogue1: u1 = silu(raw + nb1) raw bits; restage nW2
    #pragma unroll
    for (int mt = 0; mt < 2; mt++) {
        int r0 = rw * 32 + mt * 16 + g;
        #pragma unroll
        for (int nt = 0; nt < 2; nt++) {
            int c0 = cw * 16 + nt * 8 + tg * 2;
            sAf[r0 * PAD_NA + c0]           = silu(acc[mt][nt][0] + sNB1[c0]);
            sAf[r0 * PAD_NA + c0 + 1]       = silu(acc[mt][nt][1] + sNB1[c0 + 1]);
            sAf[(r0 + 8) * PAD_NA + c0]     = silu(acc[mt][nt][2] + sNB1[c0]);
            sAf[(r0 + 8) * PAD_NA + c0 + 1] = silu(acc[mt][nt][3] + sNB1[c0 + 1]);
        }
    }
    for (int idx = tid; idx < 64 * 64; idx += 256) {
        sB[(idx >> 6) * PAD_B + (idx & 63)] = f2tf32(nW2[idx]);
    }
    __syncthreads();

    // GEMM2: u1 @ nW2
    #pragma unroll
    for (int mt = 0; mt < 2; mt++)
        #pragma unroll
        for (int nt = 0; nt < 2; nt++)
            #pragma unroll
            for (int q = 0; q < 4; q++) acc[mt][nt][q] = 0.0f;
    #pragma unroll
    for (int ks = 0; ks < 8; ks++) {
        uint32_t af[2][4];
        #pragma unroll
        for (int mt = 0; mt < 2; mt++) {
            int rr = rw * 32 + mt * 16 + g;
            int cc = ks * 8 + tg;
            af[mt][0] = sAu[rr * PAD_NA + cc];
            af[mt][1] = sAu[(rr + 8) * PAD_NA + cc];
            af[mt][2] = sAu[rr * PAD_NA + cc + 4];
            af[mt][3] = sAu[(rr + 8) * PAD_NA + cc + 4];
        }
        uint32_t bf[2][2];
        #pragma unroll
        for (int nt = 0; nt < 2; nt++) {
            int n = cw * 16 + nt * 8 + g;
            bf[nt][0] = sB[(ks * 8 + tg) * PAD_B + n];
            bf[nt][1] = sB[(ks * 8 + tg + 4) * PAD_B + n];
        }
        #pragma unroll
        for (int mt = 0; mt < 2; mt++)
            #pragma unroll
            for (int nt = 0; nt < 2; nt++) mma_tf32(acc[mt][nt], af[mt], bf[nt]);
    }
    __syncthreads();

    // epilogue2: hn = h + raw + nb2; restage proj (eW1) or out (oW1) weights
    #pragma unroll
    for (int mt = 0; mt < 2; mt++) {
        int r0 = rw * 32 + mt * 16 + g;
        #pragma unroll
        for (int nt = 0; nt < 2; nt++) {
            int c0 = cw * 16 + nt * 8 + tg * 2;
            float2 h0 = *reinterpret_cast<const float2*>(d_h + (size_t)(node0 + r0) * HH + c0);
            float2 h1 = *reinterpret_cast<const float2*>(d_h + (size_t)(node0 + r0 + 8) * HH + c0);
            sAf[r0 * PAD_NA + c0]           = h0.x + acc[mt][nt][0] + sNB2[c0];
            sAf[r0 * PAD_NA + c0 + 1]       = h0.y + acc[mt][nt][1] + sNB2[c0 + 1];
            sAf[(r0 + 8) * PAD_NA + c0]     = h1.x + acc[mt][nt][2] + sNB2[c0];
            sAf[(r0 + 8) * PAD_NA + c0 + 1] = h1.y + acc[mt][nt][3] + sNB2[c0 + 1];
        }
    }
    if (eW1n) {
        for (int idx = tid; idx < 64 * 128; idx += 256) {
            int i = idx >> 7, n = idx & 127;
            float v = (n < 64) ? eW1n[i * HH + n] : eW1n[(64 + i) * HH + (n - 64)];
            sB[i * PAD_NP + n] = f2tf32(v);
        }
    } else {
        for (int idx = tid; idx < 64 * 64; idx += 256) {
            sB[(idx >> 6) * PAD_B + (idx & 63)] = f2tf32(oW1[idx]);
        }
    }
    __syncthreads();

    // layernorm
    {
        int row = tid >> 2;
        int part = tid & 3;
        float s = 0.0f, q = 0.0f;
        #pragma unroll
        for (int i = 0; i < 16; i++) {
            float v = sAf[row * PAD_NA + part * 16 + i];
            s += v;
            q += v * v;
        }
        sLNs[row * 4 + part] = s;
        sLNq[row * 4 + part] = q;
    }
    __syncthreads();
    {
        int row = tid >> 2;
        int part = tid & 3;
        float s = sLNs[row * 4] + sLNs[row * 4 + 1] + sLNs[row * 4 + 2] + sLNs[row * 4 + 3];
        float q = sLNq[row * 4] + sLNq[row * 4 + 1] + sLNq[row * 4 + 2] + sLNq[row * 4 + 3];
        float mu = s * (1.0f / HH);
        float var = q * (1.0f / HH) - mu * mu;
        float rstd = rsqrtf(var + 1e-5f);
        float hv[16];
        #pragma unroll
        for (int i = 0; i < 16; i++) {
            int c = part * 16 + i;
            hv[i] = (sAf[row * PAD_NA + c] - mu) * rstd * sLG[c] + sLB[c];
        }
        float4* hout = reinterpret_cast<float4*>(d_h + (size_t)(node0 + row) * HH + part * 16);
        #pragma unroll
        for (int i4 = 0; i4 < 4; i4++)
            hout[i4] = make_float4(hv[i4 * 4], hv[i4 * 4 + 1], hv[i4 * 4 + 2], hv[i4 * 4 + 3]);
        #pragma unroll
        for (int i = 0; i < 16; i++)
            sAf[row * PAD_NA + part * 16 + i] = hv[i];   // raw bits for next GEMM
    }
    __syncthreads();

    if (eW1n) {
        // GEMM3 (proj): hnew @ eW1 -> [p1 | p2]
        float acc3[2][4][4];
        #pragma unroll
        for (int mt = 0; mt < 2; mt++)
            #pragma unroll
            for (int nt = 0; nt < 4; nt++)
                #pragma unroll
                for (int q = 0; q < 4; q++) acc3[mt][nt][q] = 0.0f;
        #pragma unroll
        for (int ks = 0; ks < 8; ks++) {
            uint32_t af[2][4];
            #pragma unroll
            for (int mt = 0; mt < 2; mt++) {
                int rr = rw * 32 + mt * 16 + g;
                int cc = ks * 8 + tg;
                af[mt][0] = sAu[rr * PAD_NA + cc];
                af[mt][1] = sAu[(rr + 8) * PAD_NA + cc];
                af[mt][2] = sAu[rr * PAD_NA + cc + 4];
                af[mt][3] = sAu[(rr + 8) * PAD_NA + cc + 4];
            }
            uint32_t bf[4][2];
            #pragma unroll
            for (int nt = 0; nt < 4; nt++) {
                int n = cw * 32 + nt * 8 + g;
                bf[nt][0] = sB[(ks * 8 + tg) * PAD_NP + n];
                bf[nt][1] = sB[(ks * 8 + tg + 4) * PAD_NP + n];
            }
            #pragma unroll
            for (int mt = 0; mt < 2; mt++)
                #pragma unroll
                for (int nt = 0; nt < 4; nt++) mma_tf32(acc3[mt][nt], af[mt], bf[nt]);
        }
        #pragma unroll
        for (int mt = 0; mt < 2; mt++) {
            int r0 = rw * 32 + mt * 16 + g;
            #pragma unroll
            for (int nt = 0; nt < 4; nt++) {
                int c0 = cw * 32 + nt * 8 + tg * 2;
                #pragma unroll
                for (int hh = 0; hh < 2; hh++) {
                    int rr = r0 + hh * 8;
                    float v0 = acc3[mt][nt][hh * 2];
                    float v1 = acc3[mt][nt][hh * 2 + 1];
                    if (c0 < 64) {
                        v0 += sEB[c0];
                        v1 += sEB[c0 + 1];
                        *reinterpret_cast<float2*>(d_p1 + (size_t)(node0 + rr) * HH + c0)
                            = make_float2(v0, v1);
                    } else {
                        *reinterpret_cast<float2*>(d_p2 + (size_t)(node0 + rr) * HH + (c0 - 64))
                            = make_float2(v0, v1);
                    }
                }
            }
        }
    } else {
        // fused output head: r = relu(hnew @ oW1 + ob1); out = r @ oW2 + ob2
        float acco[2][2][4];
        #pragma unroll
        for (int mt = 0; mt < 2; mt++)
            #pragma unroll
            for (int nt = 0; nt < 2; nt++)
                #pragma unroll
                for (int q = 0; q < 4; q++) acco[mt][nt][q] = 0.0f;
        #pragma unroll
        for (int ks = 0; ks < 8; ks++) {
            uint32_t af[2][4];
            #pragma unroll
            for (int mt = 0; mt < 2; mt++) {
                int rr = rw * 32 + mt * 16 + g;
                int cc = ks * 8 + tg;
                af[mt][0] = sAu[rr * PAD_NA + cc];
                af[mt][1] = sAu[(rr + 8) * PAD_NA + cc];
                af[mt][2] = sAu[rr * PAD_NA + cc + 4];
                af[mt][3] = sAu[(rr + 8) * PAD_NA + cc + 4];
            }
            uint32_t bf[2][2];
            #pragma unroll
            for (int nt = 0; nt < 2; nt++) {
                int n = cw * 16 + nt * 8 + g;
                bf[nt][0] = sB[(ks * 8 + tg) * PAD_B + n];
                bf[nt][1] = sB[(ks * 8 + tg + 4) * PAD_B + n];
            }
            #pragma unroll
            for (int mt = 0; mt < 2; mt++)
                #pragma unroll
                for (int nt = 0; nt < 2; nt++) mma_tf32(acco[mt][nt], af[mt], bf[nt]);
        }
        __syncthreads();    // A reads done before relu overwrite

        #pragma unroll
        for (int mt = 0; mt < 2; mt++) {
            int r0 = rw * 32 + mt * 16 + g;
            #pragma unroll
            for (int nt = 0; nt < 2; nt++) {
                int c0 = cw * 16 + nt * 8 + tg * 2;
                sAf[r0 * PAD_NA + c0]           = fmaxf(acco[mt][nt][0] + sEB[c0], 0.0f);
                sAf[r0 * PAD_NA + c0 + 1]       = fmaxf(acco[mt][nt][1] + sEB[c0 + 1], 0.0f);
                sAf[(r0 + 8) * PAD_NA + c0]     = fmaxf(acco[mt][nt][2] + sEB[c0], 0.0f);
                sAf[(r0 + 8) * PAD_NA + c0 + 1] = fmaxf(acco[mt][nt][3] + sEB[c0 + 1], 0.0f);
            }
        }
        if (tid < 192) sLNs[tid] = oW2[tid];   // reuse LN buffer for oW2 [64x3]
        __syncthreads();

        if (tid < 192) {
            int row = tid / 3;
            int k3 = tid % 3;
            float o = ob2[k3];
            #pragma unroll 8
            for (int i = 0; i < HH; i++)
                o += sAf[row * PAD_NA + i] * sLNs[i * 3 + k3];
            outp[(size_t)(node0 + row) * 3 + k3] = o;
        }
    }
}

extern "C" void kernel_launch(void* const* d_in, const int* in_sizes, int n_in,
                              void* d_out, int out_size) {
    const float* z   = (const float*)d_in[0];
    const int*   ei  = (const int*)d_in[1];
    const float* nf  = (const float*)d_in[2];
    const float* Wg  = (const float*)d_in[3];
    const float* bg  = (const float*)d_in[4];
    const float* Wn  = (const float*)d_in[5];
    const float* bn  = (const float*)d_in[6];
    const float* eW1 = (const float*)d_in[7];
    const float* eb1 = (const float*)d_in[8];
    const float* eW2 = (const float*)d_in[9];
    const float* eb2 = (const float*)d_in[10];
    const float* nW1 = (const float*)d_in[14];
    const float* nb1 = (const float*)d_in[15];
    const float* nW2 = (const float*)d_in[16];
    const float* nb2 = (const float*)d_in[17];
    const float* lng = (const float*)d_in[18];
    const float* lnb = (const float*)d_in[19];
    const float* oW1 = (const float*)d_in[20];
    const float* ob1 = (const float*)d_in[21];
    const float* oW2 = (const float*)d_in[22];
    const float* ob2 = (const float*)d_in[23];

    void* pAgg;
    cudaGetSymbolAddress(&pAgg, d_agg);
    cudaMemsetAsync(pAgg, 0, sizeof(float) * BB * NN * HH);

    cudaFuncSetAttribute((const void*)edge_kernel,
                         cudaFuncAttributeMaxDynamicSharedMemorySize, SME_TOTAL);
    cudaFuncSetAttribute((const void*)node_kernel,
                         cudaFuncAttributeMaxDynamicSharedMemorySize, SMN_TOTAL);

    g_kernel<<<1, 1024>>>(z, Wg, bg);
    h_kernel<<<BB * NN / 4, 256>>>(nf, Wn, bn, eW1, eb1);
    csr_kernel<<<1, 1024>>>(ei, ei + EE);

    for (int l = 0; l < LL; l++) {
        edge_kernel<<<EDGE_GRID, 256, SME_TOTAL>>>(
            eW2 + (size_t)l * HH * HH, eb2 + l * HH);
        const float* eW1n = (l + 1 < LL) ? eW1 + (size_t)(l + 1) * 129 * HH : nullptr;
        const float* eb1n = (l + 1 < LL) ? eb1 + (l + 1) * HH : nullptr;
        node_kernel<<<BB * NN / 64, 256, SMN_TOTAL>>>(
            nW1 + (size_t)l * 2 * HH * HH, nb1 + l * HH,
            nW2 + (size_t)l * HH * HH, nb2 + l * HH,
            lng + l * HH, lnb + l * HH,
            eW1n, eb1n,
            oW1, ob1, oW2, ob2, (float*)d_out);
    }
}

// round 15
// speedup vs baseline: 1.5431x; 1.1135x over previous
#include <cuda_runtime.h>
#include <cstdint>

#define BB 16
#define LATENT 128
#define NN 1024
#define EE 32768
#define HH 64
#define LL 4
#define TPB 256                    // tiles per batch: EE/128
#define NTILES (BB * TPB)          // 4096
#define EDGE_GRID 444              // 148 SMs * 3 CTAs

// ---- scratch (device globals; no allocations allowed) ----
__device__ float d_g[BB * HH];
__device__ float d_h[BB * NN * HH];
__device__ float d_p1[BB * NN * HH];
__device__ float d_p2[BB * NN * HH];
__device__ float d_agg[BB * NN * HH];
__device__ int   d_rowptr[NN + 1];
__device__ int   d_rs[EE];
__device__ int   d_cs[EE];

__device__ __forceinline__ float silu(float x) {
    return __fdividef(x, 1.0f + __expf(-x));
}

__device__ __forceinline__ uint32_t f2tf32(float x) {
    uint32_t r;
    asm("cvt.rna.tf32.f32 %0, %1;" : "=r"(r) : "f"(x));
    return r;
}

__device__ __forceinline__ void mma_tf32(float* c, const uint32_t* a, const uint32_t* b) {
    asm volatile(
        "mma.sync.aligned.m16n8k8.row.col.f32.tf32.tf32.f32 "
        "{%0,%1,%2,%3}, {%4,%5,%6,%7}, {%8,%9}, {%0,%1,%2,%3};"
        : "+f"(c[0]), "+f"(c[1]), "+f"(c[2]), "+f"(c[3])
        : "r"(a[0]), "r"(a[1]), "r"(a[2]), "r"(a[3]), "r"(b[0]), "r"(b[1]));
}

// ---- edge kernel SMEM layout ----
#define PAD_A 68
#define SME_A     0                 // 128*68*4 = 34816
#define SME_W2P   34816             // packed B pairs: 17408
#define SME_B2    52224             // 256
#define SME_R     52480             // 512
#define SME_P1    52992             // p1 cache: 16*64*4 = 4096
#define SME_TOTAL 57088

// ---- node kernel SMEM layout ----
#define PAD_B  72
#define PAD_NA 132
#define PAD_NP 136
#define SMN_A    0
#define SMN_B    33792
#define SMN_BIAS (SMN_B + 36864)
#define SMN_LN   (SMN_BIAS + 1280)
#define SMN_TOTAL (SMN_LN + 2048)

// ---- g = z @ Wg + bg ----
__global__ void g_kernel(const float* __restrict__ z,
                         const float* __restrict__ Wg,
                         const float* __restrict__ bg) {
    int t = blockIdx.x * blockDim.x + threadIdx.x;
    int b = t >> 6, k = t & 63;
    float acc = bg[k];
    const float* zr = z + b * LATENT;
    #pragma unroll 8
    for (int i = 0; i < LATENT; i++) acc += zr[i] * Wg[i * HH + k];
    d_g[t] = acc;
}

// ---- h + proj for layer 0; 4 nodes per block ----
__global__ void __launch_bounds__(256) h_kernel(
    const float* __restrict__ nf, const float* __restrict__ Wn,
    const float* __restrict__ bn, const float* __restrict__ eW1,
    const float* __restrict__ eb1) {
    int sub = threadIdx.x >> 6;
    int k = threadIdx.x & 63;
    int node = blockIdx.x * 4 + sub;
    int b = node >> 10, n = node & (NN - 1);
    __shared__ float x[4][HH];
    float v = bn[k] + d_g[b * HH + k];
    v += nf[n * 3 + 0] * Wn[0 * HH + k]
       + nf[n * 3 + 1] * Wn[1 * HH + k]
       + nf[n * 3 + 2] * Wn[2 * HH + k];
    d_h[node * HH + k] = v;
    x[sub][k] = v;
    __syncthreads();
    float a1 = eb1[k], a2 = 0.0f;
    #pragma unroll 8
    for (int i = 0; i < HH; i++) {
        float xv = x[sub][i];
        a1 += xv * eW1[i * HH + k];
        a2 += xv * eW1[(HH + i) * HH + k];
    }
    d_p1[node * HH + k] = a1;
    d_p2[node * HH + k] = a2;
}

// ---- CSR build ----
__global__ void csr_kernel(const int* __restrict__ row,
                           const int* __restrict__ col) {
    __shared__ int sc[NN];
    __shared__ int wo[NN];
    int t = threadIdx.x;
    sc[t] = 0;
    __syncthreads();
    for (int e = t; e < EE; e += 1024) atomicAdd(&sc[row[e]], 1);
    __syncthreads();
    int v = sc[t];
    #pragma unroll
    for (int o = 1; o < NN; o <<= 1) {
        int u = (t >= o) ? sc[t - o] : 0;
        __syncthreads();
        sc[t] += u;
        __syncthreads();
    }
    d_rowptr[t + 1] = sc[t];
    if (t == 0) d_rowptr[0] = 0;
    wo[t] = sc[t] - v;
    __syncthreads();
    for (int e = t; e < EE; e += 1024) {
        int r = row[e];
        int p = atomicAdd(&wo[r], 1);
        d_rs[p] = r;
        d_cs[p] = col[e];
    }
}

// ---- fused edge kernel: row-coalesced gather, p1 cache, packed-B ----
__global__ void __launch_bounds__(256, 3) edge_kernel(
    const float* __restrict__ eW2, const float* __restrict__ eb2) {
    extern __shared__ __align__(16) char smem[];
    float*    sAf  = (float*)(smem + SME_A);
    uint32_t* sAu  = (uint32_t*)(smem + SME_A);
    uint32_t* sW2p = (uint32_t*)(smem + SME_W2P);
    const uint2* sW2p2 = (const uint2*)(smem + SME_W2P);
    float*    sB2  = (float*)(smem + SME_B2);
    int*      sR   = (int*)(smem + SME_R);
    float*    sP1  = (float*)(smem + SME_P1);

    int tid = threadIdx.x;
    int wid = tid >> 5;
    int lane = tid & 31;
    int g = lane >> 2;
    int tg = lane & 3;
    int rb = wid & 3;
    int ch = wid >> 2;

    for (int idx = tid; idx < HH * HH; idx += 256) {
        int i = idx >> 6;
        int n = idx & 63;
        int ks = i >> 3;
        int r8 = i & 7;
        int tgw = (r8 < 4) ? r8 : r8 - 4;
        int slot = (r8 < 4) ? 0 : 1;
        sW2p[(((ks * 4 + tgw) * 68) + n) * 2 + slot] = f2tf32(eW2[idx]);
    }
    if (tid < HH) sB2[tid] = eb2[tid];
    __syncthreads();

    // gather mapping: warp covers 16 rows; lanes 0-15 one row, 16-31 the next
    int gsub = lane >> 4;            // row within pair
    int goff = (lane & 15) * 4;      // float offset within row

    for (int tile = blockIdx.x; tile < NTILES; tile += EDGE_GRID) {
        int b = tile >> 8;
        int jbase = (tile & (TPB - 1)) * 128;

        if (tid < 128) sR[tid] = d_rs[jbase + tid];
        int r0v = d_rs[jbase];
        int nseg = d_rs[jbase + 127] - r0v + 1;   // rows sorted -> range
        if (nseg <= 16) {
            for (int u = tid; u < nseg * 16; u += 256) {
                int s = u >> 4, q = (u & 15) * 4;
                float4 val = *reinterpret_cast<const float4*>(
                    d_p1 + (size_t)(b * NN + r0v + s) * HH + q);
                *reinterpret_cast<float4*>(sP1 + s * 64 + q) = val;
            }
        }
        __syncthreads();                           // sR + sP1 ready

        // a-stage: row-coalesced p2 gather + p1-cache combine + silu + cvt
        {
            int rbase = wid * 16;
            #pragma unroll
            for (int it = 0; it < 8; it++) {
                int row = rbase + it * 2 + gsub;
                int c = d_cs[jbase + row];         // broadcast across 16 lanes
                int r = sR[row];
                float4 v = *reinterpret_cast<const float4*>(
                    d_p2 + (size_t)(b * NN + c) * HH + goff);
                float4 u = (nseg <= 16)
                    ? *reinterpret_cast<const float4*>(sP1 + (r - r0v) * 64 + goff)
                    : *reinterpret_cast<const float4*>(
                          d_p1 + (size_t)(b * NN + r) * HH + goff);
                uint4 t;
                t.x = f2tf32(silu(u.x + v.x));
                t.y = f2tf32(silu(u.y + v.y));
                t.z = f2tf32(silu(u.z + v.z));
                t.w = f2tf32(silu(u.w + v.w));
                *reinterpret_cast<uint4*>(sAu + row * PAD_A + goff) = t;
            }
        }
        __syncthreads();

        float acc[2][4][4];
        #pragma unroll
        for (int mt = 0; mt < 2; mt++)
            #pragma unroll
            for (int jj = 0; jj < 4; jj++)
                #pragma unroll
                for (int q = 0; q < 4; q++) acc[mt][jj][q] = 0.0f;

        #pragma unroll
        for (int ks = 0; ks < 8; ks++) {
            uint32_t af[2][4];
            #pragma unroll
            for (int mt = 0; mt < 2; mt++) {
                int rr = rb * 32 + mt * 16 + g;
                int cc = ks * 8 + tg;
                af[mt][0] = sAu[rr * PAD_A + cc];
                af[mt][1] = sAu[(rr + 8) * PAD_A + cc];
                af[mt][2] = sAu[rr * PAD_A + cc + 4];
                af[mt][3] = sAu[(rr + 8) * PAD_A + cc + 4];
            }
            uint32_t bf[4][2];
            #pragma unroll
            for (int jj = 0; jj < 4; jj++) {
                int n = ch * 32 + jj * 8 + g;
                uint2 bv = sW2p2[(ks * 4 + tg) * 68 + n];
                bf[jj][0] = bv.x;
                bf[jj][1] = bv.y;
            }
            #pragma unroll
            for (int mt = 0; mt < 2; mt++)
                #pragma unroll
                for (int jj = 0; jj < 4; jj++) mma_tf32(acc[mt][jj], af[mt], bf[jj]);
        }
        __syncthreads();

        #pragma unroll
        for (int mt = 0; mt < 2; mt++) {
            int r0 = rb * 32 + mt * 16 + g;
            #pragma unroll
            for (int jj = 0; jj < 4; jj++) {
                int c0 = ch * 32 + jj * 8 + tg * 2;
                sAf[r0 * PAD_A + c0]           = silu(acc[mt][jj][0] + sB2[c0]);
                sAf[r0 * PAD_A + c0 + 1]       = silu(acc[mt][jj][1] + sB2[c0 + 1]);
                sAf[(r0 + 8) * PAD_A + c0]     = silu(acc[mt][jj][2] + sB2[c0]);
                sAf[(r0 + 8) * PAD_A + c0 + 1] = silu(acc[mt][jj][3] + sB2[c0 + 1]);
            }
        }
        __syncthreads();

        {
            int k2 = tid & 63;
            int seg = tid >> 6;
            int r0 = seg * 32;
            int rcur = sR[r0];
            float a = 0.0f;
            #pragma unroll 8
            for (int rr = r0; rr < r0 + 32; rr++) {
                int rn = sR[rr];
                if (rn != rcur) {
                    atomicAdd(&d_agg[((size_t)b * NN + rcur) * HH + k2], a);
                    a = 0.0f;
                    rcur = rn;
                }
                a += sAf[rr * PAD_A + k2];
            }
            atomicAdd(&d_agg[((size_t)b * NN + rcur) * HH + k2], a);
        }
        __syncthreads();
    }
}

// ---- tensorized node kernel + fused output head on last layer ----
__global__ void __launch_bounds__(256, 3) node_kernel(
    const float* __restrict__ nW1, const float* __restrict__ nb1,
    const float* __restrict__ nW2, const float* __restrict__ nb2,
    const float* __restrict__ lng, const float* __restrict__ lnb,
    const float* __restrict__ eW1n, const float* __restrict__ eb1n,
    const float* __restrict__ oW1, const float* __restrict__ ob1,
    const float* __restrict__ oW2, const float* __restrict__ ob2,
    float* __restrict__ outp) {
    extern __shared__ __align__(16) char smem[];
    float*    sAf = (float*)(smem + SMN_A);
    uint32_t* sAu = (uint32_t*)(smem + SMN_A);
    uint32_t* sB  = (uint32_t*)(smem + SMN_B);
    float*    sNB1 = (float*)(smem + SMN_BIAS);
    float*    sNB2 = sNB1 + 64;
    float*    sLG  = sNB1 + 128;
    float*    sLB  = sNB1 + 192;
    float*    sEB  = sNB1 + 256;
    float*    sLNs = (float*)(smem + SMN_LN);
    float*    sLNq = sLNs + 256;

    int tid = threadIdx.x;
    int wid = tid >> 5;
    int lane = tid & 31;
    int g = lane >> 2;
    int tg = lane & 3;
    int rw = wid & 1;
    int cw = wid >> 1;
    int node0 = blockIdx.x * 64;

    // stage A = [h | agg] (rounded tf32) and B = nW1
    {
        int row = tid & 63;
        int qtr = tid >> 6;
        const float* src = (qtr < 2)
            ? d_h  + (size_t)(node0 + row) * HH + qtr * 32
            : d_agg + (size_t)(node0 + row) * HH + (qtr - 2) * 32;
        uint32_t* dst = sAu + row * PAD_NA + qtr * 32;
        #pragma unroll
        for (int i4 = 0; i4 < 8; i4++) {
            float4 v = reinterpret_cast<const float4*>(src)[i4];
            uint4 t;
            t.x = f2tf32(v.x); t.y = f2tf32(v.y);
            t.z = f2tf32(v.z); t.w = f2tf32(v.w);
            reinterpret_cast<uint4*>(dst)[i4] = t;
        }
        if (qtr >= 2) {
            float4* az = reinterpret_cast<float4*>(
                d_agg + (size_t)(node0 + row) * HH + (qtr - 2) * 32);
            #pragma unroll
            for (int i4 = 0; i4 < 8; i4++) az[i4] = make_float4(0, 0, 0, 0);
        }
    }
    for (int idx = tid; idx < 128 * 64; idx += 256) {
        sB[(idx >> 6) * PAD_B + (idx & 63)] = f2tf32(nW1[idx]);
    }
    if (tid < 64) {
        sNB1[tid] = nb1[tid];
        sNB2[tid] = nb2[tid];
        sLG[tid] = lng[tid];
        sLB[tid] = lnb[tid];
        sEB[tid] = eW1n ? eb1n[tid] : ob1[tid];
    }
    __syncthreads();

    // GEMM1: [64 x 128] @ nW1
    float acc[2][2][4];
    #pragma unroll
    for (int mt = 0; mt < 2; mt++)
        #pragma unroll
        for (int nt = 0; nt < 2; nt++)
            #pragma unroll
            for (int q = 0; q < 4; q++) acc[mt][nt][q] = 0.0f;
    #pragma unroll
    for (int ks = 0; ks < 16; ks++) {
        uint32_t af[2][4];
        #pragma unroll
        for (int mt = 0; mt < 2; mt++) {
            int rr = rw * 32 + mt * 16 + g;
            int cc = ks * 8 + tg;
            af[mt][0] = sAu[rr * PAD_NA + cc];
            af[mt][1] = sAu[(rr + 8) * PAD_NA + cc];
            af[mt][2] = sAu[rr * PAD_NA + cc + 4];
            af[mt][3] = sAu[(rr + 8) * PAD_NA + cc + 4];
        }
        uint32_t bf[2][2];
        #pragma unroll
        for (int nt = 0; nt < 2; nt++) {
            int n = cw * 16 + nt * 8 + g;
            bf[nt][0] = sB[(ks * 8 + tg) * PAD_B + n];
            bf[nt][1] = sB[(ks * 8 + tg + 4) * PAD_B + n];
        }
        #pragma unroll
        for (int mt = 0; mt < 2; mt++)
            #pragma unroll
            for (int nt = 0; nt < 2; nt++) mma_tf32(acc[mt][nt], af[mt], bf[nt]);
    }
    __syncthreads();

    // epilogue1: u1 = silu(raw + nb1) (rounded); restage nW2
    #pragma unroll
    for (int mt = 0; mt < 2; mt++) {
        int r0 = rw * 32 + mt * 16 + g;
        #pragma unroll
        for (int nt = 0; nt < 2; nt++) {
            int c0 = cw * 16 + nt * 8 + tg * 2;
            sAu[r0 * PAD_NA + c0]           = f2tf32(silu(acc[mt][nt][0] + sNB1[c0]));
            sAu[r0 * PAD_NA + c0 + 1]       = f2tf32(silu(acc[mt][nt][1] + sNB1[c0 + 1]));
            sAu[(r0 + 8) * PAD_NA + c0]     = f2tf32(silu(acc[mt][nt][2] + sNB1[c0]));
            sAu[(r0 + 8) * PAD_NA + c0 + 1] = f2tf32(silu(acc[mt][nt][3] + sNB1[c0 + 1]));
        }
    }
    for (int idx = tid; idx < 64 * 64; idx += 256) {
        sB[(idx >> 6) * PAD_B + (idx & 63)] = f2tf32(nW2[idx]);
    }
    __syncthreads();

    // GEMM2: u1 @ nW2
    #pragma unroll
    for (int mt = 0; mt < 2; mt++)
        #pragma unroll
        for (int nt = 0; nt < 2; nt++)
            #pragma unroll
            for (int q = 0; q < 4; q++) acc[mt][nt][q] = 0.0f;
    #pragma unroll
    for (int ks = 0; ks < 8; ks++) {
        uint32_t af[2][4];
        #pragma unroll
        for (int mt = 0; mt < 2; mt++) {
            int rr = rw * 32 + mt * 16 + g;
            int cc = ks * 8 + tg;
            af[mt][0] = sAu[rr * PAD_NA + cc];
            af[mt][1] = sAu[(rr + 8) * PAD_NA + cc];
            af[mt][2] = sAu[rr * PAD_NA + cc + 4];
            af[mt][3] = sAu[(rr + 8) * PAD_NA + cc + 4];
        }
        uint32_t bf[2][2];
        #pragma unroll
        for (int nt = 0; nt < 2; nt++) {
            int n = cw * 16 + nt * 8 + g;
            bf[nt][0] = sB[(ks * 8 + tg) * PAD_B + n];
            bf[nt][1] = sB[(ks * 8 + tg + 4) * PAD_B + n];
        }
        #pragma unroll
        for (int mt = 0; mt < 2; mt++)
            #pragma unroll
            for (int nt = 0; nt < 2; nt++) mma_tf32(acc[mt][nt], af[mt], bf[nt]);
    }
    __syncthreads();

    // epilogue2: hn = h + raw + nb2 (fp32); restage proj/out weights
    #pragma unroll
    for (int mt = 0; mt < 2; mt++) {
        int r0 = rw * 32 + mt * 16 + g;
        #pragma unroll
        for (int nt = 0; nt < 2; nt++) {
            int c0 = cw * 16 + nt * 8 + tg * 2;
            float2 h0 = *reinterpret_cast<const float2*>(d_h + (size_t)(node0 + r0) * HH + c0);
            float2 h1 = *reinterpret_cast<const float2*>(d_h + (size_t)(node0 + r0 + 8) * HH + c0);
            sAf[r0 * PAD_NA + c0]           = h0.x + acc[mt][nt][0] + sNB2[c0];
            sAf[r0 * PAD_NA + c0 + 1]       = h0.y + acc[mt][nt][1] + sNB2[c0 + 1];
            sAf[(r0 + 8) * PAD_NA + c0]     = h1.x + acc[mt][nt][2] + sNB2[c0];
            sAf[(r0 + 8) * PAD_NA + c0 + 1] = h1.y + acc[mt][nt][3] + sNB2[c0 + 1];
        }
    }
    if (eW1n) {
        for (int idx = tid; idx < 64 * 128; idx += 256) {
            int i = idx >> 7, n = idx & 127;
            float v = (n < 64) ? eW1n[i * HH + n] : eW1n[(64 + i) * HH + (n - 64)];
            sB[i * PAD_NP + n] = f2tf32(v);
        }
    } else {
        for (int idx = tid; idx < 64 * 64; idx += 256) {
            sB[(idx >> 6) * PAD_B + (idx & 63)] = f2tf32(oW1[idx]);
        }
    }
    __syncthreads();

    // layernorm
    {
        int row = tid >> 2;
        int part = tid & 3;
        float s = 0.0f, q = 0.0f;
        #pragma unroll
        for (int i = 0; i < 16; i++) {
            float v = sAf[row * PAD_NA + part * 16 + i];
            s += v;
            q += v * v;
        }
        sLNs[row * 4 + part] = s;
        sLNq[row * 4 + part] = q;
    }
    __syncthreads();
    {
        int row = tid >> 2;
        int part = tid & 3;
        float s = sLNs[row * 4] + sLNs[row * 4 + 1] + sLNs[row * 4 + 2] + sLNs[row * 4 + 3];
        float q = sLNq[row * 4] + sLNq[row * 4 + 1] + sLNq[row * 4 + 2] + sLNq[row * 4 + 3];
        float mu = s * (1.0f / HH);
        float var = q * (1.0f / HH) - mu * mu;
        float rstd = rsqrtf(var + 1e-5f);
        float hv[16];
        #pragma unroll
        for (int i = 0; i < 16; i++) {
            int c = part * 16 + i;
            hv[i] = (sAf[row * PAD_NA + c] - mu) * rstd * sLG[c] + sLB[c];
        }
        float4* hout = reinterpret_cast<float4*>(d_h + (size_t)(node0 + row) * HH + part * 16);
        #pragma unroll
        for (int i4 = 0; i4 < 4; i4++)
            hout[i4] = make_float4(hv[i4 * 4], hv[i4 * 4 + 1], hv[i4 * 4 + 2], hv[i4 * 4 + 3]);
        #pragma unroll
        for (int i = 0; i < 16; i++)
            sAu[row * PAD_NA + part * 16 + i] = f2tf32(hv[i]);
    }
    __syncthreads();

    if (eW1n) {
        // GEMM3 (proj): hnew @ eW1 -> [p1 | p2]
        float acc3[2][4][4];
        #pragma unroll
        for (int mt = 0; mt < 2; mt++)
            #pragma unroll
            for (int nt = 0; nt < 4; nt++)
                #pragma unroll
                for (int q = 0; q < 4; q++) acc3[mt][nt][q] = 0.0f;
        #pragma unroll
        for (int ks = 0; ks < 8; ks++) {
            uint32_t af[2][4];
            #pragma unroll
            for (int mt = 0; mt < 2; mt++) {
                int rr = rw * 32 + mt * 16 + g;
                int cc = ks * 8 + tg;
                af[mt][0] = sAu[rr * PAD_NA + cc];
                af[mt][1] = sAu[(rr + 8) * PAD_NA + cc];
                af[mt][2] = sAu[rr * PAD_NA + cc + 4];
                af[mt][3] = sAu[(rr + 8) * PAD_NA + cc + 4];
            }
            uint32_t bf[4][2];
            #pragma unroll
            for (int nt = 0; nt < 4; nt++) {
                int n = cw * 32 + nt * 8 + g;
                bf[nt][0] = sB[(ks * 8 + tg) * PAD_NP + n];
                bf[nt][1] = sB[(ks * 8 + tg + 4) * PAD_NP + n];
            }
            #pragma unroll
            for (int mt = 0; mt < 2; mt++)
                #pragma unroll
                for (int nt = 0; nt < 4; nt++) mma_tf32(acc3[mt][nt], af[mt], bf[nt]);
        }
        #pragma unroll
        for (int mt = 0; mt < 2; mt++) {
            int r0 = rw * 32 + mt * 16 + g;
            #pragma unroll
            for (int nt = 0; nt < 4; nt++) {
                int c0 = cw * 32 + nt * 8 + tg * 2;
                #pragma unroll
                for (int hh = 0; hh < 2; hh++) {
                    int rr = r0 + hh * 8;
                    float v0 = acc3[mt][nt][hh * 2];
                    float v1 = acc3[mt][nt][hh * 2 + 1];
                    if (c0 < 64) {
                        v0 += sEB[c0];
                        v1 += sEB[c0 + 1];
                        *reinterpret_cast<float2*>(d_p1 + (size_t)(node0 + rr) * HH + c0)
                            = make_float2(v0, v1);
                    } else {
                        *reinterpret_cast<float2*>(d_p2 + (size_t)(node0 + rr) * HH + (c0 - 64))
                            = make_float2(v0, v1);
                    }
                }
            }
        }
    } else {
        // fused output head: r = relu(hnew @ oW1 + ob1); out = r @ oW2 + ob2
        float acco[2][2][4];
        #pragma unroll
        for (int mt = 0; mt < 2; mt++)
            #pragma unroll
            for (int nt = 0; nt < 2; nt++)
                #pragma unroll
                for (int q = 0; q < 4; q++) acco[mt][nt][q] = 0.0f;
        #pragma unroll
        for (int ks = 0; ks < 8; ks++) {
            uint32_t af[2][4];
            #pragma unroll
            for (int mt = 0; mt < 2; mt++) {
                int rr = rw * 32 + mt * 16 + g;
                int cc = ks * 8 + tg;
                af[mt][0] = sAu[rr * PAD_NA + cc];
                af[mt][1] = sAu[(rr + 8) * PAD_NA + cc];
                af[mt][2] = sAu[rr * PAD_NA + cc + 4];
                af[mt][3] = sAu[(rr + 8) * PAD_NA + cc + 4];
            }
            uint32_t bf[2][2];
            #pragma unroll
            for (int nt = 0; nt < 2; nt++) {
                int n = cw * 16 + nt * 8 + g;
                bf[nt][0] = sB[(ks * 8 + tg) * PAD_B + n];
                bf[nt][1] = sB[(ks * 8 + tg + 4) * PAD_B + n];
            }
            #pragma unroll
            for (int mt = 0; mt < 2; mt++)
                #pragma unroll
                for (int nt = 0; nt < 2; nt++) mma_tf32(acco[mt][nt], af[mt], bf[nt]);
        }
        __syncthreads();

        #pragma unroll
        for (int mt = 0; mt < 2; mt++) {
            int r0 = rw * 32 + mt * 16 + g;
            #pragma unroll
            for (int nt = 0; nt < 2; nt++) {
                int c0 = cw * 16 + nt * 8 + tg * 2;
                sAf[r0 * PAD_NA + c0]           = fmaxf(acco[mt][nt][0] + sEB[c0], 0.0f);
                sAf[r0 * PAD_NA + c0 + 1]       = fmaxf(acco[mt][nt][1] + sEB[c0 + 1], 0.0f);
                sAf[(r0 + 8) * PAD_NA + c0]     = fmaxf(acco[mt][nt][2] + sEB[c0], 0.0f);
                sAf[(r0 + 8) * PAD_NA + c0 + 1] = fmaxf(acco[mt][nt][3] + sEB[c0 + 1], 0.0f);
            }
        }
        if (tid < 192) sLNs[tid] = oW2[tid];
        __syncthreads();

        if (tid < 192) {
            int row = tid / 3;
            int k3 = tid % 3;
            float o = ob2[k3];
            #pragma unroll 8
            for (int i = 0; i < HH; i++)
                o += sAf[row * PAD_NA + i] * sLNs[i * 3 + k3];
            outp[(size_t)(node0 + row) * 3 + k3] = o;
        }
    }
}

extern "C" void kernel_launch(void* const* d_in, const int* in_sizes, int n_in,
                              void* d_out, int out_size) {
    const float* z   = (const float*)d_in[0];
    const int*   ei  = (const int*)d_in[1];
    const float* nf  = (const float*)d_in[2];
    const float* Wg  = (const float*)d_in[3];
    const float* bg  = (const float*)d_in[4];
    const float* Wn  = (const float*)d_in[5];
    const float* bn  = (const float*)d_in[6];
    const float* eW1 = (const float*)d_in[7];
    const float* eb1 = (const float*)d_in[8];
    const float* eW2 = (const float*)d_in[9];
    const float* eb2 = (const float*)d_in[10];
    const float* nW1 = (const float*)d_in[14];
    const float* nb1 = (const float*)d_in[15];
    const float* nW2 = (const float*)d_in[16];
    const float* nb2 = (const float*)d_in[17];
    const float* lng = (const float*)d_in[18];
    const float* lnb = (const float*)d_in[19];
    const float* oW1 = (const float*)d_in[20];
    const float* ob1 = (const float*)d_in[21];
    const float* oW2 = (const float*)d_in[22];
    const float* ob2 = (const float*)d_in[23];

    void* pAgg;
    cudaGetSymbolAddress(&pAgg, d_agg);
    cudaMemsetAsync(pAgg, 0, sizeof(float) * BB * NN * HH);

    cudaFuncSetAttribute((const void*)edge_kernel,
                         cudaFuncAttributeMaxDynamicSharedMemorySize, SME_TOTAL);
    cudaFuncSetAttribute((const void*)node_kernel,
                         cudaFuncAttributeMaxDynamicSharedMemorySize, SMN_TOTAL);

    g_kernel<<<1, 1024>>>(z, Wg, bg);
    h_kernel<<<BB * NN / 4, 256>>>(nf, Wn, bn, eW1, eb1);
    csr_kernel<<<1, 1024>>>(ei, ei + EE);

    for (int l = 0; l < LL; l++) {
        edge_kernel<<<EDGE_GRID, 256, SME_TOTAL>>>(
            eW2 + (size_t)l * HH * HH, eb2 + l * HH);
        const float* eW1n = (l + 1 < LL) ? eW1 + (size_t)(l + 1) * 129 * HH : nullptr;
        const float* eb1n = (l + 1 < LL) ? eb1 + (l + 1) * HH : nullptr;
        node_kernel<<<BB * NN / 64, 256, SMN_TOTAL>>>(
            nW1 + (size_t)l * 2 * HH * HH, nb1 + l * HH,
            nW2 + (size_t)l * HH * HH, nb2 + l * HH,
            lng + l * HH, lnb + l * HH,
            eW1n, eb1n,
            oW1, ob1, oW2, ob2, (float*)d_out);
    }
}

// round 16
// speedup vs baseline: 1.6478x; 1.0678x over previous
#include <cuda_runtime.h>
#include <cstdint>

#define BB 16
#define LATENT 128
#define NN 1024
#define EE 32768
#define HH 64
#define LL 4
#define TPB 256                    // tiles per batch: EE/128
#define NTILES (BB * TPB)          // 4096
#define EDGE_GRID 444              // 148 SMs * 3 CTAs

// ---- scratch (device globals; no allocations allowed) ----
__device__ float d_g[BB * HH];
__device__ float d_h[BB * NN * HH];
__device__ float d_p1[BB * NN * HH];
__device__ float d_p2[BB * NN * HH];
__device__ float d_agg[BB * NN * HH];
__device__ int   d_rowptr[NN + 1];
__device__ int   d_rs[EE];
__device__ int   d_cs[EE];

// 3-instruction silu via HW tanh: silu(x) = h + h*tanh(h), h = x/2
__device__ __forceinline__ float silu(float x) {
    float h = 0.5f * x;
    float t;
    asm("tanh.approx.f32 %0, %1;" : "=f"(t) : "f"(h));
    return fmaf(h, t, h);
}

__device__ __forceinline__ uint32_t f2tf32(float x) {
    uint32_t r;
    asm("cvt.rna.tf32.f32 %0, %1;" : "=r"(r) : "f"(x));
    return r;
}

__device__ __forceinline__ void mma_tf32(float* c, const uint32_t* a, const uint32_t* b) {
    asm volatile(
        "mma.sync.aligned.m16n8k8.row.col.f32.tf32.tf32.f32 "
        "{%0,%1,%2,%3}, {%4,%5,%6,%7}, {%8,%9}, {%0,%1,%2,%3};"
        : "+f"(c[0]), "+f"(c[1]), "+f"(c[2]), "+f"(c[3])
        : "r"(a[0]), "r"(a[1]), "r"(a[2]), "r"(a[3]), "r"(b[0]), "r"(b[1]));
}

// ---- edge kernel SMEM layout ----
#define PAD_A 68
#define SME_A     0                 // 128*68*4 = 34816
#define SME_W2P   34816             // packed B pairs: 17408
#define SME_B2    52224             // 256
#define SME_R     52480             // 512
#define SME_P1    52992             // p1 cache: 16*64*4 = 4096
#define SME_TOTAL 57088

// ---- node kernel SMEM layout ----
#define PAD_B  72
#define PAD_NA 132
#define PAD_NP 136
#define SMN_A    0
#define SMN_B    33792
#define SMN_BIAS (SMN_B + 36864)
#define SMN_LN   (SMN_BIAS + 1280)
#define SMN_TOTAL (SMN_LN + 2048)

// ---- g = z @ Wg + bg ----
__global__ void g_kernel(const float* __restrict__ z,
                         const float* __restrict__ Wg,
                         const float* __restrict__ bg) {
    int t = blockIdx.x * blockDim.x + threadIdx.x;
    int b = t >> 6, k = t & 63;
    float acc = bg[k];
    const float* zr = z + b * LATENT;
    #pragma unroll 8
    for (int i = 0; i < LATENT; i++) acc += zr[i] * Wg[i * HH + k];
    d_g[t] = acc;
}

// ---- h + proj for layer 0; 4 nodes per block ----
__global__ void __launch_bounds__(256) h_kernel(
    const float* __restrict__ nf, const float* __restrict__ Wn,
    const float* __restrict__ bn, const float* __restrict__ eW1,
    const float* __restrict__ eb1) {
    int sub = threadIdx.x >> 6;
    int k = threadIdx.x & 63;
    int node = blockIdx.x * 4 + sub;
    int b = node >> 10, n = node & (NN - 1);
    __shared__ float x[4][HH];
    float v = bn[k] + d_g[b * HH + k];
    v += nf[n * 3 + 0] * Wn[0 * HH + k]
       + nf[n * 3 + 1] * Wn[1 * HH + k]
       + nf[n * 3 + 2] * Wn[2 * HH + k];
    d_h[node * HH + k] = v;
    x[sub][k] = v;
    __syncthreads();
    float a1 = eb1[k], a2 = 0.0f;
    #pragma unroll 8
    for (int i = 0; i < HH; i++) {
        float xv = x[sub][i];
        a1 += xv * eW1[i * HH + k];
        a2 += xv * eW1[(HH + i) * HH + k];
    }
    d_p1[node * HH + k] = a1;
    d_p2[node * HH + k] = a2;
}

// ---- CSR build ----
__global__ void csr_kernel(const int* __restrict__ row,
                           const int* __restrict__ col) {
    __shared__ int sc[NN];
    __shared__ int wo[NN];
    int t = threadIdx.x;
    sc[t] = 0;
    __syncthreads();
    for (int e = t; e < EE; e += 1024) atomicAdd(&sc[row[e]], 1);
    __syncthreads();
    int v = sc[t];
    #pragma unroll
    for (int o = 1; o < NN; o <<= 1) {
        int u = (t >= o) ? sc[t - o] : 0;
        __syncthreads();
        sc[t] += u;
        __syncthreads();
    }
    d_rowptr[t + 1] = sc[t];
    if (t == 0) d_rowptr[0] = 0;
    wo[t] = sc[t] - v;
    __syncthreads();
    for (int e = t; e < EE; e += 1024) {
        int r = row[e];
        int p = atomicAdd(&wo[r], 1);
        d_rs[p] = r;
        d_cs[p] = col[e];
    }
}

// ---- fused edge kernel: row-coalesced gather, p1 cache, packed-B ----
__global__ void __launch_bounds__(256, 3) edge_kernel(
    const float* __restrict__ eW2, const float* __restrict__ eb2) {
    extern __shared__ __align__(16) char smem[];
    float*    sAf  = (float*)(smem + SME_A);
    uint32_t* sAu  = (uint32_t*)(smem + SME_A);
    uint32_t* sW2p = (uint32_t*)(smem + SME_W2P);
    const uint2* sW2p2 = (const uint2*)(smem + SME_W2P);
    float*    sB2  = (float*)(smem + SME_B2);
    int*      sR   = (int*)(smem + SME_R);
    float*    sP1  = (float*)(smem + SME_P1);

    int tid = threadIdx.x;
    int wid = tid >> 5;
    int lane = tid & 31;
    int g = lane >> 2;
    int tg = lane & 3;
    int rb = wid & 3;
    int ch = wid >> 2;

    for (int idx = tid; idx < HH * HH; idx += 256) {
        int i = idx >> 6;
        int n = idx & 63;
        int ks = i >> 3;
        int r8 = i & 7;
        int tgw = (r8 < 4) ? r8 : r8 - 4;
        int slot = (r8 < 4) ? 0 : 1;
        sW2p[(((ks * 4 + tgw) * 68) + n) * 2 + slot] = f2tf32(eW2[idx]);
    }
    if (tid < HH) sB2[tid] = eb2[tid];
    __syncthreads();

    // gather mapping: warp covers 16 rows; lanes 0-15 one row, 16-31 the next
    int gsub = lane >> 4;
    int goff = (lane & 15) * 4;

    for (int tile = blockIdx.x; tile < NTILES; tile += EDGE_GRID) {
        int b = tile >> 8;
        int jbase = (tile & (TPB - 1)) * 128;

        if (tid < 128) sR[tid] = d_rs[jbase + tid];
        int r0v = d_rs[jbase];
        int nseg = d_rs[jbase + 127] - r0v + 1;
        if (nseg <= 16) {
            for (int u = tid; u < nseg * 16; u += 256) {
                int s = u >> 4, q = (u & 15) * 4;
                float4 val = *reinterpret_cast<const float4*>(
                    d_p1 + (size_t)(b * NN + r0v + s) * HH + q);
                *reinterpret_cast<float4*>(sP1 + s * 64 + q) = val;
            }
        }
        __syncthreads();

        // a-stage: row-coalesced p2 gather + p1-cache combine + silu + cvt
        {
            int rbase = wid * 16;
            #pragma unroll
            for (int it = 0; it < 8; it++) {
                int row = rbase + it * 2 + gsub;
                int c = d_cs[jbase + row];
                int r = sR[row];
                float4 v = *reinterpret_cast<const float4*>(
                    d_p2 + (size_t)(b * NN + c) * HH + goff);
                float4 u = (nseg <= 16)
                    ? *reinterpret_cast<const float4*>(sP1 + (r - r0v) * 64 + goff)
                    : *reinterpret_cast<const float4*>(
                          d_p1 + (size_t)(b * NN + r) * HH + goff);
                uint4 t;
                t.x = f2tf32(silu(u.x + v.x));
                t.y = f2tf32(silu(u.y + v.y));
                t.z = f2tf32(silu(u.z + v.z));
                t.w = f2tf32(silu(u.w + v.w));
                *reinterpret_cast<uint4*>(sAu + row * PAD_A + goff) = t;
            }
        }
        __syncthreads();

        float acc[2][4][4];
        #pragma unroll
        for (int mt = 0; mt < 2; mt++)
            #pragma unroll
            for (int jj = 0; jj < 4; jj++)
                #pragma unroll
                for (int q = 0; q < 4; q++) acc[mt][jj][q] = 0.0f;

        #pragma unroll
        for (int ks = 0; ks < 8; ks++) {
            uint32_t af[2][4];
            #pragma unroll
            for (int mt = 0; mt < 2; mt++) {
                int rr = rb * 32 + mt * 16 + g;
                int cc = ks * 8 + tg;
                af[mt][0] = sAu[rr * PAD_A + cc];
                af[mt][1] = sAu[(rr + 8) * PAD_A + cc];
                af[mt][2] = sAu[rr * PAD_A + cc + 4];
                af[mt][3] = sAu[(rr + 8) * PAD_A + cc + 4];
            }
            uint32_t bf[4][2];
            #pragma unroll
            for (int jj = 0; jj < 4; jj++) {
                int n = ch * 32 + jj * 8 + g;
                uint2 bv = sW2p2[(ks * 4 + tg) * 68 + n];
                bf[jj][0] = bv.x;
                bf[jj][1] = bv.y;
            }
            #pragma unroll
            for (int mt = 0; mt < 2; mt++)
                #pragma unroll
                for (int jj = 0; jj < 4; jj++) mma_tf32(acc[mt][jj], af[mt], bf[jj]);
        }
        __syncthreads();

        #pragma unroll
        for (int mt = 0; mt < 2; mt++) {
            int r0 = rb * 32 + mt * 16 + g;
            #pragma unroll
            for (int jj = 0; jj < 4; jj++) {
                int c0 = ch * 32 + jj * 8 + tg * 2;
                sAf[r0 * PAD_A + c0]           = silu(acc[mt][jj][0] + sB2[c0]);
                sAf[r0 * PAD_A + c0 + 1]       = silu(acc[mt][jj][1] + sB2[c0 + 1]);
                sAf[(r0 + 8) * PAD_A + c0]     = silu(acc[mt][jj][2] + sB2[c0]);
                sAf[(r0 + 8) * PAD_A + c0 + 1] = silu(acc[mt][jj][3] + sB2[c0 + 1]);
            }
        }
        __syncthreads();

        {
            int k2 = tid & 63;
            int seg = tid >> 6;
            int r0 = seg * 32;
            int rcur = sR[r0];
            float a = 0.0f;
            #pragma unroll 8
            for (int rr = r0; rr < r0 + 32; rr++) {
                int rn = sR[rr];
                if (rn != rcur) {
                    atomicAdd(&d_agg[((size_t)b * NN + rcur) * HH + k2], a);
                    a = 0.0f;
                    rcur = rn;
                }
                a += sAf[rr * PAD_A + k2];
            }
            atomicAdd(&d_agg[((size_t)b * NN + rcur) * HH + k2], a);
        }
        __syncthreads();
    }
}

// ---- tensorized node kernel + fused output head on last layer ----
__global__ void __launch_bounds__(256, 3) node_kernel(
    const float* __restrict__ nW1, const float* __restrict__ nb1,
    const float* __restrict__ nW2, const float* __restrict__ nb2,
    const float* __restrict__ lng, const float* __restrict__ lnb,
    const float* __restrict__ eW1n, const float* __restrict__ eb1n,
    const float* __restrict__ oW1, const float* __restrict__ ob1,
    const float* __restrict__ oW2, const float* __restrict__ ob2,
    float* __restrict__ outp) {
    extern __shared__ __align__(16) char smem[];
    float*    sAf = (float*)(smem + SMN_A);
    uint32_t* sAu = (uint32_t*)(smem + SMN_A);
    uint32_t* sB  = (uint32_t*)(smem + SMN_B);
    float*    sNB1 = (float*)(smem + SMN_BIAS);
    float*    sNB2 = sNB1 + 64;
    float*    sLG  = sNB1 + 128;
    float*    sLB  = sNB1 + 192;
    float*    sEB  = sNB1 + 256;
    float*    sLNs = (float*)(smem + SMN_LN);
    float*    sLNq = sLNs + 256;

    int tid = threadIdx.x;
    int wid = tid >> 5;
    int lane = tid & 31;
    int g = lane >> 2;
    int tg = lane & 3;
    int rw = wid & 1;
    int cw = wid >> 1;
    int node0 = blockIdx.x * 64;

    {
        int row = tid & 63;
        int qtr = tid >> 6;
        const float* src = (qtr < 2)
            ? d_h  + (size_t)(node0 + row) * HH + qtr * 32
            : d_agg + (size_t)(node0 + row) * HH + (qtr - 2) * 32;
        uint32_t* dst = sAu + row * PAD_NA + qtr * 32;
        #pragma unroll
        for (int i4 = 0; i4 < 8; i4++) {
            float4 v = reinterpret_cast<const float4*>(src)[i4];
            uint4 t;
            t.x = f2tf32(v.x); t.y = f2tf32(v.y);
            t.z = f2tf32(v.z); t.w = f2tf32(v.w);
            reinterpret_cast<uint4*>(dst)[i4] = t;
        }
        if (qtr >= 2) {
            float4* az = reinterpret_cast<float4*>(
                d_agg + (size_t)(node0 + row) * HH + (qtr - 2) * 32);
            #pragma unroll
            for (int i4 = 0; i4 < 8; i4++) az[i4] = make_float4(0, 0, 0, 0);
        }
    }
    for (int idx = tid; idx < 128 * 64; idx += 256) {
        sB[(idx >> 6) * PAD_B + (idx & 63)] = f2tf32(nW1[idx]);
    }
    if (tid < 64) {
        sNB1[tid] = nb1[tid];
        sNB2[tid] = nb2[tid];
        sLG[tid] = lng[tid];
        sLB[tid] = lnb[tid];
        sEB[tid] = eW1n ? eb1n[tid] : ob1[tid];
    }
    __syncthreads();

    float acc[2][2][4];
    #pragma unroll
    for (int mt = 0; mt < 2; mt++)
        #pragma unroll
        for (int nt = 0; nt < 2; nt++)
            #pragma unroll
            for (int q = 0; q < 4; q++) acc[mt][nt][q] = 0.0f;
    #pragma unroll
    for (int ks = 0; ks < 16; ks++) {
        uint32_t af[2][4];
        #pragma unroll
        for (int mt = 0; mt < 2; mt++) {
            int rr = rw * 32 + mt * 16 + g;
            int cc = ks * 8 + tg;
            af[mt][0] = sAu[rr * PAD_NA + cc];
            af[mt][1] = sAu[(rr + 8) * PAD_NA + cc];
            af[mt][2] = sAu[rr * PAD_NA + cc + 4];
            af[mt][3] = sAu[(rr + 8) * PAD_NA + cc + 4];
        }
        uint32_t bf[2][2];
        #pragma unroll
        for (int nt = 0; nt < 2; nt++) {
            int n = cw * 16 + nt * 8 + g;
            bf[nt][0] = sB[(ks * 8 + tg) * PAD_B + n];
            bf[nt][1] = sB[(ks * 8 + tg + 4) * PAD_B + n];
        }
        #pragma unroll
        for (int mt = 0; mt < 2; mt++)
            #pragma unroll
            for (int nt = 0; nt < 2; nt++) mma_tf32(acc[mt][nt], af[mt], bf[nt]);
    }
    __syncthreads();

    #pragma unroll
    for (int mt = 0; mt < 2; mt++) {
        int r0 = rw * 32 + mt * 16 + g;
        #pragma unroll
        for (int nt = 0; nt < 2; nt++) {
            int c0 = cw * 16 + nt * 8 + tg * 2;
            sAu[r0 * PAD_NA + c0]           = f2tf32(silu(acc[mt][nt][0] + sNB1[c0]));
            sAu[r0 * PAD_NA + c0 + 1]       = f2tf32(silu(acc[mt][nt][1] + sNB1[c0 + 1]));
            sAu[(r0 + 8) * PAD_NA + c0]     = f2tf32(silu(acc[mt][nt][2] + sNB1[c0]));
            sAu[(r0 + 8) * PAD_NA + c0 + 1] = f2tf32(silu(acc[mt][nt][3] + sNB1[c0 + 1]));
        }
    }
    for (int idx = tid; idx < 64 * 64; idx += 256) {
        sB[(idx >> 6) * PAD_B + (idx & 63)] = f2tf32(nW2[idx]);
    }
    __syncthreads();

    #pragma unroll
    for (int mt = 0; mt < 2; mt++)
        #pragma unroll
        for (int nt = 0; nt < 2; nt++)
            #pragma unroll
            for (int q = 0; q < 4; q++) acc[mt][nt][q] = 0.0f;
    #pragma unroll
    for (int ks = 0; ks < 8; ks++) {
        uint32_t af[2][4];
        #pragma unroll
        for (int mt = 0; mt < 2; mt++) {
            int rr = rw * 32 + mt * 16 + g;
            int cc = ks * 8 + tg;
            af[mt][0] = sAu[rr * PAD_NA + cc];
            af[mt][1] = sAu[(rr + 8) * PAD_NA + cc];
            af[mt][2] = sAu[rr * PAD_NA + cc + 4];
            af[mt][3] = sAu[(rr + 8) * PAD_NA + cc + 4];
        }
        uint32_t bf[2][2];
        #pragma unroll
        for (int nt = 0; nt < 2; nt++) {
            int n = cw * 16 + nt * 8 + g;
            bf[nt][0] = sB[(ks * 8 + tg) * PAD_B + n];
            bf[nt][1] = sB[(ks * 8 + tg + 4) * PAD_B + n];
        }
        #pragma unroll
        for (int mt = 0; mt < 2; mt++)
            #pragma unroll
            for (int nt = 0; nt < 2; nt++) mma_tf32(acc[mt][nt], af[mt], bf[nt]);
    }
    __syncthreads();

    #pragma unroll
    for (int mt = 0; mt < 2; mt++) {
        int r0 = rw * 32 + mt * 16 + g;
        #pragma unroll
        for (int nt = 0; nt < 2; nt++) {
            int c0 = cw * 16 + nt * 8 + tg * 2;
            float2 h0 = *reinterpret_cast<const float2*>(d_h + (size_t)(node0 + r0) * HH + c0);
            float2 h1 = *reinterpret_cast<const float2*>(d_h + (size_t)(node0 + r0 + 8) * HH + c0);
            sAf[r0 * PAD_NA + c0]           = h0.x + acc[mt][nt][0] + sNB2[c0];
            sAf[r0 * PAD_NA + c0 + 1]       = h0.y + acc[mt][nt][1] + sNB2[c0 + 1];
            sAf[(r0 + 8) * PAD_NA + c0]     = h1.x + acc[mt][nt][2] + sNB2[c0];
            sAf[(r0 + 8) * PAD_NA + c0 + 1] = h1.y + acc[mt][nt][3] + sNB2[c0 + 1];
        }
    }
    if (eW1n) {
        for (int idx = tid; idx < 64 * 128; idx += 256) {
            int i = idx >> 7, n = idx & 127;
            float v = (n < 64) ? eW1n[i * HH + n] : eW1n[(64 + i) * HH + (n - 64)];
            sB[i * PAD_NP + n] = f2tf32(v);
        }
    } else {
        for (int idx = tid; idx < 64 * 64; idx += 256) {
            sB[(idx >> 6) * PAD_B + (idx & 63)] = f2tf32(oW1[idx]);
        }
    }
    __syncthreads();

    {
        int row = tid >> 2;
        int part = tid & 3;
        float s = 0.0f, q = 0.0f;
        #pragma unroll
        for (int i = 0; i < 16; i++) {
            float v = sAf[row * PAD_NA + part * 16 + i];
            s += v;
            q += v * v;
        }
        sLNs[row * 4 + part] = s;
        sLNq[row * 4 + part] = q;
    }
    __syncthreads();
    {
        int row = tid >> 2;
        int part = tid & 3;
        float s = sLNs[row * 4] + sLNs[row * 4 + 1] + sLNs[row * 4 + 2] + sLNs[row * 4 + 3];
        float q = sLNq[row * 4] + sLNq[row * 4 + 1] + sLNq[row * 4 + 2] + sLNq[row * 4 + 3];
        float mu = s * (1.0f / HH);
        float var = q * (1.0f / HH) - mu * mu;
        float rstd = rsqrtf(var + 1e-5f);
        float hv[16];
        #pragma unroll
        for (int i = 0; i < 16; i++) {
            int c = part * 16 + i;
            hv[i] = (sAf[row * PAD_NA + c] - mu) * rstd * sLG[c] + sLB[c];
        }
        float4* hout = reinterpret_cast<float4*>(d_h + (size_t)(node0 + row) * HH + part * 16);
        #pragma unroll
        for (int i4 = 0; i4 < 4; i4++)
            hout[i4] = make_float4(hv[i4 * 4], hv[i4 * 4 + 1], hv[i4 * 4 + 2], hv[i4 * 4 + 3]);
        #pragma unroll
        for (int i = 0; i < 16; i++)
            sAu[row * PAD_NA + part * 16 + i] = f2tf32(hv[i]);
    }
    __syncthreads();

    if (eW1n) {
        float acc3[2][4][4];
        #pragma unroll
        for (int mt = 0; mt < 2; mt++)
            #pragma unroll
            for (int nt = 0; nt < 4; nt++)
                #pragma unroll
                for (int q = 0; q < 4; q++) acc3[mt][nt][q] = 0.0f;
        #pragma unroll
        for (int ks = 0; ks < 8; ks++) {
            uint32_t af[2][4];
            #pragma unroll
            for (int mt = 0; mt < 2; mt++) {
                int rr = rw * 32 + mt * 16 + g;
                int cc = ks * 8 + tg;
                af[mt][0] = sAu[rr * PAD_NA + cc];
                af[mt][1] = sAu[(rr + 8) * PAD_NA + cc];
                af[mt][2] = sAu[rr * PAD_NA + cc + 4];
                af[mt][3] = sAu[(rr + 8) * PAD_NA + cc + 4];
            }
            uint32_t bf[4][2];
            #pragma unroll
            for (int nt = 0; nt < 4; nt++) {
                int n = cw * 32 + nt * 8 + g;
                bf[nt][0] = sB[(ks * 8 + tg) * PAD_NP + n];
                bf[nt][1] = sB[(ks * 8 + tg + 4) * PAD_NP + n];
            }
            #pragma unroll
            for (int mt = 0; mt < 2; mt++)
                #pragma unroll
                for (int nt = 0; nt < 4; nt++) mma_tf32(acc3[mt][nt], af[mt], bf[nt]);
        }
        #pragma unroll
        for (int mt = 0; mt < 2; mt++) {
            int r0 = rw * 32 + mt * 16 + g;
            #pragma unroll
            for (int nt = 0; nt < 4; nt++) {
                int c0 = cw * 32 + nt * 8 + tg * 2;
                #pragma unroll
                for (int hh = 0; hh < 2; hh++) {
                    int rr = r0 + hh * 8;
                    float v0 = acc3[mt][nt][hh * 2];
                    float v1 = acc3[mt][nt][hh * 2 + 1];
                    if (c0 < 64) {
                        v0 += sEB[c0];
                        v1 += sEB[c0 + 1];
                        *reinterpret_cast<float2*>(d_p1 + (size_t)(node0 + rr) * HH + c0)
                            = make_float2(v0, v1);
                    } else {
                        *reinterpret_cast<float2*>(d_p2 + (size_t)(node0 + rr) * HH + (c0 - 64))
                            = make_float2(v0, v1);
                    }
                }
            }
        }
    } else {
        float acco[2][2][4];
        #pragma unroll
        for (int mt = 0; mt < 2; mt++)
            #pragma unroll
            for (int nt = 0; nt < 2; nt++)
                #pragma unroll
                for (int q = 0; q < 4; q++) acco[mt][nt][q] = 0.0f;
        #pragma unroll
        for (int ks = 0; ks < 8; ks++) {
            uint32_t af[2][4];
            #pragma unroll
            for (int mt = 0; mt < 2; mt++) {
                int rr = rw * 32 + mt * 16 + g;
                int cc = ks * 8 + tg;
                af[mt][0] = sAu[rr * PAD_NA + cc];
                af[mt][1] = sAu[(rr + 8) * PAD_NA + cc];
                af[mt][2] = sAu[rr * PAD_NA + cc + 4];
                af[mt][3] = sAu[(rr + 8) * PAD_NA + cc + 4];
            }
            uint32_t bf[2][2];
            #pragma unroll
            for (int nt = 0; nt < 2; nt++) {
                int n = cw * 16 + nt * 8 + g;
                bf[nt][0] = sB[(ks * 8 + tg) * PAD_B + n];
                bf[nt][1] = sB[(ks * 8 + tg + 4) * PAD_B + n];
            }
            #pragma unroll
            for (int mt = 0; mt < 2; mt++)
                #pragma unroll
                for (int nt = 0; nt < 2; nt++) mma_tf32(acco[mt][nt], af[mt], bf[nt]);
        }
        __syncthreads();

        #pragma unroll
        for (int mt = 0; mt < 2; mt++) {
            int r0 = rw * 32 + mt * 16 + g;
            #pragma unroll
            for (int nt = 0; nt < 2; nt++) {
                int c0 = cw * 16 + nt * 8 + tg * 2;
                sAf[r0 * PAD_NA + c0]           = fmaxf(acco[mt][nt][0] + sEB[c0], 0.0f);
                sAf[r0 * PAD_NA + c0 + 1]       = fmaxf(acco[mt][nt][1] + sEB[c0 + 1], 0.0f);
                sAf[(r0 + 8) * PAD_NA + c0]     = fmaxf(acco[mt][nt][2] + sEB[c0], 0.0f);
                sAf[(r0 + 8) * PAD_NA + c0 + 1] = fmaxf(acco[mt][nt][3] + sEB[c0 + 1], 0.0f);
            }
        }
        if (tid < 192) sLNs[tid] = oW2[tid];
        __syncthreads();

        if (tid < 192) {
            int row = tid / 3;
            int k3 = tid % 3;
            float o = ob2[k3];
            #pragma unroll 8
            for (int i = 0; i < HH; i++)
                o += sAf[row * PAD_NA + i] * sLNs[i * 3 + k3];
            outp[(size_t)(node0 + row) * 3 + k3] = o;
        }
    }
}

extern "C" void kernel_launch(void* const* d_in, const int* in_sizes, int n_in,
                              void* d_out, int out_size) {
    const float* z   = (const float*)d_in[0];
    const int*   ei  = (const int*)d_in[1];
    const float* nf  = (const float*)d_in[2];
    const float* Wg  = (const float*)d_in[3];
    const float* bg  = (const float*)d_in[4];
    const float* Wn  = (const float*)d_in[5];
    const float* bn  = (const float*)d_in[6];
    const float* eW1 = (const float*)d_in[7];
    const float* eb1 = (const float*)d_in[8];
    const float* eW2 = (const float*)d_in[9];
    const float* eb2 = (const float*)d_in[10];
    const float* nW1 = (const float*)d_in[14];
    const float* nb1 = (const float*)d_in[15];
    const float* nW2 = (const float*)d_in[16];
    const float* nb2 = (const float*)d_in[17];
    const float* lng = (const float*)d_in[18];
    const float* lnb = (const float*)d_in[19];
    const float* oW1 = (const float*)d_in[20];
    const float* ob1 = (const float*)d_in[21];
    const float* oW2 = (const float*)d_in[22];
    const float* ob2 = (const float*)d_in[23];

    void* pAgg;
    cudaGetSymbolAddress(&pAgg, d_agg);
    cudaMemsetAsync(pAgg, 0, sizeof(float) * BB * NN * HH);

    cudaFuncSetAttribute((const void*)edge_kernel,
                         cudaFuncAttributeMaxDynamicSharedMemorySize, SME_TOTAL);
    cudaFuncSetAttribute((const void*)node_kernel,
                         cudaFuncAttributeMaxDynamicSharedMemorySize, SMN_TOTAL);

    g_kernel<<<1, 1024>>>(z, Wg, bg);
    h_kernel<<<BB * NN / 4, 256>>>(nf, Wn, bn, eW1, eb1);
    csr_kernel<<<1, 1024>>>(ei, ei + EE);

    for (int l = 0; l < LL; l++) {
        edge_kernel<<<EDGE_GRID, 256, SME_TOTAL>>>(
            eW2 + (size_t)l * HH * HH, eb2 + l * HH);
        const float* eW1n = (l + 1 < LL) ? eW1 + (size_t)(l + 1) * 129 * HH : nullptr;
        const float* eb1n = (l + 1 < LL) ? eb1 + (l + 1) * HH : nullptr;
        node_kernel<<<BB * NN / 64, 256, SMN_TOTAL>>>(
            nW1 + (size_t)l * 2 * HH * HH, nb1 + l * HH,
            nW2 + (size_t)l * HH * HH, nb2 + l * HH,
            lng + l * HH, lnb + l * HH,
            eW1n, eb1n,
            oW1, ob1, oW2, ob2, (float*)d_out);
    }
}

// round 17
// speedup vs baseline: 1.9063x; 1.1569x over previous
#include <cuda_runtime.h>
#include <cuda_fp16.h>
#include <cstdint>

#define BB 16
#define LATENT 128
#define NN 1024
#define EE 32768
#define HH 64
#define LL 4
#define TPB 256                    // tiles per batch: EE/128
#define NTILES (BB * TPB)          // 4096
#define EDGE_GRID 444              // 148 SMs * 3 CTAs

// ---- scratch (device globals; no allocations allowed) ----
__device__ float d_g[BB * HH];
__device__ float d_h[BB * NN * HH];
__device__ float d_p1[BB * NN * HH];
__device__ float d_p2[BB * NN * HH];
__device__ float d_agg[BB * NN * HH];
__device__ int   d_rowptr[NN + 1];
__device__ int   d_rs[EE];
__device__ int   d_cs[EE];

// 3-instruction silu via HW tanh: silu(x) = h + h*tanh(h), h = x/2
__device__ __forceinline__ float silu(float x) {
    float h = 0.5f * x;
    float t;
    asm("tanh.approx.f32 %0, %1;" : "=f"(t) : "f"(h));
    return fmaf(h, t, h);
}

__device__ __forceinline__ uint32_t f2tf32(float x) {
    uint32_t r;
    asm("cvt.rna.tf32.f32 %0, %1;" : "=r"(r) : "f"(x));
    return r;
}

__device__ __forceinline__ uint32_t pack_h2(float lo, float hi) {
    __half2 h = __float22half2_rn(make_float2(lo, hi));
    return *reinterpret_cast<uint32_t*>(&h);
}

__device__ __forceinline__ void mma_tf32(float* c, const uint32_t* a, const uint32_t* b) {
    asm volatile(
        "mma.sync.aligned.m16n8k8.row.col.f32.tf32.tf32.f32 "
        "{%0,%1,%2,%3}, {%4,%5,%6,%7}, {%8,%9}, {%0,%1,%2,%3};"
        : "+f"(c[0]), "+f"(c[1]), "+f"(c[2]), "+f"(c[3])
        : "r"(a[0]), "r"(a[1]), "r"(a[2]), "r"(a[3]), "r"(b[0]), "r"(b[1]));
}

__device__ __forceinline__ void mma_f16(float* c, const uint32_t* a, const uint32_t* b) {
    asm volatile(
        "mma.sync.aligned.m16n8k16.row.col.f32.f16.f16.f32 "
        "{%0,%1,%2,%3}, {%4,%5,%6,%7}, {%8,%9}, {%0,%1,%2,%3};"
        : "+f"(c[0]), "+f"(c[1]), "+f"(c[2]), "+f"(c[3])
        : "r"(a[0]), "r"(a[1]), "r"(a[2]), "r"(a[3]), "r"(b[0]), "r"(b[1]));
}

// ---- edge kernel SMEM layout (fp16 path) ----
#define PAD_AH 36                  // uint32 (half2) stride per row: 32 + 4 pad
#define SME_AH    0                // 128*36*4 = 18432
#define SME_W2P   18432            // packed half2 B pairs: 16*68*2*4 = 8704
#define SME_B2    27136            // 256
#define SME_R     27392            // 512
#define SME_P1    27904            // p1 cache: 16*64*4 = 4096
#define SME_TOTAL 32000

// ---- node kernel SMEM layout (unchanged, tf32) ----
#define PAD_B  72
#define PAD_NA 132
#define PAD_NP 136
#define SMN_A    0
#define SMN_B    33792
#define SMN_BIAS (SMN_B + 36864)
#define SMN_LN   (SMN_BIAS + 1280)
#define SMN_TOTAL (SMN_LN + 2048)

// ---- g = z @ Wg + bg ----
__global__ void g_kernel(const float* __restrict__ z,
                         const float* __restrict__ Wg,
                         const float* __restrict__ bg) {
    int t = blockIdx.x * blockDim.x + threadIdx.x;
    int b = t >> 6, k = t & 63;
    float acc = bg[k];
    const float* zr = z + b * LATENT;
    #pragma unroll 8
    for (int i = 0; i < LATENT; i++) acc += zr[i] * Wg[i * HH + k];
    d_g[t] = acc;
}

// ---- h + proj for layer 0; 4 nodes per block ----
__global__ void __launch_bounds__(256) h_kernel(
    const float* __restrict__ nf, const float* __restrict__ Wn,
    const float* __restrict__ bn, const float* __restrict__ eW1,
    const float* __restrict__ eb1) {
    int sub = threadIdx.x >> 6;
    int k = threadIdx.x & 63;
    int node = blockIdx.x * 4 + sub;
    int b = node >> 10, n = node & (NN - 1);
    __shared__ float x[4][HH];
    float v = bn[k] + d_g[b * HH + k];
    v += nf[n * 3 + 0] * Wn[0 * HH + k]
       + nf[n * 3 + 1] * Wn[1 * HH + k]
       + nf[n * 3 + 2] * Wn[2 * HH + k];
    d_h[node * HH + k] = v;
    x[sub][k] = v;
    __syncthreads();
    float a1 = eb1[k], a2 = 0.0f;
    #pragma unroll 8
    for (int i = 0; i < HH; i++) {
        float xv = x[sub][i];
        a1 += xv * eW1[i * HH + k];
        a2 += xv * eW1[(HH + i) * HH + k];
    }
    d_p1[node * HH + k] = a1;
    d_p2[node * HH + k] = a2;
}

// ---- CSR build ----
__global__ void csr_kernel(const int* __restrict__ row,
                           const int* __restrict__ col) {
    __shared__ int sc[NN];
    __shared__ int wo[NN];
    int t = threadIdx.x;
    sc[t] = 0;
    __syncthreads();
    for (int e = t; e < EE; e += 1024) atomicAdd(&sc[row[e]], 1);
    __syncthreads();
    int v = sc[t];
    #pragma unroll
    for (int o = 1; o < NN; o <<= 1) {
        int u = (t >= o) ? sc[t - o] : 0;
        __syncthreads();
        sc[t] += u;
        __syncthreads();
    }
    d_rowptr[t + 1] = sc[t];
    if (t == 0) d_rowptr[0] = 0;
    wo[t] = sc[t] - v;
    __syncthreads();
    for (int e = t; e < EE; e += 1024) {
        int r = row[e];
        int p = atomicAdd(&wo[r], 1);
        d_rs[p] = r;
        d_cs[p] = col[e];
    }
}

// ---- fused edge kernel: fp16 m16n8k16 GEMM, row-coalesced gather, p1 cache ----
__global__ void __launch_bounds__(256, 3) edge_kernel(
    const float* __restrict__ eW2, const float* __restrict__ eb2) {
    extern __shared__ __align__(16) char smem[];
    uint32_t* sAh  = (uint32_t*)(smem + SME_AH);      // half2 words [128][36]
    uint32_t* sW2p = (uint32_t*)(smem + SME_W2P);
    const uint2* sW2p2 = (const uint2*)(smem + SME_W2P);
    float*    sB2  = (float*)(smem + SME_B2);
    int*      sR   = (int*)(smem + SME_R);
    float*    sP1  = (float*)(smem + SME_P1);

    int tid = threadIdx.x;
    int wid = tid >> 5;
    int lane = tid & 31;
    int g = lane >> 2;
    int tg = lane & 3;
    int rb = wid & 3;
    int ch = wid >> 2;

    // stage weights as packed half2 pairs: word kk holds (W[2kk][n], W[2kk+1][n])
    // pair layout: slot0 <-> kk = ks*8+tgw, slot1 <-> kk = ks*8+tgw+4
    for (int idx = tid; idx < 32 * HH; idx += 256) {
        int kk = idx >> 6;
        int n = idx & 63;
        uint32_t hv = pack_h2(eW2[(2 * kk) * HH + n], eW2[(2 * kk + 1) * HH + n]);
        int ks = kk >> 3, r8 = kk & 7;
        int tgw = (r8 < 4) ? r8 : r8 - 4;
        int slot = (r8 < 4) ? 0 : 1;
        sW2p[(((ks * 4 + tgw) * 68) + n) * 2 + slot] = hv;
    }
    if (tid < HH) sB2[tid] = eb2[tid];
    __syncthreads();

    int gsub = lane >> 4;            // row within pair
    int goff = (lane & 15) * 4;      // float offset within row

    for (int tile = blockIdx.x; tile < NTILES; tile += EDGE_GRID) {
        int b = tile >> 8;
        int jbase = (tile & (TPB - 1)) * 128;

        if (tid < 128) sR[tid] = d_rs[jbase + tid];
        int r0v = d_rs[jbase];
        int nseg = d_rs[jbase + 127] - r0v + 1;
        if (nseg <= 16) {
            for (int u = tid; u < nseg * 16; u += 256) {
                int s = u >> 4, q = (u & 15) * 4;
                float4 val = *reinterpret_cast<const float4*>(
                    d_p1 + (size_t)(b * NN + r0v + s) * HH + q);
                *reinterpret_cast<float4*>(sP1 + s * 64 + q) = val;
            }
        }
        __syncthreads();

        // a-stage: row-coalesced p2 gather + p1 combine + silu + half2 pack
        {
            int rbase = wid * 16;
            #pragma unroll
            for (int it = 0; it < 8; it++) {
                int row = rbase + it * 2 + gsub;
                int c = d_cs[jbase + row];
                int r = sR[row];
                float4 v = *reinterpret_cast<const float4*>(
                    d_p2 + (size_t)(b * NN + c) * HH + goff);
                float4 u = (nseg <= 16)
                    ? *reinterpret_cast<const float4*>(sP1 + (r - r0v) * 64 + goff)
                    : *reinterpret_cast<const float4*>(
                          d_p1 + (size_t)(b * NN + r) * HH + goff);
                uint2 t;
                t.x = pack_h2(silu(u.x + v.x), silu(u.y + v.y));
                t.y = pack_h2(silu(u.z + v.z), silu(u.w + v.w));
                *reinterpret_cast<uint2*>(sAh + row * PAD_AH + (lane & 15) * 2) = t;
            }
        }
        __syncthreads();

        // GEMM: fp16 m16n8k16, 4 K-steps; warp = rows rb*32..+31, cols ch*32..+31
        float acc[2][4][4];
        #pragma unroll
        for (int mt = 0; mt < 2; mt++)
            #pragma unroll
            for (int jj = 0; jj < 4; jj++)
                #pragma unroll
                for (int q = 0; q < 4; q++) acc[mt][jj][q] = 0.0f;

        #pragma unroll
        for (int ks = 0; ks < 4; ks++) {
            uint32_t af[2][4];
            #pragma unroll
            for (int mt = 0; mt < 2; mt++) {
                int rr = rb * 32 + mt * 16 + g;
                int cc = ks * 8 + tg;
                af[mt][0] = sAh[rr * PAD_AH + cc];
                af[mt][1] = sAh[(rr + 8) * PAD_AH + cc];
                af[mt][2] = sAh[rr * PAD_AH + cc + 4];
                af[mt][3] = sAh[(rr + 8) * PAD_AH + cc + 4];
            }
            uint32_t bf[4][2];
            #pragma unroll
            for (int jj = 0; jj < 4; jj++) {
                int n = ch * 32 + jj * 8 + g;
                uint2 bv = sW2p2[(ks * 4 + tg) * 68 + n];
                bf[jj][0] = bv.x;
                bf[jj][1] = bv.y;
            }
            #pragma unroll
            for (int mt = 0; mt < 2; mt++)
                #pragma unroll
                for (int jj = 0; jj < 4; jj++) mma_f16(acc[mt][jj], af[mt], bf[jj]);
        }
        __syncthreads();

        // epilogue: m = silu(raw + b2) packed half2 back into sAh
        #pragma unroll
        for (int mt = 0; mt < 2; mt++) {
            int r0 = rb * 32 + mt * 16 + g;
            #pragma unroll
            for (int jj = 0; jj < 4; jj++) {
                int c0 = ch * 32 + jj * 8 + tg * 2;
                int w = c0 >> 1;
                sAh[r0 * PAD_AH + w] =
                    pack_h2(silu(acc[mt][jj][0] + sB2[c0]),
                            silu(acc[mt][jj][1] + sB2[c0 + 1]));
                sAh[(r0 + 8) * PAD_AH + w] =
                    pack_h2(silu(acc[mt][jj][2] + sB2[c0]),
                            silu(acc[mt][jj][3] + sB2[c0 + 1]));
            }
        }
        __syncthreads();

        // segmented reduction: thread = (column k2, quarter seg); fp32 accum
        {
            int k2 = tid & 63;
            int seg = tid >> 6;
            int w = k2 >> 1;
            int hi = k2 & 1;
            int r0 = seg * 32;
            int rcur = sR[r0];
            float a = 0.0f;
            #pragma unroll 8
            for (int rr = r0; rr < r0 + 32; rr++) {
                int rn = sR[rr];
                if (rn != rcur) {
                    atomicAdd(&d_agg[((size_t)b * NN + rcur) * HH + k2], a);
                    a = 0.0f;
                    rcur = rn;
                }
                uint32_t mw = sAh[rr * PAD_AH + w];
                __half2 mh = *reinterpret_cast<__half2*>(&mw);
                a += hi ? __high2float(mh) : __low2float(mh);
            }
            atomicAdd(&d_agg[((size_t)b * NN + rcur) * HH + k2], a);
        }
        __syncthreads();
    }
}

// ---- tensorized node kernel + fused output head on last layer (tf32) ----
__global__ void __launch_bounds__(256, 3) node_kernel(
    const float* __restrict__ nW1, const float* __restrict__ nb1,
    const float* __restrict__ nW2, const float* __restrict__ nb2,
    const float* __restrict__ lng, const float* __restrict__ lnb,
    const float* __restrict__ eW1n, const float* __restrict__ eb1n,
    const float* __restrict__ oW1, const float* __restrict__ ob1,
    const float* __restrict__ oW2, const float* __restrict__ ob2,
    float* __restrict__ outp) {
    extern __shared__ __align__(16) char smem[];
    float*    sAf = (float*)(smem + SMN_A);
    uint32_t* sAu = (uint32_t*)(smem + SMN_A);
    uint32_t* sB  = (uint32_t*)(smem + SMN_B);
    float*    sNB1 = (float*)(smem + SMN_BIAS);
    float*    sNB2 = sNB1 + 64;
    float*    sLG  = sNB1 + 128;
    float*    sLB  = sNB1 + 192;
    float*    sEB  = sNB1 + 256;
    float*    sLNs = (float*)(smem + SMN_LN);
    float*    sLNq = sLNs + 256;

    int tid = threadIdx.x;
    int wid = tid >> 5;
    int lane = tid & 31;
    int g = lane >> 2;
    int tg = lane & 3;
    int rw = wid & 1;
    int cw = wid >> 1;
    int node0 = blockIdx.x * 64;

    {
        int row = tid & 63;
        int qtr = tid >> 6;
        const float* src = (qtr < 2)
            ? d_h  + (size_t)(node0 + row) * HH + qtr * 32
            : d_agg + (size_t)(node0 + row) * HH + (qtr - 2) * 32;
        uint32_t* dst = sAu + row * PAD_NA + qtr * 32;
        #pragma unroll
        for (int i4 = 0; i4 < 8; i4++) {
            float4 v = reinterpret_cast<const float4*>(src)[i4];
            uint4 t;
            t.x = f2tf32(v.x); t.y = f2tf32(v.y);
            t.z = f2tf32(v.z); t.w = f2tf32(v.w);
            reinterpret_cast<uint4*>(dst)[i4] = t;
        }
        if (qtr >= 2) {
            float4* az = reinterpret_cast<float4*>(
                d_agg + (size_t)(node0 + row) * HH + (qtr - 2) * 32);
            #pragma unroll
            for (int i4 = 0; i4 < 8; i4++) az[i4] = make_float4(0, 0, 0, 0);
        }
    }
    for (int idx = tid; idx < 128 * 64; idx += 256) {
        sB[(idx >> 6) * PAD_B + (idx & 63)] = f2tf32(nW1[idx]);
    }
    if (tid < 64) {
        sNB1[tid] = nb1[tid];
        sNB2[tid] = nb2[tid];
        sLG[tid] = lng[tid];
        sLB[tid] = lnb[tid];
        sEB[tid] = eW1n ? eb1n[tid] : ob1[tid];
    }
    __syncthreads();

    float acc[2][2][4];
    #pragma unroll
    for (int mt = 0; mt < 2; mt++)
        #pragma unroll
        for (int nt = 0; nt < 2; nt++)
            #pragma unroll
            for (int q = 0; q < 4; q++) acc[mt][nt][q] = 0.0f;
    #pragma unroll
    for (int ks = 0; ks < 16; ks++) {
        uint32_t af[2][4];
        #pragma unroll
        for (int mt = 0; mt < 2; mt++) {
            int rr = rw * 32 + mt * 16 + g;
            int cc = ks * 8 + tg;
            af[mt][0] = sAu[rr * PAD_NA + cc];
            af[mt][1] = sAu[(rr + 8) * PAD_NA + cc];
            af[mt][2] = sAu[rr * PAD_NA + cc + 4];
            af[mt][3] = sAu[(rr + 8) * PAD_NA + cc + 4];
        }
        uint32_t bf[2][2];
        #pragma unroll
        for (int nt = 0; nt < 2; nt++) {
            int n = cw * 16 + nt * 8 + g;
            bf[nt][0] = sB[(ks * 8 + tg) * PAD_B + n];
            bf[nt][1] = sB[(ks * 8 + tg + 4) * PAD_B + n];
        }
        #pragma unroll
        for (int mt = 0; mt < 2; mt++)
            #pragma unroll
            for (int nt = 0; nt < 2; nt++) mma_tf32(acc[mt][nt], af[mt], bf[nt]);
    }
    __syncthreads();

    #pragma unroll
    for (int mt = 0; mt < 2; mt++) {
        int r0 = rw * 32 + mt * 16 + g;
        #pragma unroll
        for (int nt = 0; nt < 2; nt++) {
            int c0 = cw * 16 + nt * 8 + tg * 2;
            sAu[r0 * PAD_NA + c0]           = f2tf32(silu(acc[mt][nt][0] + sNB1[c0]));
            sAu[r0 * PAD_NA + c0 + 1]       = f2tf32(silu(acc[mt][nt][1] + sNB1[c0 + 1]));
            sAu[(r0 + 8) * PAD_NA + c0]     = f2tf32(silu(acc[mt][nt][2] + sNB1[c0]));
            sAu[(r0 + 8) * PAD_NA + c0 + 1] = f2tf32(silu(acc[mt][nt][3] + sNB1[c0 + 1]));
        }
    }
    for (int idx = tid; idx < 64 * 64; idx += 256) {
        sB[(idx >> 6) * PAD_B + (idx & 63)] = f2tf32(nW2[idx]);
    }
    __syncthreads();

    #pragma unroll
    for (int mt = 0; mt < 2; mt++)
        #pragma unroll
        for (int nt = 0; nt < 2; nt++)
            #pragma unroll
            for (int q = 0; q < 4; q++) acc[mt][nt][q] = 0.0f;
    #pragma unroll
    for (int ks = 0; ks < 8; ks++) {
        uint32_t af[2][4];
        #pragma unroll
        for (int mt = 0; mt < 2; mt++) {
            int rr = rw * 32 + mt * 16 + g;
            int cc = ks * 8 + tg;
            af[mt][0] = sAu[rr * PAD_NA + cc];
            af[mt][1] = sAu[(rr + 8) * PAD_NA + cc];
            af[mt][2] = sAu[rr * PAD_NA + cc + 4];
            af[mt][3] = sAu[(rr + 8) * PAD_NA + cc + 4];
        }
        uint32_t bf[2][2];
        #pragma unroll
        for (int nt = 0; nt < 2; nt++) {
            int n = cw * 16 + nt * 8 + g;
            bf[nt][0] = sB[(ks * 8 + tg) * PAD_B + n];
            bf[nt][1] = sB[(ks * 8 + tg + 4) * PAD_B + n];
        }
        #pragma unroll
        for (int mt = 0; mt < 2; mt++)
            #pragma unroll
            for (int nt = 0; nt < 2; nt++) mma_tf32(acc[mt][nt], af[mt], bf[nt]);
    }
    __syncthreads();

    #pragma unroll
    for (int mt = 0; mt < 2; mt++) {
        int r0 = rw * 32 + mt * 16 + g;
        #pragma unroll
        for (int nt = 0; nt < 2; nt++) {
            int c0 = cw * 16 + nt * 8 + tg * 2;
            float2 h0 = *reinterpret_cast<const float2*>(d_h + (size_t)(node0 + r0) * HH + c0);
            float2 h1 = *reinterpret_cast<const float2*>(d_h + (size_t)(node0 + r0 + 8) * HH + c0);
            sAf[r0 * PAD_NA + c0]           = h0.x + acc[mt][nt][0] + sNB2[c0];
            sAf[r0 * PAD_NA + c0 + 1]       = h0.y + acc[mt][nt][1] + sNB2[c0 + 1];
            sAf[(r0 + 8) * PAD_NA + c0]     = h1.x + acc[mt][nt][2] + sNB2[c0];
            sAf[(r0 + 8) * PAD_NA + c0 + 1] = h1.y + acc[mt][nt][3] + sNB2[c0 + 1];
        }
    }
    if (eW1n) {
        for (int idx = tid; idx < 64 * 128; idx += 256) {
            int i = idx >> 7, n = idx & 127;
            float v = (n < 64) ? eW1n[i * HH + n] : eW1n[(64 + i) * HH + (n - 64)];
            sB[i * PAD_NP + n] = f2tf32(v);
        }
    } else {
        for (int idx = tid; idx < 64 * 64; idx += 256) {
            sB[(idx >> 6) * PAD_B + (idx & 63)] = f2tf32(oW1[idx]);
        }
    }
    __syncthreads();

    {
        int row = tid >> 2;
        int part = tid & 3;
        float s = 0.0f, q = 0.0f;
        #pragma unroll
        for (int i = 0; i < 16; i++) {
            float v = sAf[row * PAD_NA + part * 16 + i];
            s += v;
            q += v * v;
        }
        sLNs[row * 4 + part] = s;
        sLNq[row * 4 + part] = q;
    }
    __syncthreads();
    {
        int row = tid >> 2;
        int part = tid & 3;
        float s = sLNs[row * 4] + sLNs[row * 4 + 1] + sLNs[row * 4 + 2] + sLNs[row * 4 + 3];
        float q = sLNq[row * 4] + sLNq[row * 4 + 1] + sLNq[row * 4 + 2] + sLNq[row * 4 + 3];
        float mu = s * (1.0f / HH);
        float var = q * (1.0f / HH) - mu * mu;
        float rstd = rsqrtf(var + 1e-5f);
        float hv[16];
        #pragma unroll
        for (int i = 0; i < 16; i++) {
            int c = part * 16 + i;
            hv[i] = (sAf[row * PAD_NA + c] - mu) * rstd * sLG[c] + sLB[c];
        }
        float4* hout = reinterpret_cast<float4*>(d_h + (size_t)(node0 + row) * HH + part * 16);
        #pragma unroll
        for (int i4 = 0; i4 < 4; i4++)
            hout[i4] = make_float4(hv[i4 * 4], hv[i4 * 4 + 1], hv[i4 * 4 + 2], hv[i4 * 4 + 3]);
        #pragma unroll
        for (int i = 0; i < 16; i++)
            sAu[row * PAD_NA + part * 16 + i] = f2tf32(hv[i]);
    }
    __syncthreads();

    if (eW1n) {
        float acc3[2][4][4];
        #pragma unroll
        for (int mt = 0; mt < 2; mt++)
            #pragma unroll
            for (int nt = 0; nt < 4; nt++)
                #pragma unroll
                for (int q = 0; q < 4; q++) acc3[mt][nt][q] = 0.0f;
        #pragma unroll
        for (int ks = 0; ks < 8; ks++) {
            uint32_t af[2][4];
            #pragma unroll
            for (int mt = 0; mt < 2; mt++) {
                int rr = rw * 32 + mt * 16 + g;
                int cc = ks * 8 + tg;
                af[mt][0] = sAu[rr * PAD_NA + cc];
                af[mt][1] = sAu[(rr + 8) * PAD_NA + cc];
                af[mt][2] = sAu[rr * PAD_NA + cc + 4];
                af[mt][3] = sAu[(rr + 8) * PAD_NA + cc + 4];
            }
            uint32_t bf[4][2];
            #pragma unroll
            for (int nt = 0; nt < 4; nt++) {
                int n = cw * 32 + nt * 8 + g;
                bf[nt][0] = sB[(ks * 8 + tg) * PAD_NP + n];
                bf[nt][1] = sB[(ks * 8 + tg + 4) * PAD_NP + n];
            }
            #pragma unroll
            for (int mt = 0; mt < 2; mt++)
                #pragma unroll
                for (int nt = 0; nt < 4; nt++) mma_tf32(acc3[mt][nt], af[mt], bf[nt]);
        }
        #pragma unroll
        for (int mt = 0; mt < 2; mt++) {
            int r0 = rw * 32 + mt * 16 + g;
            #pragma unroll
            for (int nt = 0; nt < 4; nt++) {
                int c0 = cw * 32 + nt * 8 + tg * 2;
                #pragma unroll
                for (int hh = 0; hh < 2; hh++) {
                    int rr = r0 + hh * 8;
                    float v0 = acc3[mt][nt][hh * 2];
                    float v1 = acc3[mt][nt][hh * 2 + 1];
                    if (c0 < 64) {
                        v0 += sEB[c0];
                        v1 += sEB[c0 + 1];
                        *reinterpret_cast<float2*>(d_p1 + (size_t)(node0 + rr) * HH + c0)
                            = make_float2(v0, v1);
                    } else {
                        *reinterpret_cast<float2*>(d_p2 + (size_t)(node0 + rr) * HH + (c0 - 64))
                            = make_float2(v0, v1);
                    }
                }
            }
        }
    } else {
        float acco[2][2][4];
        #pragma unroll
        for (int mt = 0; mt < 2; mt++)
            #pragma unroll
            for (int nt = 0; nt < 2; nt++)
                #pragma unroll
                for (int q = 0; q < 4; q++) acco[mt][nt][q] = 0.0f;
        #pragma unroll
        for (int ks = 0; ks < 8; ks++) {
            uint32_t af[2][4];
            #pragma unroll
            for (int mt = 0; mt < 2; mt++) {
                int rr = rw * 32 + mt * 16 + g;
                int cc = ks * 8 + tg;
                af[mt][0] = sAu[rr * PAD_NA + cc];
                af[mt][1] = sAu[(rr + 8) * PAD_NA + cc];
                af[mt][2] = sAu[rr * PAD_NA + cc + 4];
                af[mt][3] = sAu[(rr + 8) * PAD_NA + cc + 4];
            }
            uint32_t bf[2][2];
            #pragma unroll
            for (int nt = 0; nt < 2; nt++) {
                int n = cw * 16 + nt * 8 + g;
                bf[nt][0] = sB[(ks * 8 + tg) * PAD_B + n];
                bf[nt][1] = sB[(ks * 8 + tg + 4) * PAD_B + n];
            }
            #pragma unroll
            for (int mt = 0; mt < 2; mt++)
                #pragma unroll
                for (int nt = 0; nt < 2; nt++) mma_tf32(acco[mt][nt], af[mt], bf[nt]);
        }
        __syncthreads();

        #pragma unroll
        for (int mt = 0; mt < 2; mt++) {
            int r0 = rw * 32 + mt * 16 + g;
            #pragma unroll
            for (int nt = 0; nt < 2; nt++) {
                int c0 = cw * 16 + nt * 8 + tg * 2;
                sAf[r0 * PAD_NA + c0]           = fmaxf(acco[mt][nt][0] + sEB[c0], 0.0f);
                sAf[r0 * PAD_NA + c0 + 1]       = fmaxf(acco[mt][nt][1] + sEB[c0 + 1], 0.0f);
                sAf[(r0 + 8) * PAD_NA + c0]     = fmaxf(acco[mt][nt][2] + sEB[c0], 0.0f);
                sAf[(r0 + 8) * PAD_NA + c0 + 1] = fmaxf(acco[mt][nt][3] + sEB[c0 + 1], 0.0f);
            }
        }
        if (tid < 192) sLNs[tid] = oW2[tid];
        __syncthreads();

        if (tid < 192) {
            int row = tid / 3;
            int k3 = tid % 3;
            float o = ob2[k3];
            #pragma unroll 8
            for (int i = 0; i < HH; i++)
                o += sAf[row * PAD_NA + i] * sLNs[i * 3 + k3];
            outp[(size_t)(node0 + row) * 3 + k3] = o;
        }
    }
}

extern "C" void kernel_launch(void* const* d_in, const int* in_sizes, int n_in,
                              void* d_out, int out_size) {
    const float* z   = (const float*)d_in[0];
    const int*   ei  = (const int*)d_in[1];
    const float* nf  = (const float*)d_in[2];
    const float* Wg  = (const float*)d_in[3];
    const float* bg  = (const float*)d_in[4];
    const float* Wn  = (const float*)d_in[5];
    const float* bn  = (const float*)d_in[6];
    const float* eW1 = (const float*)d_in[7];
    const float* eb1 = (const float*)d_in[8];
    const float* eW2 = (const float*)d_in[9];
    const float* eb2 = (const float*)d_in[10];
    const float* nW1 = (const float*)d_in[14];
    const float* nb1 = (const float*)d_in[15];
    const float* nW2 = (const float*)d_in[16];
    const float* nb2 = (const float*)d_in[17];
    const float* lng = (const float*)d_in[18];
    const float* lnb = (const float*)d_in[19];
    const float* oW1 = (const float*)d_in[20];
    const float* ob1 = (const float*)d_in[21];
    const float* oW2 = (const float*)d_in[22];
    const float* ob2 = (const float*)d_in[23];

    void* pAgg;
    cudaGetSymbolAddress(&pAgg, d_agg);
    cudaMemsetAsync(pAgg, 0, sizeof(float) * BB * NN * HH);

    cudaFuncSetAttribute((const void*)edge_kernel,
                         cudaFuncAttributeMaxDynamicSharedMemorySize, SME_TOTAL);
    cudaFuncSetAttribute((const void*)node_kernel,
                         cudaFuncAttributeMaxDynamicSharedMemorySize, SMN_TOTAL);

    g_kernel<<<1, 1024>>>(z, Wg, bg);
    h_kernel<<<BB * NN / 4, 256>>>(nf, Wn, bn, eW1, eb1);
    csr_kernel<<<1, 1024>>>(ei, ei + EE);

    for (int l = 0; l < LL; l++) {
        edge_kernel<<<EDGE_GRID, 256, SME_TOTAL>>>(
            eW2 + (size_t)l * HH * HH, eb2 + l * HH);
        const float* eW1n = (l + 1 < LL) ? eW1 + (size_t)(l + 1) * 129 * HH : nullptr;
        const float* eb1n = (l + 1 < LL) ? eb1 + (l + 1) * HH : nullptr;
        node_kernel<<<BB * NN / 64, 256, SMN_TOTAL>>>(
            nW1 + (size_t)l * 2 * HH * HH, nb1 + l * HH,
            nW2 + (size_t)l * HH * HH, nb2 + l * HH,
            lng + l * HH, lnb + l * HH,
            eW1n, eb1n,
            oW1, ob1, oW2, ob2, (float*)d_out);
    }
}